// round 1
// baseline (speedup 1.0000x reference)
#include <cuda_runtime.h>
#include <math.h>

#define NTOK   8192
#define NE     10
#define DMODEL 768
#define DFF    3072
#define LINSZ  1376
#define BM     64
#define BN     64
#define BK     16
#define CAP    18432   // >= 2*NTOK + NE*(BM-1), padded segments

// ---------------- device scratch (no allocation allowed) ----------------
__device__ int   d_counts[NE];
__device__ int   d_cursor[NE];
__device__ int   d_seg_start[NE + 1];
__device__ int   d_top_e[NTOK * 2];
__device__ float d_top_g[NTOK * 2];
__device__ int   d_slot_token[CAP];
__device__ int   d_token_slot[NTOK * 2];
__device__ float d_h[(size_t)CAP * DFF];        // gelu(x@w1+b1), per slot
__device__ float d_outslot[(size_t)CAP * DMODEL];

// ---------------- init ----------------
__global__ void init_kernel() {
    int i = blockIdx.x * blockDim.x + threadIdx.x;
    if (i < NE) { d_counts[i] = 0; d_cursor[i] = 0; }
    if (i < CAP) d_slot_token[i] = -1;
}

// ---------------- router: warp per token ----------------
// rin = [x(768), city_emb(32), dt(192), ddis(192), drg(96), dent(96)] -> 1376
__global__ __launch_bounds__(256) void router_kernel(
    const float* __restrict__ x,
    const int*   __restrict__ city,
    const float* __restrict__ dt,
    const float* __restrict__ ddis,
    const float* __restrict__ drg,
    const float* __restrict__ dent,
    const float* __restrict__ city_emb,
    const float* __restrict__ rw,
    const float* __restrict__ rb,
    float* __restrict__ gate1_out)
{
    int gwarp = (blockIdx.x * blockDim.x + threadIdx.x) >> 5;
    int lane  = threadIdx.x & 31;
    if (gwarp >= NTOK) return;
    int t = gwarp;

    const float* ce = city_emb + city[0] * 32;

    // 1376 / 32 = 43 values per lane
    float rin[43];
#pragma unroll
    for (int i = 0; i < 43; i++) {
        int f = lane + 32 * i;
        float v;
        if      (f < 768)  v = x[(size_t)t * 768 + f];
        else if (f < 800)  v = ce[f - 768];
        else if (f < 992)  v = dt[(size_t)t * 192 + (f - 800)];
        else if (f < 1184) v = ddis[(size_t)t * 192 + (f - 992)];
        else if (f < 1280) v = drg[(size_t)t * 96 + (f - 1184)];
        else               v = dent[(size_t)t * 96 + (f - 1280)];
        rin[i] = v;
    }

    float logits[NE];
#pragma unroll
    for (int e = 0; e < NE; e++) {
        const float* w = rw + e * LINSZ;
        float acc = 0.f;
#pragma unroll
        for (int i = 0; i < 43; i++)
            acc = fmaf(rin[i], w[lane + 32 * i], acc);
#pragma unroll
        for (int o = 16; o > 0; o >>= 1)
            acc += __shfl_xor_sync(0xffffffffu, acc, o);
        logits[e] = acc + rb[e];
    }

    if (lane == 0) {
        // full softmax -> gate1
        float m = logits[0];
#pragma unroll
        for (int e = 1; e < NE; e++) m = fmaxf(m, logits[e]);
        float ex[NE], s = 0.f;
#pragma unroll
        for (int e = 0; e < NE; e++) { ex[e] = expf(logits[e] - m); s += ex[e]; }
        float inv = 1.f / s;
#pragma unroll
        for (int e = 0; e < NE; e++)
            gate1_out[(size_t)t * NE + e] = ex[e] * inv;

        // top-2 (lowest index wins ties, matching lax.top_k)
        int i0 = 0;
#pragma unroll
        for (int e = 1; e < NE; e++) if (logits[e] > logits[i0]) i0 = e;
        int i1 = (i0 == 0) ? 1 : 0;
#pragma unroll
        for (int e = 0; e < NE; e++)
            if (e != i0 && logits[e] > logits[i1]) i1 = e;

        float e1 = expf(logits[i1] - logits[i0]);
        float g0 = 1.f / (1.f + e1);
        float g1 = e1 * g0;

        d_top_e[2 * t]     = i0;
        d_top_e[2 * t + 1] = i1;
        d_top_g[2 * t]     = g0;
        d_top_g[2 * t + 1] = g1;
        atomicAdd(&d_counts[i0], 1);
        atomicAdd(&d_counts[i1], 1);
    }
}

// ---------------- segment scan (BM-aligned) ----------------
__global__ void scan_kernel() {
    if (threadIdx.x == 0 && blockIdx.x == 0) {
        int off = 0;
#pragma unroll
        for (int e = 0; e < NE; e++) {
            d_seg_start[e] = off;
            off += ((d_counts[e] + BM - 1) / BM) * BM;
        }
        d_seg_start[NE] = off;
    }
}

// ---------------- dispatch tokens into compact slots ----------------
__global__ void dispatch_kernel() {
    int i = blockIdx.x * blockDim.x + threadIdx.x;
    if (i >= NTOK * 2) return;
    int e = d_top_e[i];
    int pos = atomicAdd(&d_cursor[e], 1);
    int slot = d_seg_start[e] + pos;
    d_slot_token[slot] = i >> 1;
    d_token_slot[i] = slot;
}

// ---------------- GEMM1: h = gelu(gather(x) @ w1[e] + b1[e]) ----------------
__global__ __launch_bounds__(256) void gemm1_kernel(
    const float* __restrict__ x,
    const float* __restrict__ w1,
    const float* __restrict__ b1)
{
    __shared__ float As[BK][BM + 4];
    __shared__ float Bs[BK][BN];

    int row0 = blockIdx.y * BM;
    int col0 = blockIdx.x * BN;
    if (row0 >= d_seg_start[NE]) return;

    int e = 0;
#pragma unroll
    for (int i = 0; i < NE; i++) if (row0 >= d_seg_start[i + 1]) e = i + 1;
    const float* W    = w1 + (size_t)e * DMODEL * DFF;
    const float* bias = b1 + (size_t)e * DFF;

    int tid = threadIdx.x;
    int ar = tid >> 2;            // 0..63
    int ak = (tid & 3) * 4;       // 0,4,8,12
    int tokenA = d_slot_token[row0 + ar];
    const float* aptr = (tokenA >= 0) ? (x + (size_t)tokenA * DMODEL) : nullptr;
    int bk = tid >> 4;            // 0..15
    int bn = (tid & 15) * 4;      // 0..60
    int tx = tid & 15, ty = tid >> 4;

    float acc[4][4] = {};
    for (int k0 = 0; k0 < DMODEL; k0 += BK) {
        float4 av = aptr ? *(const float4*)(aptr + k0 + ak) : make_float4(0.f,0.f,0.f,0.f);
        float4 bv = *(const float4*)(W + (size_t)(k0 + bk) * DFF + col0 + bn);
        __syncthreads();
        As[ak + 0][ar] = av.x; As[ak + 1][ar] = av.y;
        As[ak + 2][ar] = av.z; As[ak + 3][ar] = av.w;
        *(float4*)&Bs[bk][bn] = bv;
        __syncthreads();
#pragma unroll
        for (int k = 0; k < BK; k++) {
            float4 a = *(const float4*)&As[k][ty * 4];
            float4 b = *(const float4*)&Bs[k][tx * 4];
            float av_[4] = {a.x, a.y, a.z, a.w};
            float bv_[4] = {b.x, b.y, b.z, b.w};
#pragma unroll
            for (int i = 0; i < 4; i++)
#pragma unroll
                for (int j = 0; j < 4; j++)
                    acc[i][j] = fmaf(av_[i], bv_[j], acc[i][j]);
        }
    }
#pragma unroll
    for (int i = 0; i < 4; i++) {
        float* hrow = d_h + (size_t)(row0 + ty * 4 + i) * DFF + col0;
#pragma unroll
        for (int j = 0; j < 4; j++) {
            int n = tx * 4 + j;
            float v = acc[i][j] + bias[col0 + n];
            v = 0.5f * v * (1.f + erff(v * 0.70710678118654752f));
            hrow[n] = v;
        }
    }
}

// ---------------- GEMM2: outslot = h @ w2[e] + b2[e] ----------------
__global__ __launch_bounds__(256) void gemm2_kernel(
    const float* __restrict__ w2,
    const float* __restrict__ b2)
{
    __shared__ float As[BK][BM + 4];
    __shared__ float Bs[BK][BN];

    int row0 = blockIdx.y * BM;
    int col0 = blockIdx.x * BN;
    if (row0 >= d_seg_start[NE]) return;

    int e = 0;
#pragma unroll
    for (int i = 0; i < NE; i++) if (row0 >= d_seg_start[i + 1]) e = i + 1;
    const float* W    = w2 + (size_t)e * DFF * DMODEL;
    const float* bias = b2 + (size_t)e * DMODEL;

    int tid = threadIdx.x;
    int ar = tid >> 2;
    int ak = (tid & 3) * 4;
    const float* aptr = d_h + (size_t)(row0 + ar) * DFF;
    int bk = tid >> 4;
    int bn = (tid & 15) * 4;
    int tx = tid & 15, ty = tid >> 4;

    float acc[4][4] = {};
    for (int k0 = 0; k0 < DFF; k0 += BK) {
        float4 av = *(const float4*)(aptr + k0 + ak);
        float4 bv = *(const float4*)(W + (size_t)(k0 + bk) * DMODEL + col0 + bn);
        __syncthreads();
        As[ak + 0][ar] = av.x; As[ak + 1][ar] = av.y;
        As[ak + 2][ar] = av.z; As[ak + 3][ar] = av.w;
        *(float4*)&Bs[bk][bn] = bv;
        __syncthreads();
#pragma unroll
        for (int k = 0; k < BK; k++) {
            float4 a = *(const float4*)&As[k][ty * 4];
            float4 b = *(const float4*)&Bs[k][tx * 4];
            float av_[4] = {a.x, a.y, a.z, a.w};
            float bv_[4] = {b.x, b.y, b.z, b.w};
#pragma unroll
            for (int i = 0; i < 4; i++)
#pragma unroll
                for (int j = 0; j < 4; j++)
                    acc[i][j] = fmaf(av_[i], bv_[j], acc[i][j]);
        }
    }
#pragma unroll
    for (int i = 0; i < 4; i++) {
        float* orow = d_outslot + (size_t)(row0 + ty * 4 + i) * DMODEL + col0;
#pragma unroll
        for (int j = 0; j < 4; j++) {
            int n = tx * 4 + j;
            orow[n] = acc[i][j] + bias[col0 + n];
        }
    }
}

// ---------------- combine: out[t] = g0*slot0 + g1*slot1 ----------------
__global__ void combine_kernel(float* __restrict__ out) {
    int t = blockIdx.x;
    int s0 = d_token_slot[2 * t];
    int s1 = d_token_slot[2 * t + 1];
    float g0 = d_top_g[2 * t];
    float g1 = d_top_g[2 * t + 1];
    int d = threadIdx.x * 4;
    float4 a = *(const float4*)(d_outslot + (size_t)s0 * DMODEL + d);
    float4 b = *(const float4*)(d_outslot + (size_t)s1 * DMODEL + d);
    float4 r;
    r.x = g0 * a.x + g1 * b.x;
    r.y = g0 * a.y + g1 * b.y;
    r.z = g0 * a.z + g1 * b.z;
    r.w = g0 * a.w + g1 * b.w;
    *(float4*)(out + (size_t)t * DMODEL + d) = r;
}

// ---------------- launch ----------------
extern "C" void kernel_launch(void* const* d_in, const int* in_sizes, int n_in,
                              void* d_out, int out_size)
{
    const float* x        = (const float*)d_in[0];
    const int*   city     = (const int*)d_in[1];
    const float* dt       = (const float*)d_in[2];
    const float* ddis     = (const float*)d_in[3];
    const float* drg      = (const float*)d_in[4];
    const float* dent     = (const float*)d_in[5];
    const float* city_emb = (const float*)d_in[6];
    const float* rw       = (const float*)d_in[7];
    const float* rb       = (const float*)d_in[8];
    const float* w1       = (const float*)d_in[9];
    const float* b1       = (const float*)d_in[10];
    const float* w2       = (const float*)d_in[11];
    const float* b2       = (const float*)d_in[12];

    float* out   = (float*)d_out;                       // [8192, 768]
    float* gate1 = (float*)d_out + (size_t)NTOK * DMODEL; // [8192, 10]

    init_kernel<<<(CAP + 255) / 256, 256>>>();
    router_kernel<<<(NTOK * 32 + 255) / 256, 256>>>(
        x, city, dt, ddis, drg, dent, city_emb, rw, rb, gate1);
    scan_kernel<<<1, 32>>>();
    dispatch_kernel<<<(NTOK * 2 + 255) / 256, 256>>>();

    dim3 g1(DFF / BN, CAP / BM);
    gemm1_kernel<<<g1, 256>>>(x, w1, b1);
    dim3 g2(DMODEL / BN, CAP / BM);
    gemm2_kernel<<<g2, 256>>>(w2, b2);

    combine_kernel<<<NTOK, DMODEL / 4>>>(out);
}

// round 8
// speedup vs baseline: 1.4225x; 1.4225x over previous
#include <cuda_runtime.h>
#include <cuda_bf16.h>
#include <mma.h>
#include <math.h>
#include <stdint.h>

using namespace nvcuda;

#define NTOK   8192
#define NE     10
#define DMODEL 768
#define DFF    3072
#define LINSZ  1376
#define BM     64
#define CAP    18432          // 288 * 64, same footprint as R1

// ---------------- device scratch (matches R1 footprint: ~283 MB) ----------------
__device__ int   d_counts[NE];
__device__ int   d_cursor[NE];
__device__ int   d_seg_start[NE + 1];
__device__ int   d_top_e[NTOK * 2];
__device__ float d_top_g[NTOK * 2];
__device__ int   d_slot_token[CAP];
__device__ int   d_token_slot[NTOK * 2];
__device__ float d_h[(size_t)CAP * DFF];        // fp32, like R1
__device__ float d_outslot[(size_t)CAP * DMODEL];

// ---------------- init ----------------
__global__ void init_kernel() {
    int i = blockIdx.x * blockDim.x + threadIdx.x;
    if (i < NE) { d_counts[i] = 0; d_cursor[i] = 0; }
    if (i < CAP) d_slot_token[i] = -1;
}

// ---------------- router: warp per token ----------------
__global__ __launch_bounds__(256) void router_kernel(
    const float* __restrict__ x, const int* __restrict__ city,
    const float* __restrict__ dt, const float* __restrict__ ddis,
    const float* __restrict__ drg, const float* __restrict__ dent,
    const float* __restrict__ city_emb, const float* __restrict__ rw,
    const float* __restrict__ rb, float* __restrict__ gate1_out)
{
    int gwarp = (blockIdx.x * blockDim.x + threadIdx.x) >> 5;
    int lane  = threadIdx.x & 31;
    if (gwarp >= NTOK) return;
    int t = gwarp;
    const float* ce = city_emb + city[0] * 32;

    float rin[43];
#pragma unroll
    for (int i = 0; i < 43; i++) {
        int f = lane + 32 * i;
        float v;
        if      (f < 768)  v = x[(size_t)t * 768 + f];
        else if (f < 800)  v = ce[f - 768];
        else if (f < 992)  v = dt[(size_t)t * 192 + (f - 800)];
        else if (f < 1184) v = ddis[(size_t)t * 192 + (f - 992)];
        else if (f < 1280) v = drg[(size_t)t * 96 + (f - 1184)];
        else               v = dent[(size_t)t * 96 + (f - 1280)];
        rin[i] = v;
    }

    float logits[NE];
#pragma unroll
    for (int e = 0; e < NE; e++) {
        const float* w = rw + e * LINSZ;
        float acc = 0.f;
#pragma unroll
        for (int i = 0; i < 43; i++) acc = fmaf(rin[i], w[lane + 32 * i], acc);
#pragma unroll
        for (int o = 16; o > 0; o >>= 1) acc += __shfl_xor_sync(0xffffffffu, acc, o);
        logits[e] = acc + rb[e];
    }

    if (lane == 0) {
        float m = logits[0];
#pragma unroll
        for (int e = 1; e < NE; e++) m = fmaxf(m, logits[e]);
        float ex[NE], s = 0.f;
#pragma unroll
        for (int e = 0; e < NE; e++) { ex[e] = expf(logits[e] - m); s += ex[e]; }
        float inv = 1.f / s;
#pragma unroll
        for (int e = 0; e < NE; e++) gate1_out[(size_t)t * NE + e] = ex[e] * inv;

        int i0 = 0;
#pragma unroll
        for (int e = 1; e < NE; e++) if (logits[e] > logits[i0]) i0 = e;
        int i1 = (i0 == 0) ? 1 : 0;
#pragma unroll
        for (int e = 0; e < NE; e++) if (e != i0 && logits[e] > logits[i1]) i1 = e;

        float e1 = expf(logits[i1] - logits[i0]);
        float g0 = 1.f / (1.f + e1);
        float g1 = e1 * g0;

        d_top_e[2 * t] = i0;     d_top_e[2 * t + 1] = i1;
        d_top_g[2 * t] = g0;     d_top_g[2 * t + 1] = g1;
        atomicAdd(&d_counts[i0], 1);
        atomicAdd(&d_counts[i1], 1);
    }
}

__global__ void scan_kernel() {
    if (threadIdx.x == 0) {
        int off = 0;
#pragma unroll
        for (int e = 0; e < NE; e++) {
            d_seg_start[e] = off;
            off += ((d_counts[e] + BM - 1) / BM) * BM;
        }
        d_seg_start[NE] = off;
    }
}

__global__ void dispatch_kernel() {
    int i = blockIdx.x * blockDim.x + threadIdx.x;
    if (i >= NTOK * 2) return;
    int e = d_top_e[i];
    int pos = atomicAdd(&d_cursor[e], 1);
    int slot = d_seg_start[e] + pos;
    d_slot_token[slot] = i >> 1;
    d_token_slot[i] = slot;
}

// ---------------- bf16 hi/lo split helpers ----------------
__device__ __forceinline__ uint32_t pack_bf2(float a, float b) {
    __nv_bfloat162 t;
    t.x = __float2bfloat16(a);
    t.y = __float2bfloat16(b);
    return *reinterpret_cast<uint32_t*>(&t);
}

// split 8 consecutive floats (f0,f1) into 8 hi-bf16 (uint4) + 8 lo-bf16 (uint4)
__device__ __forceinline__ void split8(float4 f0, float4 f1, uint4& hi, uint4& lo) {
    hi.x = pack_bf2(f0.x, f0.y);
    hi.y = pack_bf2(f0.z, f0.w);
    hi.z = pack_bf2(f1.x, f1.y);
    hi.w = pack_bf2(f1.z, f1.w);
    __nv_bfloat162* h = reinterpret_cast<__nv_bfloat162*>(&hi);
    lo.x = pack_bf2(f0.x - __bfloat162float(h[0].x), f0.y - __bfloat162float(h[0].y));
    lo.y = pack_bf2(f0.z - __bfloat162float(h[1].x), f0.w - __bfloat162float(h[1].y));
    lo.z = pack_bf2(f1.x - __bfloat162float(h[2].x), f1.y - __bfloat162float(h[2].y));
    lo.w = pack_bf2(f1.z - __bfloat162float(h[3].x), f1.w - __bfloat162float(h[3].y));
}

// ---------------- WMMA MoE GEMM, fp32 in / on-the-fly hi-lo split ----------------
// MODE 0: d_h = gelu(gather(x) @ w1[e] + b1[e])    A=x gathered, W=w1 [768][3072]
// MODE 1: d_outslot = d_h @ w2[e] + b2[e]          A=d_h,       W=w2 [3072][768]
// CTA 64x64, BK=32, 8 warps (2m x 4n), 3-pass hi/lo bf16, double-buffered smem.
#define PITCH_A 40                     // bf16 elems per A smem row (80 B)
#define PITCH_B 72                     // bf16 elems per B smem row (144 B)
#define A_SLAB_E (64 * PITCH_A)        // 2560
#define B_SLAB_E (32 * PITCH_B)        // 2304
#define STAGE_E  (2 * A_SLAB_E + 2 * B_SLAB_E)   // 9728 elems = 19456 B

template<int MODE>
__global__ __launch_bounds__(256, 2) void moe_wmma(
    const float* __restrict__ Ain,     // x (MODE 0) / unused (MODE 1)
    const float* __restrict__ Wglob,   // w1 / w2
    const float* __restrict__ bias_g)
{
    constexpr int KDIM = MODE ? DFF : DMODEL;
    constexpr int NDIM = MODE ? DMODEL : DFF;
    constexpr int NS   = KDIM / 32;

    __shared__ __align__(256) __nv_bfloat16 smem[2 * STAGE_E];   // 38912 B

    int row0 = blockIdx.y * 64;
    if (row0 >= d_seg_start[NE]) return;
    int col0 = blockIdx.x * 64;

    int e = 0;
#pragma unroll
    for (int i = 0; i < NE; i++) if (row0 >= d_seg_start[i + 1]) e = i + 1;

    int tid = threadIdx.x;
    int wid = tid >> 5;
    int wm  = wid & 1;
    int wn  = wid >> 1;

    // ---- loader assignments ----
    // A: row ra = tid>>2, k-group kg = (tid&3)*8  (64 rows x 32 k)
    int ra = tid >> 2;
    int kg = (tid & 3) * 8;
    const float* gpa;
    bool zf = false;
    if (MODE == 0) {
        int tok = d_slot_token[row0 + ra];
        if (tok < 0) { zf = true; tok = 0; }
        gpa = Ain + (size_t)tok * DMODEL + kg;
    } else {
        gpa = d_h + (size_t)(row0 + ra) * DFF + kg;
    }
    // B: k-row kb = tid>>3, n-group ng = (tid&7)*8  (32 k x 64 n)
    int kb = tid >> 3;
    int ng = (tid & 7) * 8;
    const float* gpb = Wglob + (size_t)e * DMODEL * DFF + (size_t)kb * NDIM + col0 + ng;

    wmma::fragment<wmma::accumulator, 16, 16, 16, float> acc0, acc1;
    wmma::fill_fragment(acc0, 0.0f);
    wmma::fill_fragment(acc1, 0.0f);

    const float4 zero4 = make_float4(0.f, 0.f, 0.f, 0.f);
    float4 fa0, fa1, fb0, fb1;
    // prefetch stage 0
    fa0 = zf ? zero4 : *(const float4*)(gpa);
    fa1 = zf ? zero4 : *(const float4*)(gpa + 4);
    fb0 = *(const float4*)(gpb);
    fb1 = *(const float4*)(gpb + 4);

    uint32_t a_off = ra * PITCH_A + kg;        // element offset in A slab
    uint32_t b_off = kb * PITCH_B + ng;        // element offset in B slab

#pragma unroll 1
    for (int k = 0; k < NS; k++) {
        __nv_bfloat16* st = smem + (k & 1) * STAGE_E;
        {
            uint4 hi, lo;
            split8(fa0, fa1, hi, lo);
            *(uint4*)(st + a_off)            = hi;
            *(uint4*)(st + A_SLAB_E + a_off) = lo;
            split8(fb0, fb1, hi, lo);
            *(uint4*)(st + 2 * A_SLAB_E + b_off)             = hi;
            *(uint4*)(st + 2 * A_SLAB_E + B_SLAB_E + b_off)  = lo;
        }
        __syncthreads();

        if (k + 1 < NS) {
            const float* pa = gpa + (k + 1) * 32;
            fa0 = zf ? zero4 : *(const float4*)(pa);
            fa1 = zf ? zero4 : *(const float4*)(pa + 4);
            const float* pb = gpb + (size_t)(k + 1) * 32 * NDIM;
            fb0 = *(const float4*)(pb);
            fb1 = *(const float4*)(pb + 4);
        }

        const __nv_bfloat16* sAhi = st;
        const __nv_bfloat16* sAlo = st + A_SLAB_E;
        const __nv_bfloat16* sBhi = st + 2 * A_SLAB_E;
        const __nv_bfloat16* sBlo = st + 2 * A_SLAB_E + B_SLAB_E;

#pragma unroll
        for (int kk = 0; kk < 32; kk += 16) {
            wmma::fragment<wmma::matrix_a, 16, 16, 16, __nv_bfloat16, wmma::row_major> aH0, aH1, aL0, aL1;
            wmma::fragment<wmma::matrix_b, 16, 16, 16, __nv_bfloat16, wmma::row_major> bH, bL;
            wmma::load_matrix_sync(aH0, sAhi + (wm * 32 +  0) * PITCH_A + kk, PITCH_A);
            wmma::load_matrix_sync(aH1, sAhi + (wm * 32 + 16) * PITCH_A + kk, PITCH_A);
            wmma::load_matrix_sync(aL0, sAlo + (wm * 32 +  0) * PITCH_A + kk, PITCH_A);
            wmma::load_matrix_sync(aL1, sAlo + (wm * 32 + 16) * PITCH_A + kk, PITCH_A);
            wmma::load_matrix_sync(bH,  sBhi + kk * PITCH_B + wn * 16, PITCH_B);
            wmma::load_matrix_sync(bL,  sBlo + kk * PITCH_B + wn * 16, PITCH_B);

            wmma::mma_sync(acc0, aH0, bH, acc0);
            wmma::mma_sync(acc0, aL0, bH, acc0);
            wmma::mma_sync(acc0, aH0, bL, acc0);
            wmma::mma_sync(acc1, aH1, bH, acc1);
            wmma::mma_sync(acc1, aL1, bH, acc1);
            wmma::mma_sync(acc1, aH1, bL, acc1);
        }
        __syncthreads();
    }

    // ---- epilogue: stage through smem, add bias, (gelu), store fp32 ----
    float* ebuf = (float*)smem;     // 64 x 68 fp32 = 17408 B < 38912 B
    wmma::store_matrix_sync(ebuf + (wm * 32 +  0) * 68 + wn * 16, acc0, 68, wmma::mem_row_major);
    wmma::store_matrix_sync(ebuf + (wm * 32 + 16) * 68 + wn * 16, acc1, 68, wmma::mem_row_major);
    __syncthreads();

    int r  = tid >> 2;
    int cb = (tid & 3) * 16;
    const float* brow = bias_g + (size_t)e * NDIM + col0 + cb;
    float* orow = (MODE == 0)
        ? (d_h + (size_t)(row0 + r) * DFF + col0 + cb)
        : (d_outslot + (size_t)(row0 + r) * DMODEL + col0 + cb);
#pragma unroll
    for (int c = 0; c < 16; c += 4) {
        float4 v;
        v.x = ebuf[r * 68 + cb + c + 0] + brow[c + 0];
        v.y = ebuf[r * 68 + cb + c + 1] + brow[c + 1];
        v.z = ebuf[r * 68 + cb + c + 2] + brow[c + 2];
        v.w = ebuf[r * 68 + cb + c + 3] + brow[c + 3];
        if (MODE == 0) {
            v.x = 0.5f * v.x * (1.f + erff(v.x * 0.70710678118654752f));
            v.y = 0.5f * v.y * (1.f + erff(v.y * 0.70710678118654752f));
            v.z = 0.5f * v.z * (1.f + erff(v.z * 0.70710678118654752f));
            v.w = 0.5f * v.w * (1.f + erff(v.w * 0.70710678118654752f));
        }
        *(float4*)(orow + c) = v;
    }
}

// ---------------- combine ----------------
__global__ void combine_kernel(float* __restrict__ out) {
    int t = blockIdx.x;
    int s0 = d_token_slot[2 * t];
    int s1 = d_token_slot[2 * t + 1];
    float g0 = d_top_g[2 * t];
    float g1 = d_top_g[2 * t + 1];
    int d = threadIdx.x * 4;
    float4 a = *(const float4*)(d_outslot + (size_t)s0 * DMODEL + d);
    float4 b = *(const float4*)(d_outslot + (size_t)s1 * DMODEL + d);
    float4 r;
    r.x = g0 * a.x + g1 * b.x;
    r.y = g0 * a.y + g1 * b.y;
    r.z = g0 * a.z + g1 * b.z;
    r.w = g0 * a.w + g1 * b.w;
    *(float4*)(out + (size_t)t * DMODEL + d) = r;
}

// ---------------- launch ----------------
extern "C" void kernel_launch(void* const* d_in, const int* in_sizes, int n_in,
                              void* d_out, int out_size)
{
    const float* x        = (const float*)d_in[0];
    const int*   city     = (const int*)d_in[1];
    const float* dt       = (const float*)d_in[2];
    const float* ddis     = (const float*)d_in[3];
    const float* drg      = (const float*)d_in[4];
    const float* dent     = (const float*)d_in[5];
    const float* city_emb = (const float*)d_in[6];
    const float* rw       = (const float*)d_in[7];
    const float* rb       = (const float*)d_in[8];
    const float* w1       = (const float*)d_in[9];
    const float* b1       = (const float*)d_in[10];
    const float* w2       = (const float*)d_in[11];
    const float* b2       = (const float*)d_in[12];

    float* out   = (float*)d_out;
    float* gate1 = (float*)d_out + (size_t)NTOK * DMODEL;

    init_kernel<<<(CAP + 255) / 256, 256>>>();
    router_kernel<<<NTOK * 32 / 256, 256>>>(x, city, dt, ddis, drg, dent,
                                            city_emb, rw, rb, gate1);
    scan_kernel<<<1, 32>>>();
    dispatch_kernel<<<(NTOK * 2 + 255) / 256, 256>>>();

    moe_wmma<0><<<dim3(DFF / 64, CAP / 64), 256>>>(x, w1, b1);
    moe_wmma<1><<<dim3(DMODEL / 64, CAP / 64), 256>>>(x, w2, b2);

    combine_kernel<<<NTOK, DMODEL / 4>>>(out);
}

// round 9
// speedup vs baseline: 1.5179x; 1.0671x over previous
#include <cuda_runtime.h>
#include <cuda_bf16.h>
#include <mma.h>
#include <math.h>
#include <stdint.h>

using namespace nvcuda;

#define NTOK   8192
#define NE     10
#define DMODEL 768
#define DFF    3072
#define LINSZ  1376
#define BM     128
#define CAP    18432          // 144 * 128 — same global footprint as R8 (passed)

// smem stage layout (bf16 elements): Ahi(128x40) Alo Bhi(32x136) Blo
#define PITCH_A 40
#define PITCH_B 136
#define A_SLAB_E (128 * PITCH_A)                 // 5120
#define B_SLAB_E (32 * PITCH_B)                  // 4352
#define STAGE_E  (2 * A_SLAB_E + 2 * B_SLAB_E)   // 18944 elems
#define SMEM_BYTES (2 * STAGE_E * 2)             // 75776 B

// ---------------- device scratch (R8 footprint: ~283 MB) ----------------
__device__ int   d_counts[NE];
__device__ int   d_cursor[NE];
__device__ int   d_seg_start[NE + 1];
__device__ int   d_top_e[NTOK * 2];
__device__ float d_top_g[NTOK * 2];
__device__ int   d_slot_token[CAP];
__device__ int   d_token_slot[NTOK * 2];
__device__ float d_h[(size_t)CAP * DFF];
__device__ float d_outslot[(size_t)CAP * DMODEL];

// ---------------- init ----------------
__global__ void init_kernel() {
    int i = blockIdx.x * blockDim.x + threadIdx.x;
    if (i < NE) { d_counts[i] = 0; d_cursor[i] = 0; }
    if (i < CAP) d_slot_token[i] = -1;
}

// ---------------- router: warp per token ----------------
__global__ __launch_bounds__(256) void router_kernel(
    const float* __restrict__ x, const int* __restrict__ city,
    const float* __restrict__ dt, const float* __restrict__ ddis,
    const float* __restrict__ drg, const float* __restrict__ dent,
    const float* __restrict__ city_emb, const float* __restrict__ rw,
    const float* __restrict__ rb, float* __restrict__ gate1_out)
{
    int gwarp = (blockIdx.x * blockDim.x + threadIdx.x) >> 5;
    int lane  = threadIdx.x & 31;
    if (gwarp >= NTOK) return;
    int t = gwarp;
    const float* ce = city_emb + city[0] * 32;

    float rin[43];
#pragma unroll
    for (int i = 0; i < 43; i++) {
        int f = lane + 32 * i;
        float v;
        if      (f < 768)  v = x[(size_t)t * 768 + f];
        else if (f < 800)  v = ce[f - 768];
        else if (f < 992)  v = dt[(size_t)t * 192 + (f - 800)];
        else if (f < 1184) v = ddis[(size_t)t * 192 + (f - 992)];
        else if (f < 1280) v = drg[(size_t)t * 96 + (f - 1184)];
        else               v = dent[(size_t)t * 96 + (f - 1280)];
        rin[i] = v;
    }

    float logits[NE];
#pragma unroll
    for (int e = 0; e < NE; e++) {
        const float* w = rw + e * LINSZ;
        float acc = 0.f;
#pragma unroll
        for (int i = 0; i < 43; i++) acc = fmaf(rin[i], w[lane + 32 * i], acc);
#pragma unroll
        for (int o = 16; o > 0; o >>= 1) acc += __shfl_xor_sync(0xffffffffu, acc, o);
        logits[e] = acc + rb[e];
    }

    if (lane == 0) {
        float m = logits[0];
#pragma unroll
        for (int e = 1; e < NE; e++) m = fmaxf(m, logits[e]);
        float ex[NE], s = 0.f;
#pragma unroll
        for (int e = 0; e < NE; e++) { ex[e] = expf(logits[e] - m); s += ex[e]; }
        float inv = 1.f / s;
#pragma unroll
        for (int e = 0; e < NE; e++) gate1_out[(size_t)t * NE + e] = ex[e] * inv;

        int i0 = 0;
#pragma unroll
        for (int e = 1; e < NE; e++) if (logits[e] > logits[i0]) i0 = e;
        int i1 = (i0 == 0) ? 1 : 0;
#pragma unroll
        for (int e = 0; e < NE; e++) if (e != i0 && logits[e] > logits[i1]) i1 = e;

        float e1 = expf(logits[i1] - logits[i0]);
        float g0 = 1.f / (1.f + e1);
        float g1 = e1 * g0;

        d_top_e[2 * t] = i0;     d_top_e[2 * t + 1] = i1;
        d_top_g[2 * t] = g0;     d_top_g[2 * t + 1] = g1;
        atomicAdd(&d_counts[i0], 1);
        atomicAdd(&d_counts[i1], 1);
    }
}

__global__ void scan_kernel() {
    if (threadIdx.x == 0) {
        int off = 0;
#pragma unroll
        for (int e = 0; e < NE; e++) {
            d_seg_start[e] = off;
            off += ((d_counts[e] + BM - 1) / BM) * BM;
        }
        d_seg_start[NE] = off;
    }
}

__global__ void dispatch_kernel() {
    int i = blockIdx.x * blockDim.x + threadIdx.x;
    if (i >= NTOK * 2) return;
    int e = d_top_e[i];
    int pos = atomicAdd(&d_cursor[e], 1);
    int slot = d_seg_start[e] + pos;
    d_slot_token[slot] = i >> 1;
    d_token_slot[i] = slot;
}

// ---------------- bf16 hi/lo split ----------------
__device__ __forceinline__ uint32_t pack_bf2(float a, float b) {
    __nv_bfloat162 t;
    t.x = __float2bfloat16(a);
    t.y = __float2bfloat16(b);
    return *reinterpret_cast<uint32_t*>(&t);
}

__device__ __forceinline__ void split8(float4 f0, float4 f1, uint4& hi, uint4& lo) {
    hi.x = pack_bf2(f0.x, f0.y);
    hi.y = pack_bf2(f0.z, f0.w);
    hi.z = pack_bf2(f1.x, f1.y);
    hi.w = pack_bf2(f1.z, f1.w);
    __nv_bfloat162* h = reinterpret_cast<__nv_bfloat162*>(&hi);
    lo.x = pack_bf2(f0.x - __bfloat162float(h[0].x), f0.y - __bfloat162float(h[0].y));
    lo.y = pack_bf2(f0.z - __bfloat162float(h[1].x), f0.w - __bfloat162float(h[1].y));
    lo.z = pack_bf2(f1.x - __bfloat162float(h[2].x), f1.y - __bfloat162float(h[2].y));
    lo.w = pack_bf2(f1.z - __bfloat162float(h[3].x), f1.w - __bfloat162float(h[3].y));
}

// ---------------- WMMA MoE GEMM, 128x128 tile ----------------
// MODE 0: d_h = gelu(gather(x) @ w1[e] + b1[e])    K=768,  N=3072
// MODE 1: d_outslot = d_h @ w2[e] + b2[e]          K=3072, N=768
// 256 thr, 8 warps (2m x 4n), warp tile 64x32 (m4 x n2 wmma frags).
// Double-buffered smem + 1-deep register prefetch, fp32->hi/lo split on the fly.
template<int MODE>
__global__ __launch_bounds__(256, 1) void moe_wmma(
    const float* __restrict__ Ain,
    const float* __restrict__ Wglob,
    const float* __restrict__ bias_g)
{
    constexpr int KDIM = MODE ? DFF : DMODEL;
    constexpr int NDIM = MODE ? DMODEL : DFF;
    constexpr int NS   = KDIM / 32;

    extern __shared__ __align__(256) __nv_bfloat16 smem[];

    int row0 = blockIdx.y * 128;
    if (row0 >= d_seg_start[NE]) return;
    int col0 = blockIdx.x * 128;

    int e = 0;
#pragma unroll
    for (int i = 0; i < NE; i++) if (row0 >= d_seg_start[i + 1]) e = i + 1;

    int tid = threadIdx.x;
    int wid = tid >> 5;
    int wm  = wid & 1;         // m half (64 rows)
    int wn  = wid >> 1;        // n quarter (32 cols)

    // ---- loaders ----
    // A: row ra = tid>>1 (128 rows), k base kg = (tid&1)*16 : 16 floats/thread
    int ra = tid >> 1;
    int kg = (tid & 1) * 16;
    const float* gpa;
    bool zf = false;
    if (MODE == 0) {
        int tok = d_slot_token[row0 + ra];
        if (tok < 0) { zf = true; tok = 0; }
        gpa = Ain + (size_t)tok * DMODEL + kg;
    } else {
        gpa = d_h + (size_t)(row0 + ra) * DFF + kg;
    }
    // B: k row kb = tid>>3 (32 rows), n base ng = (tid&7)*16 : 16 floats/thread
    int kb = tid >> 3;
    int ng = (tid & 7) * 16;
    const float* gpb = Wglob + (size_t)e * DMODEL * DFF + (size_t)kb * NDIM + col0 + ng;

    uint32_t a_off = (uint32_t)(ra * PITCH_A + kg);
    uint32_t b_off = (uint32_t)(kb * PITCH_B + ng);

    // accumulators: 8 named fragments (m4 x n2)
    wmma::fragment<wmma::accumulator, 16, 16, 16, float> c00, c01, c10, c11,
                                                         c20, c21, c30, c31;
    wmma::fill_fragment(c00, 0.f); wmma::fill_fragment(c01, 0.f);
    wmma::fill_fragment(c10, 0.f); wmma::fill_fragment(c11, 0.f);
    wmma::fill_fragment(c20, 0.f); wmma::fill_fragment(c21, 0.f);
    wmma::fill_fragment(c30, 0.f); wmma::fill_fragment(c31, 0.f);

    const float4 zero4 = make_float4(0.f, 0.f, 0.f, 0.f);
    float4 a0, a1, a2, a3, b0, b1, b2, b3;

#define LOAD_STAGE(s) { \
        const float* pa = gpa + (s) * 32; \
        a0 = zf ? zero4 : *(const float4*)(pa); \
        a1 = zf ? zero4 : *(const float4*)(pa + 4); \
        a2 = zf ? zero4 : *(const float4*)(pa + 8); \
        a3 = zf ? zero4 : *(const float4*)(pa + 12); \
        const float* pb = gpb + (size_t)(s) * 32 * NDIM; \
        b0 = *(const float4*)(pb); \
        b1 = *(const float4*)(pb + 4); \
        b2 = *(const float4*)(pb + 8); \
        b3 = *(const float4*)(pb + 12); \
    }

#define STORE_STAGE(buf) { \
        __nv_bfloat16* st_ = (buf); \
        uint4 hi_, lo_; \
        split8(a0, a1, hi_, lo_); \
        *(uint4*)(st_ + a_off)             = hi_; \
        *(uint4*)(st_ + A_SLAB_E + a_off)  = lo_; \
        split8(a2, a3, hi_, lo_); \
        *(uint4*)(st_ + a_off + 8)             = hi_; \
        *(uint4*)(st_ + A_SLAB_E + a_off + 8)  = lo_; \
        split8(b0, b1, hi_, lo_); \
        *(uint4*)(st_ + 2 * A_SLAB_E + b_off)             = hi_; \
        *(uint4*)(st_ + 2 * A_SLAB_E + B_SLAB_E + b_off)  = lo_; \
        split8(b2, b3, hi_, lo_); \
        *(uint4*)(st_ + 2 * A_SLAB_E + b_off + 8)             = hi_; \
        *(uint4*)(st_ + 2 * A_SLAB_E + B_SLAB_E + b_off + 8)  = lo_; \
    }

    // prologue
    LOAD_STAGE(0);
    STORE_STAGE(smem);
    if (NS > 1) LOAD_STAGE(1);

#pragma unroll 1
    for (int k = 0; k < NS; k++) {
        __syncthreads();
        if (k + 1 < NS) STORE_STAGE(smem + ((k + 1) & 1) * STAGE_E);
        if (k + 2 < NS) LOAD_STAGE(k + 2);

        const __nv_bfloat16* st   = smem + (k & 1) * STAGE_E;
        const __nv_bfloat16* sAhi = st;
        const __nv_bfloat16* sAlo = st + A_SLAB_E;
        const __nv_bfloat16* sBhi = st + 2 * A_SLAB_E;
        const __nv_bfloat16* sBlo = st + 2 * A_SLAB_E + B_SLAB_E;

#pragma unroll
        for (int kk = 0; kk < 32; kk += 16) {
            wmma::fragment<wmma::matrix_b, 16, 16, 16, __nv_bfloat16, wmma::row_major> bH0, bL0, bH1, bL1;
            wmma::load_matrix_sync(bH0, sBhi + kk * PITCH_B + wn * 32,      PITCH_B);
            wmma::load_matrix_sync(bH1, sBhi + kk * PITCH_B + wn * 32 + 16, PITCH_B);
            wmma::load_matrix_sync(bL0, sBlo + kk * PITCH_B + wn * 32,      PITCH_B);
            wmma::load_matrix_sync(bL1, sBlo + kk * PITCH_B + wn * 32 + 16, PITCH_B);

#define M_BLOCK(mb, cA, cB) { \
            wmma::fragment<wmma::matrix_a, 16, 16, 16, __nv_bfloat16, wmma::row_major> aH_, aL_; \
            wmma::load_matrix_sync(aH_, sAhi + (wm * 64 + (mb) * 16) * PITCH_A + kk, PITCH_A); \
            wmma::load_matrix_sync(aL_, sAlo + (wm * 64 + (mb) * 16) * PITCH_A + kk, PITCH_A); \
            wmma::mma_sync(cA, aH_, bH0, cA); \
            wmma::mma_sync(cA, aL_, bH0, cA); \
            wmma::mma_sync(cA, aH_, bL0, cA); \
            wmma::mma_sync(cB, aH_, bH1, cB); \
            wmma::mma_sync(cB, aL_, bH1, cB); \
            wmma::mma_sync(cB, aH_, bL1, cB); \
        }
            M_BLOCK(0, c00, c01)
            M_BLOCK(1, c10, c11)
            M_BLOCK(2, c20, c21)
            M_BLOCK(3, c30, c31)
#undef M_BLOCK
        }
    }
    __syncthreads();

    // ---- epilogue: stage fp32 through smem, coalesced bias/gelu/store ----
    float* ebuf = (float*)smem;      // 128 x 132 fp32 = 67.6 KB <= 75.8 KB
#define EST(cv, mb, nb) \
    wmma::store_matrix_sync(ebuf + (wm * 64 + (mb) * 16) * 132 + wn * 32 + (nb) * 16, \
                            cv, 132, wmma::mem_row_major);
    EST(c00, 0, 0) EST(c01, 0, 1) EST(c10, 1, 0) EST(c11, 1, 1)
    EST(c20, 2, 0) EST(c21, 2, 1) EST(c30, 3, 0) EST(c31, 3, 1)
#undef EST
    __syncthreads();

    int c4 = (tid & 31) * 4;
    int rw = tid >> 5;
    float4 bias4 = *(const float4*)(bias_g + (size_t)e * NDIM + col0 + c4);
#pragma unroll
    for (int i = 0; i < 16; i++) {
        int r = rw + i * 8;
        float4 v = *(const float4*)(ebuf + r * 132 + c4);
        v.x += bias4.x; v.y += bias4.y; v.z += bias4.z; v.w += bias4.w;
        if (MODE == 0) {
            v.x = 0.5f * v.x * (1.f + erff(v.x * 0.70710678118654752f));
            v.y = 0.5f * v.y * (1.f + erff(v.y * 0.70710678118654752f));
            v.z = 0.5f * v.z * (1.f + erff(v.z * 0.70710678118654752f));
            v.w = 0.5f * v.w * (1.f + erff(v.w * 0.70710678118654752f));
            *(float4*)(d_h + (size_t)(row0 + r) * DFF + col0 + c4) = v;
        } else {
            *(float4*)(d_outslot + (size_t)(row0 + r) * DMODEL + col0 + c4) = v;
        }
    }
#undef LOAD_STAGE
#undef STORE_STAGE
}

// ---------------- combine ----------------
__global__ void combine_kernel(float* __restrict__ out) {
    int t = blockIdx.x;
    int s0 = d_token_slot[2 * t];
    int s1 = d_token_slot[2 * t + 1];
    float g0 = d_top_g[2 * t];
    float g1 = d_top_g[2 * t + 1];
    int d = threadIdx.x * 4;
    float4 a = *(const float4*)(d_outslot + (size_t)s0 * DMODEL + d);
    float4 b = *(const float4*)(d_outslot + (size_t)s1 * DMODEL + d);
    float4 r;
    r.x = g0 * a.x + g1 * b.x;
    r.y = g0 * a.y + g1 * b.y;
    r.z = g0 * a.z + g1 * b.z;
    r.w = g0 * a.w + g1 * b.w;
    *(float4*)(out + (size_t)t * DMODEL + d) = r;
}

// ---------------- launch ----------------
extern "C" void kernel_launch(void* const* d_in, const int* in_sizes, int n_in,
                              void* d_out, int out_size)
{
    const float* x        = (const float*)d_in[0];
    const int*   city     = (const int*)d_in[1];
    const float* dt       = (const float*)d_in[2];
    const float* ddis     = (const float*)d_in[3];
    const float* drg      = (const float*)d_in[4];
    const float* dent     = (const float*)d_in[5];
    const float* city_emb = (const float*)d_in[6];
    const float* rw       = (const float*)d_in[7];
    const float* rb       = (const float*)d_in[8];
    const float* w1       = (const float*)d_in[9];
    const float* b1       = (const float*)d_in[10];
    const float* w2       = (const float*)d_in[11];
    const float* b2       = (const float*)d_in[12];

    float* out   = (float*)d_out;
    float* gate1 = (float*)d_out + (size_t)NTOK * DMODEL;

    cudaFuncSetAttribute(moe_wmma<0>, cudaFuncAttributeMaxDynamicSharedMemorySize, SMEM_BYTES);
    cudaFuncSetAttribute(moe_wmma<1>, cudaFuncAttributeMaxDynamicSharedMemorySize, SMEM_BYTES);

    init_kernel<<<(CAP + 255) / 256, 256>>>();
    router_kernel<<<NTOK * 32 / 256, 256>>>(x, city, dt, ddis, drg, dent,
                                            city_emb, rw, rb, gate1);
    scan_kernel<<<1, 32>>>();
    dispatch_kernel<<<(NTOK * 2 + 255) / 256, 256>>>();

    moe_wmma<0><<<dim3(DFF / 128, CAP / 128), 256, SMEM_BYTES>>>(x, w1, b1);
    moe_wmma<1><<<dim3(DMODEL / 128, CAP / 128), 256, SMEM_BYTES>>>(x, w2, b2);

    combine_kernel<<<NTOK, DMODEL / 4>>>(out);
}

// round 10
// speedup vs baseline: 1.5891x; 1.0469x over previous
#include <cuda_runtime.h>
#include <cuda_bf16.h>
#include <mma.h>
#include <math.h>
#include <stdint.h>

using namespace nvcuda;

#define NTOK   8192
#define NE     10
#define DMODEL 768
#define DFF    3072
#define LINSZ  1376
#define BM     128
#define CAP    18432          // 144 * 128

// smem stage layout (bf16 elements): Ahi(128x40) Alo Bhi(32x136) Blo
#define PITCH_A 40
#define PITCH_B 136
#define A_SLAB_E (128 * PITCH_A)                 // 5120
#define B_SLAB_E (32 * PITCH_B)                  // 4352
#define STAGE_E  (2 * A_SLAB_E + 2 * B_SLAB_E)   // 18944 elems
#define SMEM_BYTES (2 * STAGE_E * 2)             // 75776 B

// ---------------- device scratch (same total footprint as R8/R9 pass) ----------------
__device__ int   d_counts[NE];
__device__ int   d_cursor[NE];
__device__ int   d_seg_start[NE + 1];
__device__ int   d_top_e[NTOK * 2];
__device__ float d_top_g[NTOK * 2];
__device__ int   d_slot_token[CAP];
__device__ int   d_token_slot[NTOK * 2];
__device__ __nv_bfloat16 d_h_hi[(size_t)CAP * DFF];   // 113 MB
__device__ __nv_bfloat16 d_h_lo[(size_t)CAP * DFF];   // 113 MB  (== old fp32 d_h)
__device__ float d_outslot[(size_t)CAP * DMODEL];

// ---------------- init ----------------
__global__ void init_kernel() {
    int i = blockIdx.x * blockDim.x + threadIdx.x;
    if (i < NE) { d_counts[i] = 0; d_cursor[i] = 0; }
    if (i < CAP) d_slot_token[i] = -1;
}

// ---------------- router: warp per token ----------------
__global__ __launch_bounds__(256) void router_kernel(
    const float* __restrict__ x, const int* __restrict__ city,
    const float* __restrict__ dt, const float* __restrict__ ddis,
    const float* __restrict__ drg, const float* __restrict__ dent,
    const float* __restrict__ city_emb, const float* __restrict__ rw,
    const float* __restrict__ rb, float* __restrict__ gate1_out)
{
    int gwarp = (blockIdx.x * blockDim.x + threadIdx.x) >> 5;
    int lane  = threadIdx.x & 31;
    if (gwarp >= NTOK) return;
    int t = gwarp;
    const float* ce = city_emb + city[0] * 32;

    float rin[43];
#pragma unroll
    for (int i = 0; i < 43; i++) {
        int f = lane + 32 * i;
        float v;
        if      (f < 768)  v = x[(size_t)t * 768 + f];
        else if (f < 800)  v = ce[f - 768];
        else if (f < 992)  v = dt[(size_t)t * 192 + (f - 800)];
        else if (f < 1184) v = ddis[(size_t)t * 192 + (f - 992)];
        else if (f < 1280) v = drg[(size_t)t * 96 + (f - 1184)];
        else               v = dent[(size_t)t * 96 + (f - 1280)];
        rin[i] = v;
    }

    float logits[NE];
#pragma unroll
    for (int e = 0; e < NE; e++) {
        const float* w = rw + e * LINSZ;
        float acc = 0.f;
#pragma unroll
        for (int i = 0; i < 43; i++) acc = fmaf(rin[i], w[lane + 32 * i], acc);
#pragma unroll
        for (int o = 16; o > 0; o >>= 1) acc += __shfl_xor_sync(0xffffffffu, acc, o);
        logits[e] = acc + rb[e];
    }

    if (lane == 0) {
        float m = logits[0];
#pragma unroll
        for (int e = 1; e < NE; e++) m = fmaxf(m, logits[e]);
        float ex[NE], s = 0.f;
#pragma unroll
        for (int e = 0; e < NE; e++) { ex[e] = expf(logits[e] - m); s += ex[e]; }
        float inv = 1.f / s;
#pragma unroll
        for (int e = 0; e < NE; e++) gate1_out[(size_t)t * NE + e] = ex[e] * inv;

        int i0 = 0;
#pragma unroll
        for (int e = 1; e < NE; e++) if (logits[e] > logits[i0]) i0 = e;
        int i1 = (i0 == 0) ? 1 : 0;
#pragma unroll
        for (int e = 0; e < NE; e++) if (e != i0 && logits[e] > logits[i1]) i1 = e;

        float e1 = expf(logits[i1] - logits[i0]);
        float g0 = 1.f / (1.f + e1);
        float g1 = e1 * g0;

        d_top_e[2 * t] = i0;     d_top_e[2 * t + 1] = i1;
        d_top_g[2 * t] = g0;     d_top_g[2 * t + 1] = g1;
        atomicAdd(&d_counts[i0], 1);
        atomicAdd(&d_counts[i1], 1);
    }
}

__global__ void scan_kernel() {
    if (threadIdx.x == 0) {
        int off = 0;
#pragma unroll
        for (int e = 0; e < NE; e++) {
            d_seg_start[e] = off;
            off += ((d_counts[e] + BM - 1) / BM) * BM;
        }
        d_seg_start[NE] = off;
    }
}

__global__ void dispatch_kernel() {
    int i = blockIdx.x * blockDim.x + threadIdx.x;
    if (i >= NTOK * 2) return;
    int e = d_top_e[i];
    int pos = atomicAdd(&d_cursor[e], 1);
    int slot = d_seg_start[e] + pos;
    d_slot_token[slot] = i >> 1;
    d_token_slot[i] = slot;
}

// ---------------- helpers ----------------
__device__ __forceinline__ uint32_t pack_bf2(float a, float b) {
    __nv_bfloat162 t;
    t.x = __float2bfloat16(a);
    t.y = __float2bfloat16(b);
    return *reinterpret_cast<uint32_t*>(&t);
}

__device__ __forceinline__ void split8(float4 f0, float4 f1, uint4& hi, uint4& lo) {
    hi.x = pack_bf2(f0.x, f0.y);
    hi.y = pack_bf2(f0.z, f0.w);
    hi.z = pack_bf2(f1.x, f1.y);
    hi.w = pack_bf2(f1.z, f1.w);
    __nv_bfloat162* h = reinterpret_cast<__nv_bfloat162*>(&hi);
    lo.x = pack_bf2(f0.x - __bfloat162float(h[0].x), f0.y - __bfloat162float(h[0].y));
    lo.y = pack_bf2(f0.z - __bfloat162float(h[1].x), f0.w - __bfloat162float(h[1].y));
    lo.z = pack_bf2(f1.x - __bfloat162float(h[2].x), f1.y - __bfloat162float(h[2].y));
    lo.w = pack_bf2(f1.z - __bfloat162float(h[3].x), f1.w - __bfloat162float(h[3].y));
}

// exact-grade GELU: erf via Abramowitz-Stegun 7.1.26 (|eps| <= 1.5e-7)
__device__ __forceinline__ float fast_gelu(float x) {
    float z = fabsf(x) * 0.70710678118654752f;
    float t = __fdividef(1.0f, fmaf(0.3275911f, z, 1.0f));
    float p = fmaf(1.061405429f, t, -1.453152027f);
    p = fmaf(p, t, 1.421413741f);
    p = fmaf(p, t, -0.284496736f);
    p = fmaf(p, t, 0.254829592f);
    p = p * t;
    float s = 1.0f - p * __expf(-z * z);
    return 0.5f * x * (1.0f + copysignf(s, x));
}

// ---------------- WMMA MoE GEMM, 128x128 tile ----------------
// MODE 0: d_h(hi/lo bf16) = gelu(gather(x) @ w1[e] + b1[e])   K=768,  N=3072
// MODE 1: d_outslot = (d_h_hi + d_h_lo) @ w2[e] + b2[e]       K=3072, N=768
template<int MODE>
__global__ __launch_bounds__(256, 1) void moe_wmma(
    const float* __restrict__ Ain,
    const float* __restrict__ Wglob,
    const float* __restrict__ bias_g)
{
    constexpr int KDIM = MODE ? DFF : DMODEL;
    constexpr int NDIM = MODE ? DMODEL : DFF;
    constexpr int NS   = KDIM / 32;

    extern __shared__ __align__(256) __nv_bfloat16 smem[];

    int row0 = blockIdx.y * 128;
    if (row0 >= d_seg_start[NE]) return;
    int col0 = blockIdx.x * 128;

    int e = 0;
#pragma unroll
    for (int i = 0; i < NE; i++) if (row0 >= d_seg_start[i + 1]) e = i + 1;

    int tid = threadIdx.x;
    int wid = tid >> 5;
    int wm  = wid & 1;
    int wn  = wid >> 1;

    // ---- loaders ----
    // A: row ra = tid>>1 (128 rows), k base kg = (tid&1)*16 (16 elems/thread)
    int ra = tid >> 1;
    int kg = (tid & 1) * 16;
    const float* gpa = nullptr;
    const __nv_bfloat16* gpah = nullptr;
    const __nv_bfloat16* gpal = nullptr;
    bool zf = false;
    if (MODE == 0) {
        int tok = d_slot_token[row0 + ra];
        if (tok < 0) { zf = true; tok = 0; }
        gpa = Ain + (size_t)tok * DMODEL + kg;
    } else {
        gpah = d_h_hi + (size_t)(row0 + ra) * DFF + kg;
        gpal = d_h_lo + (size_t)(row0 + ra) * DFF + kg;
    }
    // B: k row kb = tid>>3 (32 rows), n base ng = (tid&7)*16
    int kb = tid >> 3;
    int ng = (tid & 7) * 16;
    const float* gpb = Wglob + (size_t)e * DMODEL * DFF + (size_t)kb * NDIM + col0 + ng;

    uint32_t a_off = (uint32_t)(ra * PITCH_A + kg);
    uint32_t b_off = (uint32_t)(kb * PITCH_B + ng);

    wmma::fragment<wmma::accumulator, 16, 16, 16, float> c00, c01, c10, c11,
                                                         c20, c21, c30, c31;
    wmma::fill_fragment(c00, 0.f); wmma::fill_fragment(c01, 0.f);
    wmma::fill_fragment(c10, 0.f); wmma::fill_fragment(c11, 0.f);
    wmma::fill_fragment(c20, 0.f); wmma::fill_fragment(c21, 0.f);
    wmma::fill_fragment(c30, 0.f); wmma::fill_fragment(c31, 0.f);

    const float4 zero4 = make_float4(0.f, 0.f, 0.f, 0.f);
    float4 a0, a1, a2, a3, b0, b1, b2, b3;
    uint4  ah0, ah1, al0, al1;

    auto load_stage = [&](int s) {
        if (MODE == 0) {
            const float* pa = gpa + s * 32;
            a0 = zf ? zero4 : *(const float4*)(pa);
            a1 = zf ? zero4 : *(const float4*)(pa + 4);
            a2 = zf ? zero4 : *(const float4*)(pa + 8);
            a3 = zf ? zero4 : *(const float4*)(pa + 12);
        } else {
            const uint4* ph = (const uint4*)(gpah + s * 32);
            ah0 = ph[0]; ah1 = ph[1];
            const uint4* pl = (const uint4*)(gpal + s * 32);
            al0 = pl[0]; al1 = pl[1];
        }
        const float* pb = gpb + (size_t)s * 32 * NDIM;
        b0 = *(const float4*)(pb);
        b1 = *(const float4*)(pb + 4);
        b2 = *(const float4*)(pb + 8);
        b3 = *(const float4*)(pb + 12);
    };

    auto store_stage = [&](__nv_bfloat16* st_) {
        if (MODE == 0) {
            uint4 hi_, lo_;
            split8(a0, a1, hi_, lo_);
            *(uint4*)(st_ + a_off)             = hi_;
            *(uint4*)(st_ + A_SLAB_E + a_off)  = lo_;
            split8(a2, a3, hi_, lo_);
            *(uint4*)(st_ + a_off + 8)             = hi_;
            *(uint4*)(st_ + A_SLAB_E + a_off + 8)  = lo_;
        } else {
            *(uint4*)(st_ + a_off)                 = ah0;
            *(uint4*)(st_ + a_off + 8)             = ah1;
            *(uint4*)(st_ + A_SLAB_E + a_off)      = al0;
            *(uint4*)(st_ + A_SLAB_E + a_off + 8)  = al1;
        }
        uint4 hi_, lo_;
        split8(b0, b1, hi_, lo_);
        *(uint4*)(st_ + 2 * A_SLAB_E + b_off)             = hi_;
        *(uint4*)(st_ + 2 * A_SLAB_E + B_SLAB_E + b_off)  = lo_;
        split8(b2, b3, hi_, lo_);
        *(uint4*)(st_ + 2 * A_SLAB_E + b_off + 8)             = hi_;
        *(uint4*)(st_ + 2 * A_SLAB_E + B_SLAB_E + b_off + 8)  = lo_;
    };

    // prologue
    load_stage(0);
    store_stage(smem);
    if (NS > 1) load_stage(1);

#pragma unroll 1
    for (int k = 0; k < NS; k++) {
        __syncthreads();
        if (k + 1 < NS) store_stage(smem + ((k + 1) & 1) * STAGE_E);
        if (k + 2 < NS) load_stage(k + 2);

        const __nv_bfloat16* st   = smem + (k & 1) * STAGE_E;
        const __nv_bfloat16* sAhi = st;
        const __nv_bfloat16* sAlo = st + A_SLAB_E;
        const __nv_bfloat16* sBhi = st + 2 * A_SLAB_E;
        const __nv_bfloat16* sBlo = st + 2 * A_SLAB_E + B_SLAB_E;

#pragma unroll
        for (int kk = 0; kk < 32; kk += 16) {
            wmma::fragment<wmma::matrix_b, 16, 16, 16, __nv_bfloat16, wmma::row_major> bH0, bL0, bH1, bL1;
            wmma::load_matrix_sync(bH0, sBhi + kk * PITCH_B + wn * 32,      PITCH_B);
            wmma::load_matrix_sync(bH1, sBhi + kk * PITCH_B + wn * 32 + 16, PITCH_B);
            wmma::load_matrix_sync(bL0, sBlo + kk * PITCH_B + wn * 32,      PITCH_B);
            wmma::load_matrix_sync(bL1, sBlo + kk * PITCH_B + wn * 32 + 16, PITCH_B);

#define M_BLOCK(mb, cA, cB) { \
            wmma::fragment<wmma::matrix_a, 16, 16, 16, __nv_bfloat16, wmma::row_major> aH_, aL_; \
            wmma::load_matrix_sync(aH_, sAhi + (wm * 64 + (mb) * 16) * PITCH_A + kk, PITCH_A); \
            wmma::load_matrix_sync(aL_, sAlo + (wm * 64 + (mb) * 16) * PITCH_A + kk, PITCH_A); \
            wmma::mma_sync(cA, aH_, bH0, cA); \
            wmma::mma_sync(cA, aL_, bH0, cA); \
            wmma::mma_sync(cA, aH_, bL0, cA); \
            wmma::mma_sync(cB, aH_, bH1, cB); \
            wmma::mma_sync(cB, aL_, bH1, cB); \
            wmma::mma_sync(cB, aH_, bL1, cB); \
        }
            M_BLOCK(0, c00, c01)
            M_BLOCK(1, c10, c11)
            M_BLOCK(2, c20, c21)
            M_BLOCK(3, c30, c31)
#undef M_BLOCK
        }
    }
    __syncthreads();

    // ---- epilogue: stage fp32 through smem, coalesced bias/gelu/store ----
    float* ebuf = (float*)smem;      // 128 x 132 fp32 = 67.6 KB <= 75.8 KB
#define EST(cv, mb, nb) \
    wmma::store_matrix_sync(ebuf + (wm * 64 + (mb) * 16) * 132 + wn * 32 + (nb) * 16, \
                            cv, 132, wmma::mem_row_major);
    EST(c00, 0, 0) EST(c01, 0, 1) EST(c10, 1, 0) EST(c11, 1, 1)
    EST(c20, 2, 0) EST(c21, 2, 1) EST(c30, 3, 0) EST(c31, 3, 1)
#undef EST
    __syncthreads();

    int c4 = (tid & 31) * 4;
    int rw = tid >> 5;
    float4 bias4 = *(const float4*)(bias_g + (size_t)e * NDIM + col0 + c4);
#pragma unroll
    for (int i = 0; i < 16; i++) {
        int r = rw + i * 8;
        float4 v = *(const float4*)(ebuf + r * 132 + c4);
        v.x += bias4.x; v.y += bias4.y; v.z += bias4.z; v.w += bias4.w;
        if (MODE == 0) {
            v.x = fast_gelu(v.x);
            v.y = fast_gelu(v.y);
            v.z = fast_gelu(v.z);
            v.w = fast_gelu(v.w);
            uint2 h2, l2;
            h2.x = pack_bf2(v.x, v.y);
            h2.y = pack_bf2(v.z, v.w);
            __nv_bfloat162* hh = reinterpret_cast<__nv_bfloat162*>(&h2);
            l2.x = pack_bf2(v.x - __bfloat162float(hh[0].x), v.y - __bfloat162float(hh[0].y));
            l2.y = pack_bf2(v.z - __bfloat162float(hh[1].x), v.w - __bfloat162float(hh[1].y));
            size_t o = (size_t)(row0 + r) * DFF + col0 + c4;
            *(uint2*)(d_h_hi + o) = h2;
            *(uint2*)(d_h_lo + o) = l2;
        } else {
            *(float4*)(d_outslot + (size_t)(row0 + r) * DMODEL + col0 + c4) = v;
        }
    }
}

// ---------------- combine ----------------
__global__ void combine_kernel(float* __restrict__ out) {
    int t = blockIdx.x;
    int s0 = d_token_slot[2 * t];
    int s1 = d_token_slot[2 * t + 1];
    float g0 = d_top_g[2 * t];
    float g1 = d_top_g[2 * t + 1];
    int d = threadIdx.x * 4;
    float4 a = *(const float4*)(d_outslot + (size_t)s0 * DMODEL + d);
    float4 b = *(const float4*)(d_outslot + (size_t)s1 * DMODEL + d);
    float4 r;
    r.x = g0 * a.x + g1 * b.x;
    r.y = g0 * a.y + g1 * b.y;
    r.z = g0 * a.z + g1 * b.z;
    r.w = g0 * a.w + g1 * b.w;
    *(float4*)(out + (size_t)t * DMODEL + d) = r;
}

// ---------------- launch ----------------
extern "C" void kernel_launch(void* const* d_in, const int* in_sizes, int n_in,
                              void* d_out, int out_size)
{
    const float* x        = (const float*)d_in[0];
    const int*   city     = (const int*)d_in[1];
    const float* dt       = (const float*)d_in[2];
    const float* ddis     = (const float*)d_in[3];
    const float* drg      = (const float*)d_in[4];
    const float* dent     = (const float*)d_in[5];
    const float* city_emb = (const float*)d_in[6];
    const float* rw       = (const float*)d_in[7];
    const float* rb       = (const float*)d_in[8];
    const float* w1       = (const float*)d_in[9];
    const float* b1       = (const float*)d_in[10];
    const float* w2       = (const float*)d_in[11];
    const float* b2       = (const float*)d_in[12];

    float* out   = (float*)d_out;
    float* gate1 = (float*)d_out + (size_t)NTOK * DMODEL;

    cudaFuncSetAttribute(moe_wmma<0>, cudaFuncAttributeMaxDynamicSharedMemorySize, SMEM_BYTES);
    cudaFuncSetAttribute(moe_wmma<1>, cudaFuncAttributeMaxDynamicSharedMemorySize, SMEM_BYTES);

    init_kernel<<<(CAP + 255) / 256, 256>>>();
    router_kernel<<<NTOK * 32 / 256, 256>>>(x, city, dt, ddis, drg, dent,
                                            city_emb, rw, rb, gate1);
    scan_kernel<<<1, 32>>>();
    dispatch_kernel<<<(NTOK * 2 + 255) / 256, 256>>>();

    moe_wmma<0><<<dim3(DFF / 128, CAP / 128), 256, SMEM_BYTES>>>(x, w1, b1);
    moe_wmma<1><<<dim3(DMODEL / 128, CAP / 128), 256, SMEM_BYTES>>>(x, w2, b2);

    combine_kernel<<<NTOK, DMODEL / 4>>>(out);
}

// round 11
// speedup vs baseline: 1.5999x; 1.0068x over previous
#include <cuda_runtime.h>
#include <cuda_bf16.h>
#include <mma.h>
#include <math.h>
#include <stdint.h>

using namespace nvcuda;

#define NTOK   8192
#define NE     10
#define DMODEL 768
#define DFF    3072
#define LINSZ  1376
#define BM     128
#define CAP    18432          // 144 * 128

// smem: double-buffered stages (bf16) unioned with fp32 epilogue buffer
#define PITCH_A 24                                // elems (48 B rows)
#define PITCH_B 72                                // elems (144 B rows)
#define A_SLAB_E (128 * PITCH_A)                  // 3072
#define B_SLAB_E (16 * PITCH_B)                   // 1152
#define STAGE_E  (2 * A_SLAB_E + 2 * B_SLAB_E)    // 8448 elems = 16896 B
#define SMEM_TOTAL 34816                          // max(2*16896, 128*68*4)

// ---------------- device scratch (same footprint as R8-R10 pass) ----------------
__device__ int   d_counts[NE];
__device__ int   d_cursor[NE];
__device__ int   d_seg_start[NE + 1];
__device__ int   d_top_e[NTOK * 2];
__device__ float d_top_g[NTOK * 2];
__device__ int   d_slot_token[CAP];
__device__ int   d_token_slot[NTOK * 2];
__device__ __nv_bfloat16 d_h_hi[(size_t)CAP * DFF];
__device__ __nv_bfloat16 d_h_lo[(size_t)CAP * DFF];
__device__ float d_outslot[(size_t)CAP * DMODEL];

// ---------------- init ----------------
__global__ void init_kernel() {
    int i = blockIdx.x * blockDim.x + threadIdx.x;
    if (i < NE) { d_counts[i] = 0; d_cursor[i] = 0; }
    if (i < CAP) d_slot_token[i] = -1;
}

// ---------------- router: warp per token ----------------
__global__ __launch_bounds__(256) void router_kernel(
    const float* __restrict__ x, const int* __restrict__ city,
    const float* __restrict__ dt, const float* __restrict__ ddis,
    const float* __restrict__ drg, const float* __restrict__ dent,
    const float* __restrict__ city_emb, const float* __restrict__ rw,
    const float* __restrict__ rb, float* __restrict__ gate1_out)
{
    int gwarp = (blockIdx.x * blockDim.x + threadIdx.x) >> 5;
    int lane  = threadIdx.x & 31;
    if (gwarp >= NTOK) return;
    int t = gwarp;
    const float* ce = city_emb + city[0] * 32;

    float rin[43];
#pragma unroll
    for (int i = 0; i < 43; i++) {
        int f = lane + 32 * i;
        float v;
        if      (f < 768)  v = x[(size_t)t * 768 + f];
        else if (f < 800)  v = ce[f - 768];
        else if (f < 992)  v = dt[(size_t)t * 192 + (f - 800)];
        else if (f < 1184) v = ddis[(size_t)t * 192 + (f - 992)];
        else if (f < 1280) v = drg[(size_t)t * 96 + (f - 1184)];
        else               v = dent[(size_t)t * 96 + (f - 1280)];
        rin[i] = v;
    }

    float logits[NE];
#pragma unroll
    for (int e = 0; e < NE; e++) {
        const float* w = rw + e * LINSZ;
        float acc = 0.f;
#pragma unroll
        for (int i = 0; i < 43; i++) acc = fmaf(rin[i], w[lane + 32 * i], acc);
#pragma unroll
        for (int o = 16; o > 0; o >>= 1) acc += __shfl_xor_sync(0xffffffffu, acc, o);
        logits[e] = acc + rb[e];
    }

    if (lane == 0) {
        float m = logits[0];
#pragma unroll
        for (int e = 1; e < NE; e++) m = fmaxf(m, logits[e]);
        float ex[NE], s = 0.f;
#pragma unroll
        for (int e = 0; e < NE; e++) { ex[e] = expf(logits[e] - m); s += ex[e]; }
        float inv = 1.f / s;
#pragma unroll
        for (int e = 0; e < NE; e++) gate1_out[(size_t)t * NE + e] = ex[e] * inv;

        int i0 = 0;
#pragma unroll
        for (int e = 1; e < NE; e++) if (logits[e] > logits[i0]) i0 = e;
        int i1 = (i0 == 0) ? 1 : 0;
#pragma unroll
        for (int e = 0; e < NE; e++) if (e != i0 && logits[e] > logits[i1]) i1 = e;

        float e1 = expf(logits[i1] - logits[i0]);
        float g0 = 1.f / (1.f + e1);
        float g1 = e1 * g0;

        d_top_e[2 * t] = i0;     d_top_e[2 * t + 1] = i1;
        d_top_g[2 * t] = g0;     d_top_g[2 * t + 1] = g1;
        atomicAdd(&d_counts[i0], 1);
        atomicAdd(&d_counts[i1], 1);
    }
}

__global__ void scan_kernel() {
    if (threadIdx.x == 0) {
        int off = 0;
#pragma unroll
        for (int e = 0; e < NE; e++) {
            d_seg_start[e] = off;
            off += ((d_counts[e] + BM - 1) / BM) * BM;
        }
        d_seg_start[NE] = off;
    }
}

__global__ void dispatch_kernel() {
    int i = blockIdx.x * blockDim.x + threadIdx.x;
    if (i >= NTOK * 2) return;
    int e = d_top_e[i];
    int pos = atomicAdd(&d_cursor[e], 1);
    int slot = d_seg_start[e] + pos;
    d_slot_token[slot] = i >> 1;
    d_token_slot[i] = slot;
}

// ---------------- helpers ----------------
__device__ __forceinline__ uint32_t pack_bf2(float a, float b) {
    __nv_bfloat162 t;
    t.x = __float2bfloat16(a);
    t.y = __float2bfloat16(b);
    return *reinterpret_cast<uint32_t*>(&t);
}

__device__ __forceinline__ void split8(float4 f0, float4 f1, uint4& hi, uint4& lo) {
    hi.x = pack_bf2(f0.x, f0.y);
    hi.y = pack_bf2(f0.z, f0.w);
    hi.z = pack_bf2(f1.x, f1.y);
    hi.w = pack_bf2(f1.z, f1.w);
    __nv_bfloat162* h = reinterpret_cast<__nv_bfloat162*>(&hi);
    lo.x = pack_bf2(f0.x - __bfloat162float(h[0].x), f0.y - __bfloat162float(h[0].y));
    lo.y = pack_bf2(f0.z - __bfloat162float(h[1].x), f0.w - __bfloat162float(h[1].y));
    lo.z = pack_bf2(f1.x - __bfloat162float(h[2].x), f1.y - __bfloat162float(h[2].y));
    lo.w = pack_bf2(f1.z - __bfloat162float(h[3].x), f1.w - __bfloat162float(h[3].y));
}

// exact-grade GELU: erf via Abramowitz-Stegun 7.1.26 (|eps| <= 1.5e-7)
__device__ __forceinline__ float fast_gelu(float x) {
    float z = fabsf(x) * 0.70710678118654752f;
    float t = __fdividef(1.0f, fmaf(0.3275911f, z, 1.0f));
    float p = fmaf(1.061405429f, t, -1.453152027f);
    p = fmaf(p, t, 1.421413741f);
    p = fmaf(p, t, -0.284496736f);
    p = fmaf(p, t, 0.254829592f);
    p = p * t;
    float s = 1.0f - p * __expf(-z * z);
    return 0.5f * x * (1.0f + copysignf(s, x));
}

// ---------------- WMMA MoE GEMM, 128x64 tile, BK=16, 3 CTAs/SM ----------------
// MODE 0: d_h(hi/lo) = gelu(gather(x) @ w1[e] + b1[e])   K=768,  N=3072
// MODE 1: d_outslot = (d_h_hi + d_h_lo) @ w2[e] + b2[e]  K=3072, N=768
// 128 thr, 4 warps (2m x 2n), warp tile 64x32, 3-pass hi/lo bf16.
template<int MODE>
__global__ __launch_bounds__(128, 3) void moe_wmma(
    const float* __restrict__ Ain,
    const float* __restrict__ Wglob,
    const float* __restrict__ bias_g)
{
    constexpr int KDIM = MODE ? DFF : DMODEL;
    constexpr int NDIM = MODE ? DMODEL : DFF;
    constexpr int NS   = KDIM / 16;

    __shared__ __align__(256) char smem_raw[SMEM_TOTAL];
    __nv_bfloat16* smem = (__nv_bfloat16*)smem_raw;

    int row0 = blockIdx.y * 128;
    if (row0 >= d_seg_start[NE]) return;
    int col0 = blockIdx.x * 64;

    int e = 0;
#pragma unroll
    for (int i = 0; i < NE; i++) if (row0 >= d_seg_start[i + 1]) e = i + 1;

    int tid = threadIdx.x;
    int wid = tid >> 5;
    int wm  = wid & 1;         // m half (64 rows)
    int wn  = wid >> 1;        // n half (32 cols)

    // ---- loaders ----
    // A: each thread owns row ra = tid (128 rows), all 16 k-elems
    int ra = tid;
    const float* gpa = nullptr;
    const __nv_bfloat16* gpah = nullptr;
    const __nv_bfloat16* gpal = nullptr;
    bool zf = false;
    if (MODE == 0) {
        int tok = d_slot_token[row0 + ra];
        if (tok < 0) { zf = true; tok = 0; }
        gpa = Ain + (size_t)tok * DMODEL;
    } else {
        gpah = d_h_hi + (size_t)(row0 + ra) * DFF;
        gpal = d_h_lo + (size_t)(row0 + ra) * DFF;
    }
    // B: k row kb = tid>>3 (16 rows), n base ng = (tid&7)*8
    int kb = tid >> 3;
    int ng = (tid & 7) * 8;
    const float* gpb = Wglob + (size_t)e * DMODEL * DFF + (size_t)kb * NDIM + col0 + ng;

    uint32_t a_off = (uint32_t)(ra * PITCH_A);
    uint32_t b_off = (uint32_t)(kb * PITCH_B + ng);

    wmma::fragment<wmma::accumulator, 16, 16, 16, float> c00, c01, c10, c11,
                                                         c20, c21, c30, c31;
    wmma::fill_fragment(c00, 0.f); wmma::fill_fragment(c01, 0.f);
    wmma::fill_fragment(c10, 0.f); wmma::fill_fragment(c11, 0.f);
    wmma::fill_fragment(c20, 0.f); wmma::fill_fragment(c21, 0.f);
    wmma::fill_fragment(c30, 0.f); wmma::fill_fragment(c31, 0.f);

    const float4 zero4 = make_float4(0.f, 0.f, 0.f, 0.f);
    float4 a0, a1, a2, a3, b0, b1;
    uint4  ah0, ah1, al0, al1;

    auto load_stage = [&](int s) {
        if (MODE == 0) {
            const float* pa = gpa + s * 16;
            a0 = zf ? zero4 : *(const float4*)(pa);
            a1 = zf ? zero4 : *(const float4*)(pa + 4);
            a2 = zf ? zero4 : *(const float4*)(pa + 8);
            a3 = zf ? zero4 : *(const float4*)(pa + 12);
        } else {
            const uint4* ph = (const uint4*)(gpah + s * 16);
            ah0 = ph[0]; ah1 = ph[1];
            const uint4* pl = (const uint4*)(gpal + s * 16);
            al0 = pl[0]; al1 = pl[1];
        }
        const float* pb = gpb + (size_t)s * 16 * NDIM;
        b0 = *(const float4*)(pb);
        b1 = *(const float4*)(pb + 4);
    };

    auto store_stage = [&](__nv_bfloat16* st_) {
        if (MODE == 0) {
            uint4 hi_, lo_;
            split8(a0, a1, hi_, lo_);
            *(uint4*)(st_ + a_off)             = hi_;
            *(uint4*)(st_ + A_SLAB_E + a_off)  = lo_;
            split8(a2, a3, hi_, lo_);
            *(uint4*)(st_ + a_off + 8)             = hi_;
            *(uint4*)(st_ + A_SLAB_E + a_off + 8)  = lo_;
        } else {
            *(uint4*)(st_ + a_off)                 = ah0;
            *(uint4*)(st_ + a_off + 8)             = ah1;
            *(uint4*)(st_ + A_SLAB_E + a_off)      = al0;
            *(uint4*)(st_ + A_SLAB_E + a_off + 8)  = al1;
        }
        uint4 hi_, lo_;
        split8(b0, b1, hi_, lo_);
        *(uint4*)(st_ + 2 * A_SLAB_E + b_off)             = hi_;
        *(uint4*)(st_ + 2 * A_SLAB_E + B_SLAB_E + b_off)  = lo_;
    };

    // prologue
    load_stage(0);
    store_stage(smem);
    load_stage(1);

#pragma unroll 1
    for (int k = 0; k < NS; k++) {
        __syncthreads();
        if (k + 1 < NS) store_stage(smem + ((k + 1) & 1) * STAGE_E);
        if (k + 2 < NS) load_stage(k + 2);

        const __nv_bfloat16* st   = smem + (k & 1) * STAGE_E;
        const __nv_bfloat16* sAhi = st;
        const __nv_bfloat16* sAlo = st + A_SLAB_E;
        const __nv_bfloat16* sBhi = st + 2 * A_SLAB_E;
        const __nv_bfloat16* sBlo = st + 2 * A_SLAB_E + B_SLAB_E;

        wmma::fragment<wmma::matrix_b, 16, 16, 16, __nv_bfloat16, wmma::row_major> bH0, bL0, bH1, bL1;
        wmma::load_matrix_sync(bH0, sBhi + wn * 32,      PITCH_B);
        wmma::load_matrix_sync(bH1, sBhi + wn * 32 + 16, PITCH_B);
        wmma::load_matrix_sync(bL0, sBlo + wn * 32,      PITCH_B);
        wmma::load_matrix_sync(bL1, sBlo + wn * 32 + 16, PITCH_B);

#define M_BLOCK(mb, cA, cB) { \
        wmma::fragment<wmma::matrix_a, 16, 16, 16, __nv_bfloat16, wmma::row_major> aH_, aL_; \
        wmma::load_matrix_sync(aH_, sAhi + (wm * 64 + (mb) * 16) * PITCH_A, PITCH_A); \
        wmma::load_matrix_sync(aL_, sAlo + (wm * 64 + (mb) * 16) * PITCH_A, PITCH_A); \
        wmma::mma_sync(cA, aH_, bH0, cA); \
        wmma::mma_sync(cA, aL_, bH0, cA); \
        wmma::mma_sync(cA, aH_, bL0, cA); \
        wmma::mma_sync(cB, aH_, bH1, cB); \
        wmma::mma_sync(cB, aL_, bH1, cB); \
        wmma::mma_sync(cB, aH_, bL1, cB); \
    }
        M_BLOCK(0, c00, c01)
        M_BLOCK(1, c10, c11)
        M_BLOCK(2, c20, c21)
        M_BLOCK(3, c30, c31)
#undef M_BLOCK
    }
    __syncthreads();

    // ---- epilogue: stage fp32 through smem (reuses stage buffers) ----
    float* ebuf = (float*)smem_raw;      // 128 x 68 fp32 = 34816 B
#define EST(cv, mb, nb) \
    wmma::store_matrix_sync(ebuf + (wm * 64 + (mb) * 16) * 68 + wn * 32 + (nb) * 16, \
                            cv, 68, wmma::mem_row_major);
    EST(c00, 0, 0) EST(c01, 0, 1) EST(c10, 1, 0) EST(c11, 1, 1)
    EST(c20, 2, 0) EST(c21, 2, 1) EST(c30, 3, 0) EST(c31, 3, 1)
#undef EST
    __syncthreads();

    int c4 = (tid & 15) * 4;
    int rw = tid >> 4;                 // 0..7
    float4 bias4 = *(const float4*)(bias_g + (size_t)e * NDIM + col0 + c4);
#pragma unroll
    for (int i = 0; i < 16; i++) {
        int r = rw + i * 8;
        float4 v = *(const float4*)(ebuf + r * 68 + c4);
        v.x += bias4.x; v.y += bias4.y; v.z += bias4.z; v.w += bias4.w;
        if (MODE == 0) {
            v.x = fast_gelu(v.x);
            v.y = fast_gelu(v.y);
            v.z = fast_gelu(v.z);
            v.w = fast_gelu(v.w);
            uint2 h2, l2;
            h2.x = pack_bf2(v.x, v.y);
            h2.y = pack_bf2(v.z, v.w);
            __nv_bfloat162* hh = reinterpret_cast<__nv_bfloat162*>(&h2);
            l2.x = pack_bf2(v.x - __bfloat162float(hh[0].x), v.y - __bfloat162float(hh[0].y));
            l2.y = pack_bf2(v.z - __bfloat162float(hh[1].x), v.w - __bfloat162float(hh[1].y));
            size_t o = (size_t)(row0 + r) * DFF + col0 + c4;
            *(uint2*)(d_h_hi + o) = h2;
            *(uint2*)(d_h_lo + o) = l2;
        } else {
            *(float4*)(d_outslot + (size_t)(row0 + r) * DMODEL + col0 + c4) = v;
        }
    }
}

// ---------------- combine ----------------
__global__ void combine_kernel(float* __restrict__ out) {
    int t = blockIdx.x;
    int s0 = d_token_slot[2 * t];
    int s1 = d_token_slot[2 * t + 1];
    float g0 = d_top_g[2 * t];
    float g1 = d_top_g[2 * t + 1];
    int d = threadIdx.x * 4;
    float4 a = *(const float4*)(d_outslot + (size_t)s0 * DMODEL + d);
    float4 b = *(const float4*)(d_outslot + (size_t)s1 * DMODEL + d);
    float4 r;
    r.x = g0 * a.x + g1 * b.x;
    r.y = g0 * a.y + g1 * b.y;
    r.z = g0 * a.z + g1 * b.z;
    r.w = g0 * a.w + g1 * b.w;
    *(float4*)(out + (size_t)t * DMODEL + d) = r;
}

// ---------------- launch ----------------
extern "C" void kernel_launch(void* const* d_in, const int* in_sizes, int n_in,
                              void* d_out, int out_size)
{
    const float* x        = (const float*)d_in[0];
    const int*   city     = (const int*)d_in[1];
    const float* dt       = (const float*)d_in[2];
    const float* ddis     = (const float*)d_in[3];
    const float* drg      = (const float*)d_in[4];
    const float* dent     = (const float*)d_in[5];
    const float* city_emb = (const float*)d_in[6];
    const float* rw       = (const float*)d_in[7];
    const float* rb       = (const float*)d_in[8];
    const float* w1       = (const float*)d_in[9];
    const float* b1       = (const float*)d_in[10];
    const float* w2       = (const float*)d_in[11];
    const float* b2       = (const float*)d_in[12];

    float* out   = (float*)d_out;
    float* gate1 = (float*)d_out + (size_t)NTOK * DMODEL;

    init_kernel<<<(CAP + 255) / 256, 256>>>();
    router_kernel<<<NTOK * 32 / 256, 256>>>(x, city, dt, ddis, drg, dent,
                                            city_emb, rw, rb, gate1);
    scan_kernel<<<1, 32>>>();
    dispatch_kernel<<<(NTOK * 2 + 255) / 256, 256>>>();

    moe_wmma<0><<<dim3(DFF / 64, CAP / 128), 128>>>(x, w1, b1);
    moe_wmma<1><<<dim3(DMODEL / 64, CAP / 128), 128>>>(x, w2, b2);

    combine_kernel<<<NTOK, DMODEL / 4>>>(out);
}

// round 12
// speedup vs baseline: 2.2968x; 1.4356x over previous
#include <cuda_runtime.h>
#include <cuda_bf16.h>
#include <math.h>
#include <stdint.h>

#define NTOK   8192
#define NE     10
#define DMODEL 768
#define DFF    3072
#define LINSZ  1376
#define BM     128
#define CAP    18432          // 144 * 128

// ---- smem stage (bf16 elems): Ahi(128x40) Alo Bhi(32x72) Blo ----
#define PITCH_A 40
#define PITCH_B 72
#define A_SLAB_E (128 * PITCH_A)                 // 5120
#define B_SLAB_E (32 * PITCH_B)                  // 2304
#define STAGE_E  (2 * A_SLAB_E + 2 * B_SLAB_E)   // 14848 elems = 29696 B
#define SMEM_BYTES (2 * STAGE_E * 2)             // 59392 B

// ---------------- device scratch (283 MB — proven-safe footprint) ----------------
__device__ int   d_counts[NE];
__device__ int   d_cursor[NE];
__device__ int   d_seg_start[NE + 1];
__device__ int   d_top_e[NTOK * 2];
__device__ float d_top_g[NTOK * 2];
__device__ int   d_slot_token[CAP];
__device__ int   d_token_slot[NTOK * 2];
__device__ __nv_bfloat16 d_h_hi[(size_t)CAP * DFF];
__device__ __nv_bfloat16 d_h_lo[(size_t)CAP * DFF];
__device__ float d_outslot[(size_t)CAP * DMODEL];

// ---------------- PTX helpers (named operands only — no arrays) ----------------
__device__ __forceinline__ uint32_t smem_u32(const void* p) {
    uint32_t a;
    asm("{ .reg .u64 t; cvta.to.shared.u64 t, %1; cvt.u32.u64 %0, t; }" : "=r"(a) : "l"(p));
    return a;
}

#define LDM4(v, addr) \
    asm volatile("ldmatrix.sync.aligned.m8n8.x4.shared.b16 {%0,%1,%2,%3}, [%4];" \
                 : "=r"((v).x), "=r"((v).y), "=r"((v).z), "=r"((v).w) : "r"(addr))

#define LDM4T(v, addr) \
    asm volatile("ldmatrix.sync.aligned.m8n8.x4.trans.shared.b16 {%0,%1,%2,%3}, [%4];" \
                 : "=r"((v).x), "=r"((v).y), "=r"((v).z), "=r"((v).w) : "r"(addr))

#define MMA4(c, a, b0, b1) \
    asm volatile( \
        "mma.sync.aligned.m16n8k16.row.col.f32.bf16.bf16.f32 " \
        "{%0,%1,%2,%3}, {%4,%5,%6,%7}, {%8,%9}, {%0,%1,%2,%3};" \
        : "+f"((c).x), "+f"((c).y), "+f"((c).z), "+f"((c).w) \
        : "r"((a).x), "r"((a).y), "r"((a).z), "r"((a).w), "r"(b0), "r"(b1))

// 3-pass hi/lo for one (mb, n8 pair): cE gets n8#even, cO gets n8#odd of frag v
#define PASS3(cE, cO, aH, aL, vH, vL) \
    MMA4(cE, aH, (vH).x, (vH).y); MMA4(cE, aL, (vH).x, (vH).y); MMA4(cE, aH, (vL).x, (vL).y); \
    MMA4(cO, aH, (vH).z, (vH).w); MMA4(cO, aL, (vH).z, (vH).w); MMA4(cO, aH, (vL).z, (vL).w)

// ---------------- init ----------------
__global__ void init_kernel() {
    int i = blockIdx.x * blockDim.x + threadIdx.x;
    if (i < NE) { d_counts[i] = 0; d_cursor[i] = 0; }
    if (i < CAP) d_slot_token[i] = -1;
}

// ---------------- router: warp per token ----------------
__global__ __launch_bounds__(256) void router_kernel(
    const float* __restrict__ x, const int* __restrict__ city,
    const float* __restrict__ dt, const float* __restrict__ ddis,
    const float* __restrict__ drg, const float* __restrict__ dent,
    const float* __restrict__ city_emb, const float* __restrict__ rw,
    const float* __restrict__ rb, float* __restrict__ gate1_out)
{
    int gwarp = (blockIdx.x * blockDim.x + threadIdx.x) >> 5;
    int lane  = threadIdx.x & 31;
    if (gwarp >= NTOK) return;
    int t = gwarp;
    const float* ce = city_emb + city[0] * 32;

    float rin[43];
#pragma unroll
    for (int i = 0; i < 43; i++) {
        int f = lane + 32 * i;
        float v;
        if      (f < 768)  v = x[(size_t)t * 768 + f];
        else if (f < 800)  v = ce[f - 768];
        else if (f < 992)  v = dt[(size_t)t * 192 + (f - 800)];
        else if (f < 1184) v = ddis[(size_t)t * 192 + (f - 992)];
        else if (f < 1280) v = drg[(size_t)t * 96 + (f - 1184)];
        else               v = dent[(size_t)t * 96 + (f - 1280)];
        rin[i] = v;
    }

    float logits[NE];
#pragma unroll
    for (int e = 0; e < NE; e++) {
        const float* w = rw + e * LINSZ;
        float acc = 0.f;
#pragma unroll
        for (int i = 0; i < 43; i++) acc = fmaf(rin[i], w[lane + 32 * i], acc);
#pragma unroll
        for (int o = 16; o > 0; o >>= 1) acc += __shfl_xor_sync(0xffffffffu, acc, o);
        logits[e] = acc + rb[e];
    }

    if (lane == 0) {
        float m = logits[0];
#pragma unroll
        for (int e = 1; e < NE; e++) m = fmaxf(m, logits[e]);
        float ex[NE], s = 0.f;
#pragma unroll
        for (int e = 0; e < NE; e++) { ex[e] = expf(logits[e] - m); s += ex[e]; }
        float inv = 1.f / s;
#pragma unroll
        for (int e = 0; e < NE; e++) gate1_out[(size_t)t * NE + e] = ex[e] * inv;

        int i0 = 0;
#pragma unroll
        for (int e = 1; e < NE; e++) if (logits[e] > logits[i0]) i0 = e;
        int i1 = (i0 == 0) ? 1 : 0;
#pragma unroll
        for (int e = 0; e < NE; e++) if (e != i0 && logits[e] > logits[i1]) i1 = e;

        float e1 = expf(logits[i1] - logits[i0]);
        float g0 = 1.f / (1.f + e1);
        float g1 = e1 * g0;

        d_top_e[2 * t] = i0;     d_top_e[2 * t + 1] = i1;
        d_top_g[2 * t] = g0;     d_top_g[2 * t + 1] = g1;
        atomicAdd(&d_counts[i0], 1);
        atomicAdd(&d_counts[i1], 1);
    }
}

__global__ void scan_kernel() {
    if (threadIdx.x == 0) {
        int off = 0;
#pragma unroll
        for (int e = 0; e < NE; e++) {
            d_seg_start[e] = off;
            off += ((d_counts[e] + BM - 1) / BM) * BM;
        }
        d_seg_start[NE] = off;
    }
}

__global__ void dispatch_kernel() {
    int i = blockIdx.x * blockDim.x + threadIdx.x;
    if (i >= NTOK * 2) return;
    int e = d_top_e[i];
    int pos = atomicAdd(&d_cursor[e], 1);
    int slot = d_seg_start[e] + pos;
    d_slot_token[slot] = i >> 1;
    d_token_slot[i] = slot;
}

// ---------------- helpers ----------------
__device__ __forceinline__ uint32_t pack_bf2(float a, float b) {
    __nv_bfloat162 t;
    t.x = __float2bfloat16(a);
    t.y = __float2bfloat16(b);
    return *reinterpret_cast<uint32_t*>(&t);
}

__device__ __forceinline__ void split8(float4 f0, float4 f1, uint4& hi, uint4& lo) {
    hi.x = pack_bf2(f0.x, f0.y);
    hi.y = pack_bf2(f0.z, f0.w);
    hi.z = pack_bf2(f1.x, f1.y);
    hi.w = pack_bf2(f1.z, f1.w);
    __nv_bfloat162* h = reinterpret_cast<__nv_bfloat162*>(&hi);
    lo.x = pack_bf2(f0.x - __bfloat162float(h[0].x), f0.y - __bfloat162float(h[0].y));
    lo.y = pack_bf2(f0.z - __bfloat162float(h[1].x), f0.w - __bfloat162float(h[1].y));
    lo.z = pack_bf2(f1.x - __bfloat162float(h[2].x), f1.y - __bfloat162float(h[2].y));
    lo.w = pack_bf2(f1.z - __bfloat162float(h[3].x), f1.w - __bfloat162float(h[3].y));
}

__device__ __forceinline__ float fast_gelu(float x) {
    float z = fabsf(x) * 0.70710678118654752f;
    float t = __fdividef(1.0f, fmaf(0.3275911f, z, 1.0f));
    float p = fmaf(1.061405429f, t, -1.453152027f);
    p = fmaf(p, t, 1.421413741f);
    p = fmaf(p, t, -0.284496736f);
    p = fmaf(p, t, 0.254829592f);
    p = p * t;
    float s = 1.0f - p * __expf(-z * z);
    return 0.5f * x * (1.0f + copysignf(s, x));
}

// ---------------- raw mma.sync MoE GEMM, CTA 128x64, BK=32 ----------------
// MODE 0: d_h(hi/lo) = gelu(gather(x) @ w1[e] + b1[e])   K=768,  N=3072
// MODE 1: d_outslot = (d_h_hi + d_h_lo) @ w2[e] + b2[e]  K=3072, N=768
// 256 thr, 8 warps = 4m x 2n, warp tile 32x32. 3-pass hi/lo bf16.
template<int MODE>
__global__ __launch_bounds__(256, 1) void moe_mma(
    const float* __restrict__ Ain,
    const float* __restrict__ Wglob,
    const float* __restrict__ bias_g)
{
    constexpr int KDIM = MODE ? DFF : DMODEL;
    constexpr int NDIM = MODE ? DMODEL : DFF;
    constexpr int NS   = KDIM / 32;

    extern __shared__ __align__(256) __nv_bfloat16 smem[];

    int row0 = blockIdx.y * 128;
    if (row0 >= d_seg_start[NE]) return;
    int col0 = blockIdx.x * 64;

    int e = 0;
#pragma unroll
    for (int i = 0; i < NE; i++) if (row0 >= d_seg_start[i + 1]) e = i + 1;

    int tid  = threadIdx.x;
    int lane = tid & 31;
    int wid  = tid >> 5;
    int wm   = wid & 3;        // m block of 32 rows
    int wn   = wid >> 2;       // n block of 32 cols

    // ---- loaders ----
    // A: row ra = tid>>1, k half kg = (tid&1)*16
    int ra = tid >> 1;
    int kg = (tid & 1) * 16;
    const float* gpa = nullptr;
    const __nv_bfloat16* gpah = nullptr;
    const __nv_bfloat16* gpal = nullptr;
    bool zf = false;
    if (MODE == 0) {
        int tok = d_slot_token[row0 + ra];
        if (tok < 0) { zf = true; tok = 0; }
        gpa = Ain + (size_t)tok * DMODEL + kg;
    } else {
        gpah = d_h_hi + (size_t)(row0 + ra) * DFF + kg;
        gpal = d_h_lo + (size_t)(row0 + ra) * DFF + kg;
    }
    // B: k row kb = tid>>3 (32 rows), n base ng = (tid&7)*8
    int kb = tid >> 3;
    int ng = (tid & 7) * 8;
    const float* gpb = Wglob + (size_t)e * DMODEL * DFF + (size_t)kb * NDIM + col0 + ng;

    uint32_t a_off = (uint32_t)(ra * PITCH_A + kg);
    uint32_t b_off = (uint32_t)(kb * PITCH_B + ng);

    // ldmatrix lane addresses (bytes from stage base)
    uint32_t sb = smem_u32(smem);
    uint32_t aAddr = (uint32_t)(((wm * 32 + (lane & 15)) * PITCH_A + ((lane >> 4) << 3)) * 2);
    uint32_t bAddr = (uint32_t)((((lane & 15)) * PITCH_B + wn * 32 + ((lane >> 4) << 3)) * 2)
                   + 2 * A_SLAB_E * 2;   // B hi slab byte offset
    const uint32_t A_LO = A_SLAB_E * 2;        // bytes from Ahi to Alo
    const uint32_t B_LO = B_SLAB_E * 2;        // bytes from Bhi to Blo

    // 8 named accumulators: c{mb}{n8}
    float4 c00 = {}, c01 = {}, c02 = {}, c03 = {};
    float4 c10 = {}, c11 = {}, c12 = {}, c13 = {};

    const float4 zero4 = make_float4(0.f, 0.f, 0.f, 0.f);
    float4 a0, a1, a2, a3, b0, b1;
    uint4  ph0, ph1, pl0, pl1;

    auto load_stage = [&](int s) {
        if (MODE == 0) {
            const float* pa = gpa + s * 32;
            a0 = zf ? zero4 : *(const float4*)(pa);
            a1 = zf ? zero4 : *(const float4*)(pa + 4);
            a2 = zf ? zero4 : *(const float4*)(pa + 8);
            a3 = zf ? zero4 : *(const float4*)(pa + 12);
        } else {
            const uint4* ph = (const uint4*)(gpah + s * 32);
            ph0 = ph[0]; ph1 = ph[1];
            const uint4* pl = (const uint4*)(gpal + s * 32);
            pl0 = pl[0]; pl1 = pl[1];
        }
        const float* pb = gpb + (size_t)s * 32 * NDIM;
        b0 = *(const float4*)(pb);
        b1 = *(const float4*)(pb + 4);
    };

    auto store_stage = [&](__nv_bfloat16* st_) {
        if (MODE == 0) {
            uint4 hi_, lo_;
            split8(a0, a1, hi_, lo_);
            *(uint4*)(st_ + a_off)             = hi_;
            *(uint4*)(st_ + A_SLAB_E + a_off)  = lo_;
            split8(a2, a3, hi_, lo_);
            *(uint4*)(st_ + a_off + 8)             = hi_;
            *(uint4*)(st_ + A_SLAB_E + a_off + 8)  = lo_;
        } else {
            *(uint4*)(st_ + a_off)                 = ph0;
            *(uint4*)(st_ + a_off + 8)             = ph1;
            *(uint4*)(st_ + A_SLAB_E + a_off)      = pl0;
            *(uint4*)(st_ + A_SLAB_E + a_off + 8)  = pl1;
        }
        uint4 hi_, lo_;
        split8(b0, b1, hi_, lo_);
        *(uint4*)(st_ + 2 * A_SLAB_E + b_off)             = hi_;
        *(uint4*)(st_ + 2 * A_SLAB_E + B_SLAB_E + b_off)  = lo_;
    };

    // prologue
    load_stage(0);
    store_stage(smem);
    load_stage(1);

#pragma unroll 1
    for (int k = 0; k < NS; k++) {
        __syncthreads();
        if (k + 1 < NS) store_stage(smem + ((k + 1) & 1) * STAGE_E);
        if (k + 2 < NS) load_stage(k + 2);

        uint32_t stb = sb + (uint32_t)((k & 1) * STAGE_E * 2);
        uint32_t aB = stb + aAddr;
        uint32_t bB = stb + bAddr;

#pragma unroll
        for (int kk = 0; kk < 2; kk++) {
            uint32_t aK = aB + kk * 32;            // +16 k elems = 32 B within row
            uint32_t bK = bB + kk * (16 * PITCH_B * 2);  // +16 k rows

            // B fragments: n0-15 (v.x/.y = n8#0, v.z/.w = n8#1), n16-31
            uint4 bh0, bh1, bl0, bl1;
            LDM4T(bh0, bK);
            LDM4T(bh1, bK + 32);
            LDM4T(bl0, bK + B_LO);
            LDM4T(bl1, bK + B_LO + 32);

            // A fragments: 2 m16 blocks, hi/lo
            uint4 ah0, ah1, al0, al1;
            LDM4(ah0, aK);
            LDM4(al0, aK + A_LO);
            LDM4(ah1, aK + 16 * PITCH_A * 2);
            LDM4(al1, aK + A_LO + 16 * PITCH_A * 2);

            PASS3(c00, c01, ah0, al0, bh0, bl0);
            PASS3(c02, c03, ah0, al0, bh1, bl1);
            PASS3(c10, c11, ah1, al1, bh0, bl0);
            PASS3(c12, c13, ah1, al1, bh1, bl1);
        }
    }
    __syncthreads();

    // ---- epilogue: mma-layout regs -> smem fp32, then coalesced store ----
    float* ebuf = (float*)smem;      // 128 x 68 fp32 = 34816 B < 59392 B
    {
        int er = wm * 32 + (lane >> 2);
        int ec = wn * 32 + (lane & 3) * 2;
#define EST(cv, mb, n8) { \
        float* p = ebuf + (er + (mb) * 16) * 68 + ec + (n8) * 8; \
        *(float2*)(p)            = make_float2((cv).x, (cv).y); \
        *(float2*)(p + 8 * 68)   = make_float2((cv).z, (cv).w); \
    }
        EST(c00, 0, 0) EST(c01, 0, 1) EST(c02, 0, 2) EST(c03, 0, 3)
        EST(c10, 1, 0) EST(c11, 1, 1) EST(c12, 1, 2) EST(c13, 1, 3)
#undef EST
    }
    __syncthreads();

    int c4 = (tid & 15) * 4;
    int rw = tid >> 4;                 // 0..15
    float4 bias4 = *(const float4*)(bias_g + (size_t)e * NDIM + col0 + c4);
#pragma unroll
    for (int i = 0; i < 8; i++) {
        int r = rw + i * 16;
        float4 v = *(const float4*)(ebuf + r * 68 + c4);
        v.x += bias4.x; v.y += bias4.y; v.z += bias4.z; v.w += bias4.w;
        if (MODE == 0) {
            v.x = fast_gelu(v.x);
            v.y = fast_gelu(v.y);
            v.z = fast_gelu(v.z);
            v.w = fast_gelu(v.w);
            uint2 h2, l2;
            h2.x = pack_bf2(v.x, v.y);
            h2.y = pack_bf2(v.z, v.w);
            __nv_bfloat162* hh = reinterpret_cast<__nv_bfloat162*>(&h2);
            l2.x = pack_bf2(v.x - __bfloat162float(hh[0].x), v.y - __bfloat162float(hh[0].y));
            l2.y = pack_bf2(v.z - __bfloat162float(hh[1].x), v.w - __bfloat162float(hh[1].y));
            size_t o = (size_t)(row0 + r) * DFF + col0 + c4;
            *(uint2*)(d_h_hi + o) = h2;
            *(uint2*)(d_h_lo + o) = l2;
        } else {
            *(float4*)(d_outslot + (size_t)(row0 + r) * DMODEL + col0 + c4) = v;
        }
    }
}

// ---------------- combine ----------------
__global__ void combine_kernel(float* __restrict__ out) {
    int t = blockIdx.x;
    int s0 = d_token_slot[2 * t];
    int s1 = d_token_slot[2 * t + 1];
    float g0 = d_top_g[2 * t];
    float g1 = d_top_g[2 * t + 1];
    int d = threadIdx.x * 4;
    float4 a = *(const float4*)(d_outslot + (size_t)s0 * DMODEL + d);
    float4 b = *(const float4*)(d_outslot + (size_t)s1 * DMODEL + d);
    float4 r;
    r.x = g0 * a.x + g1 * b.x;
    r.y = g0 * a.y + g1 * b.y;
    r.z = g0 * a.z + g1 * b.z;
    r.w = g0 * a.w + g1 * b.w;
    *(float4*)(out + (size_t)t * DMODEL + d) = r;
}

// ---------------- launch ----------------
extern "C" void kernel_launch(void* const* d_in, const int* in_sizes, int n_in,
                              void* d_out, int out_size)
{
    const float* x        = (const float*)d_in[0];
    const int*   city     = (const int*)d_in[1];
    const float* dt       = (const float*)d_in[2];
    const float* ddis     = (const float*)d_in[3];
    const float* drg      = (const float*)d_in[4];
    const float* dent     = (const float*)d_in[5];
    const float* city_emb = (const float*)d_in[6];
    const float* rw       = (const float*)d_in[7];
    const float* rb       = (const float*)d_in[8];
    const float* w1       = (const float*)d_in[9];
    const float* b1       = (const float*)d_in[10];
    const float* w2       = (const float*)d_in[11];
    const float* b2       = (const float*)d_in[12];

    float* out   = (float*)d_out;
    float* gate1 = (float*)d_out + (size_t)NTOK * DMODEL;

    cudaFuncSetAttribute(moe_mma<0>, cudaFuncAttributeMaxDynamicSharedMemorySize, SMEM_BYTES);
    cudaFuncSetAttribute(moe_mma<1>, cudaFuncAttributeMaxDynamicSharedMemorySize, SMEM_BYTES);

    init_kernel<<<(CAP + 255) / 256, 256>>>();
    router_kernel<<<NTOK * 32 / 256, 256>>>(x, city, dt, ddis, drg, dent,
                                            city_emb, rw, rb, gate1);
    scan_kernel<<<1, 32>>>();
    dispatch_kernel<<<(NTOK * 2 + 255) / 256, 256>>>();

    moe_mma<0><<<dim3(DFF / 64, CAP / 128), 256, SMEM_BYTES>>>(x, w1, b1);
    moe_mma<1><<<dim3(DMODEL / 64, CAP / 128), 256, SMEM_BYTES>>>(x, w2, b2);

    combine_kernel<<<NTOK, DMODEL / 4>>>(out);
}

// round 13
// speedup vs baseline: 2.6232x; 1.1421x over previous
#include <cuda_runtime.h>
#include <cuda_bf16.h>
#include <math.h>
#include <stdint.h>

#define NTOK   8192
#define NE     10
#define DMODEL 768
#define DFF    3072
#define LINSZ  1376
#define BM     128
#define CAP    18432          // 144 * 128

// ---- smem stage (bf16 elems): Ahi(128x40) Alo Bhi(32x152) Blo ----
#define PITCH_A 40
#define PITCH_B 152
#define A_SLAB_E (128 * PITCH_A)                 // 5120
#define B_SLAB_E (32 * PITCH_B)                  // 4864
#define STAGE_E  (2 * A_SLAB_E + 2 * B_SLAB_E)   // 19968 elems = 39936 B
#define SMEM_BYTES (2 * STAGE_E * 2)             // 79872 B

// ---------------- device scratch (283 MB — proven-safe footprint) ----------------
__device__ int   d_counts[NE];
__device__ int   d_cursor[NE];
__device__ int   d_seg_start[NE + 1];
__device__ int   d_top_e[NTOK * 2];
__device__ float d_top_g[NTOK * 2];
__device__ int   d_slot_token[CAP];
__device__ int   d_token_slot[NTOK * 2];
__device__ __nv_bfloat16 d_h_hi[(size_t)CAP * DFF];
__device__ __nv_bfloat16 d_h_lo[(size_t)CAP * DFF];
__device__ float d_outslot[(size_t)CAP * DMODEL];

// ---------------- PTX helpers ----------------
__device__ __forceinline__ uint32_t smem_u32(const void* p) {
    uint32_t a;
    asm("{ .reg .u64 t; cvta.to.shared.u64 t, %1; cvt.u32.u64 %0, t; }" : "=r"(a) : "l"(p));
    return a;
}

#define LDM4(v, addr) \
    asm volatile("ldmatrix.sync.aligned.m8n8.x4.shared.b16 {%0,%1,%2,%3}, [%4];" \
                 : "=r"((v).x), "=r"((v).y), "=r"((v).z), "=r"((v).w) : "r"(addr))

#define LDM4T(v, addr) \
    asm volatile("ldmatrix.sync.aligned.m8n8.x4.trans.shared.b16 {%0,%1,%2,%3}, [%4];" \
                 : "=r"((v).x), "=r"((v).y), "=r"((v).z), "=r"((v).w) : "r"(addr))

#define MMA4(c, a, b0, b1) \
    asm volatile( \
        "mma.sync.aligned.m16n8k16.row.col.f32.bf16.bf16.f32 " \
        "{%0,%1,%2,%3}, {%4,%5,%6,%7}, {%8,%9}, {%0,%1,%2,%3};" \
        : "+f"((c).x), "+f"((c).y), "+f"((c).z), "+f"((c).w) \
        : "r"((a).x), "r"((a).y), "r"((a).z), "r"((a).w), "r"(b0), "r"(b1))

#define PASS3(cE, cO, aH, aL, vH, vL) \
    MMA4(cE, aH, (vH).x, (vH).y); MMA4(cE, aL, (vH).x, (vH).y); MMA4(cE, aH, (vL).x, (vL).y); \
    MMA4(cO, aH, (vH).z, (vH).w); MMA4(cO, aL, (vH).z, (vH).w); MMA4(cO, aH, (vL).z, (vL).w)

// ---------------- init ----------------
__global__ void init_kernel() {
    int i = blockIdx.x * blockDim.x + threadIdx.x;
    if (i < NE) { d_counts[i] = 0; d_cursor[i] = 0; }
    if (i < CAP) d_slot_token[i] = -1;
}

// ---------------- router: warp per token ----------------
__global__ __launch_bounds__(256) void router_kernel(
    const float* __restrict__ x, const int* __restrict__ city,
    const float* __restrict__ dt, const float* __restrict__ ddis,
    const float* __restrict__ drg, const float* __restrict__ dent,
    const float* __restrict__ city_emb, const float* __restrict__ rw,
    const float* __restrict__ rb, float* __restrict__ gate1_out)
{
    int gwarp = (blockIdx.x * blockDim.x + threadIdx.x) >> 5;
    int lane  = threadIdx.x & 31;
    if (gwarp >= NTOK) return;
    int t = gwarp;
    const float* ce = city_emb + city[0] * 32;

    float rin[43];
#pragma unroll
    for (int i = 0; i < 43; i++) {
        int f = lane + 32 * i;
        float v;
        if      (f < 768)  v = x[(size_t)t * 768 + f];
        else if (f < 800)  v = ce[f - 768];
        else if (f < 992)  v = dt[(size_t)t * 192 + (f - 800)];
        else if (f < 1184) v = ddis[(size_t)t * 192 + (f - 992)];
        else if (f < 1280) v = drg[(size_t)t * 96 + (f - 1184)];
        else               v = dent[(size_t)t * 96 + (f - 1280)];
        rin[i] = v;
    }

    float logits[NE];
#pragma unroll
    for (int e = 0; e < NE; e++) {
        const float* w = rw + e * LINSZ;
        float acc = 0.f;
#pragma unroll
        for (int i = 0; i < 43; i++) acc = fmaf(rin[i], w[lane + 32 * i], acc);
#pragma unroll
        for (int o = 16; o > 0; o >>= 1) acc += __shfl_xor_sync(0xffffffffu, acc, o);
        logits[e] = acc + rb[e];
    }

    if (lane == 0) {
        float m = logits[0];
#pragma unroll
        for (int e = 1; e < NE; e++) m = fmaxf(m, logits[e]);
        float ex[NE], s = 0.f;
#pragma unroll
        for (int e = 0; e < NE; e++) { ex[e] = expf(logits[e] - m); s += ex[e]; }
        float inv = 1.f / s;
#pragma unroll
        for (int e = 0; e < NE; e++) gate1_out[(size_t)t * NE + e] = ex[e] * inv;

        int i0 = 0;
#pragma unroll
        for (int e = 1; e < NE; e++) if (logits[e] > logits[i0]) i0 = e;
        int i1 = (i0 == 0) ? 1 : 0;
#pragma unroll
        for (int e = 0; e < NE; e++) if (e != i0 && logits[e] > logits[i1]) i1 = e;

        float e1 = expf(logits[i1] - logits[i0]);
        float g0 = 1.f / (1.f + e1);
        float g1 = e1 * g0;

        d_top_e[2 * t] = i0;     d_top_e[2 * t + 1] = i1;
        d_top_g[2 * t] = g0;     d_top_g[2 * t + 1] = g1;
        atomicAdd(&d_counts[i0], 1);
        atomicAdd(&d_counts[i1], 1);
    }
}

__global__ void scan_kernel() {
    if (threadIdx.x == 0) {
        int off = 0;
#pragma unroll
        for (int e = 0; e < NE; e++) {
            d_seg_start[e] = off;
            off += ((d_counts[e] + BM - 1) / BM) * BM;
        }
        d_seg_start[NE] = off;
    }
}

__global__ void dispatch_kernel() {
    int i = blockIdx.x * blockDim.x + threadIdx.x;
    if (i >= NTOK * 2) return;
    int e = d_top_e[i];
    int pos = atomicAdd(&d_cursor[e], 1);
    int slot = d_seg_start[e] + pos;
    d_slot_token[slot] = i >> 1;
    d_token_slot[i] = slot;
}

// ---------------- helpers ----------------
__device__ __forceinline__ uint32_t pack_bf2(float a, float b) {
    __nv_bfloat162 t;
    t.x = __float2bfloat16(a);
    t.y = __float2bfloat16(b);
    return *reinterpret_cast<uint32_t*>(&t);
}

__device__ __forceinline__ void split8(float4 f0, float4 f1, uint4& hi, uint4& lo) {
    hi.x = pack_bf2(f0.x, f0.y);
    hi.y = pack_bf2(f0.z, f0.w);
    hi.z = pack_bf2(f1.x, f1.y);
    hi.w = pack_bf2(f1.z, f1.w);
    __nv_bfloat162* h = reinterpret_cast<__nv_bfloat162*>(&hi);
    lo.x = pack_bf2(f0.x - __bfloat162float(h[0].x), f0.y - __bfloat162float(h[0].y));
    lo.y = pack_bf2(f0.z - __bfloat162float(h[1].x), f0.w - __bfloat162float(h[1].y));
    lo.z = pack_bf2(f1.x - __bfloat162float(h[2].x), f1.y - __bfloat162float(h[2].y));
    lo.w = pack_bf2(f1.z - __bfloat162float(h[3].x), f1.w - __bfloat162float(h[3].y));
}

__device__ __forceinline__ float fast_gelu(float x) {
    float z = fabsf(x) * 0.70710678118654752f;
    float t = __fdividef(1.0f, fmaf(0.3275911f, z, 1.0f));
    float p = fmaf(1.061405429f, t, -1.453152027f);
    p = fmaf(p, t, 1.421413741f);
    p = fmaf(p, t, -0.284496736f);
    p = fmaf(p, t, 0.254829592f);
    p = p * t;
    float s = 1.0f - p * __expf(-z * z);
    return 0.5f * x * (1.0f + copysignf(s, x));
}

// ---------------- raw mma.sync MoE GEMM, CTA 128x128, 4 warps (64x64/warp) ----------------
// MODE 0: d_h(hi/lo) = gelu(gather(x) @ w1[e] + b1[e])   K=768,  N=3072
// MODE 1: d_outslot = (d_h_hi + d_h_lo) @ w2[e] + b2[e]  K=3072, N=768
// BK=32, 128 threads, warps 2m x 2n. B register-prefetched, A JIT post-compute.
template<int MODE>
__global__ __launch_bounds__(128, 1) void moe_mma(
    const float* __restrict__ Ain,
    const float* __restrict__ Wglob,
    const float* __restrict__ bias_g)
{
    constexpr int KDIM = MODE ? DFF : DMODEL;
    constexpr int NDIM = MODE ? DMODEL : DFF;
    constexpr int NS   = KDIM / 32;

    extern __shared__ __align__(256) __nv_bfloat16 smem[];

    int row0 = blockIdx.y * 128;
    if (row0 >= d_seg_start[NE]) return;
    int col0 = blockIdx.x * 128;

    int e = 0;
#pragma unroll
    for (int i = 0; i < NE; i++) if (row0 >= d_seg_start[i + 1]) e = i + 1;

    int tid  = threadIdx.x;
    int lane = tid & 31;
    int wid  = tid >> 5;
    int wm   = wid & 1;        // m half (64 rows)
    int wn   = wid >> 1;       // n half (64 cols)

    // ---- A loader: thread owns full row 'tid' (32 k elems per stage) ----
    const float* gpa = nullptr;
    const __nv_bfloat16* gpah = nullptr;
    const __nv_bfloat16* gpal = nullptr;
    bool zf = false;
    if (MODE == 0) {
        int tok = d_slot_token[row0 + tid];
        if (tok < 0) { zf = true; tok = 0; }
        gpa = Ain + (size_t)tok * DMODEL;
    } else {
        gpah = d_h_hi + (size_t)(row0 + tid) * DFF;
        gpal = d_h_lo + (size_t)(row0 + tid) * DFF;
    }
    uint32_t a_off = (uint32_t)(tid * PITCH_A);

    // ---- B loader: kb = tid>>2 (32 rows), ngb = (tid&3)*8, j strides of 32 ----
    int kb  = tid >> 2;
    int ngb = (tid & 3) * 8;
    const float* gpb = Wglob + (size_t)e * DMODEL * DFF + (size_t)kb * NDIM + col0 + ngb;
    uint32_t b_off = (uint32_t)(kb * PITCH_B + ngb);

    // ldmatrix lane addresses (byte offsets within a stage)
    uint32_t sb = smem_u32(smem);
    uint32_t aAddr = (uint32_t)(((wm * 64 + (lane & 15)) * PITCH_A + ((lane >> 4) << 3)) * 2);
    uint32_t bAddr = (uint32_t)(((lane & 15) * PITCH_B + wn * 64 + ((lane >> 4) << 3)) * 2)
                   + 2 * A_SLAB_E * 2;
    const uint32_t A_LO = A_SLAB_E * 2;      // 10240 B
    const uint32_t B_LO = B_SLAB_E * 2;      // 9728 B

    // 32 named accumulators d{mb}{n8}
    float4 d00 = {}, d01 = {}, d02 = {}, d03 = {}, d04 = {}, d05 = {}, d06 = {}, d07 = {};
    float4 d10 = {}, d11 = {}, d12 = {}, d13 = {}, d14 = {}, d15 = {}, d16 = {}, d17 = {};
    float4 d20 = {}, d21 = {}, d22 = {}, d23 = {}, d24 = {}, d25 = {}, d26 = {}, d27 = {};
    float4 d30 = {}, d31 = {}, d32 = {}, d33 = {}, d34 = {}, d35 = {}, d36 = {}, d37 = {};

    float4 b0, b1, b2, b3, b4, b5, b6, b7;   // B prefetch: 32 floats
    const float4 zero4 = make_float4(0.f, 0.f, 0.f, 0.f);

    auto load_B = [&](int s) {
        const float* pb = gpb + (size_t)s * 32 * NDIM;
        b0 = *(const float4*)(pb);       b1 = *(const float4*)(pb + 4);
        b2 = *(const float4*)(pb + 32);  b3 = *(const float4*)(pb + 36);
        b4 = *(const float4*)(pb + 64);  b5 = *(const float4*)(pb + 68);
        b6 = *(const float4*)(pb + 96);  b7 = *(const float4*)(pb + 100);
    };
    auto store_B = [&](__nv_bfloat16* st_) {
        uint4 hi_, lo_;
        split8(b0, b1, hi_, lo_);
        *(uint4*)(st_ + 2 * A_SLAB_E + b_off)                  = hi_;
        *(uint4*)(st_ + 2 * A_SLAB_E + B_SLAB_E + b_off)       = lo_;
        split8(b2, b3, hi_, lo_);
        *(uint4*)(st_ + 2 * A_SLAB_E + b_off + 32)             = hi_;
        *(uint4*)(st_ + 2 * A_SLAB_E + B_SLAB_E + b_off + 32)  = lo_;
        split8(b4, b5, hi_, lo_);
        *(uint4*)(st_ + 2 * A_SLAB_E + b_off + 64)             = hi_;
        *(uint4*)(st_ + 2 * A_SLAB_E + B_SLAB_E + b_off + 64)  = lo_;
        split8(b6, b7, hi_, lo_);
        *(uint4*)(st_ + 2 * A_SLAB_E + b_off + 96)             = hi_;
        *(uint4*)(st_ + 2 * A_SLAB_E + B_SLAB_E + b_off + 96)  = lo_;
    };
    auto fill_A = [&](int s, __nv_bfloat16* st_) {
        if (MODE == 0) {
            const float* pa = gpa + s * 32;
            float4 a0 = zf ? zero4 : *(const float4*)(pa);
            float4 a1 = zf ? zero4 : *(const float4*)(pa + 4);
            float4 a2 = zf ? zero4 : *(const float4*)(pa + 8);
            float4 a3 = zf ? zero4 : *(const float4*)(pa + 12);
            float4 a4 = zf ? zero4 : *(const float4*)(pa + 16);
            float4 a5 = zf ? zero4 : *(const float4*)(pa + 20);
            float4 a6 = zf ? zero4 : *(const float4*)(pa + 24);
            float4 a7 = zf ? zero4 : *(const float4*)(pa + 28);
            uint4 hi_, lo_;
            split8(a0, a1, hi_, lo_);
            *(uint4*)(st_ + a_off)                  = hi_;
            *(uint4*)(st_ + A_SLAB_E + a_off)       = lo_;
            split8(a2, a3, hi_, lo_);
            *(uint4*)(st_ + a_off + 8)              = hi_;
            *(uint4*)(st_ + A_SLAB_E + a_off + 8)   = lo_;
            split8(a4, a5, hi_, lo_);
            *(uint4*)(st_ + a_off + 16)             = hi_;
            *(uint4*)(st_ + A_SLAB_E + a_off + 16)  = lo_;
            split8(a6, a7, hi_, lo_);
            *(uint4*)(st_ + a_off + 24)             = hi_;
            *(uint4*)(st_ + A_SLAB_E + a_off + 24)  = lo_;
        } else {
            const uint4* ph = (const uint4*)(gpah + s * 32);
            const uint4* pl = (const uint4*)(gpal + s * 32);
            uint4 h0 = ph[0], h1 = ph[1], h2 = ph[2], h3 = ph[3];
            uint4 l0 = pl[0], l1 = pl[1], l2 = pl[2], l3 = pl[3];
            *(uint4*)(st_ + a_off)                  = h0;
            *(uint4*)(st_ + a_off + 8)              = h1;
            *(uint4*)(st_ + a_off + 16)             = h2;
            *(uint4*)(st_ + a_off + 24)             = h3;
            *(uint4*)(st_ + A_SLAB_E + a_off)       = l0;
            *(uint4*)(st_ + A_SLAB_E + a_off + 8)   = l1;
            *(uint4*)(st_ + A_SLAB_E + a_off + 16)  = l2;
            *(uint4*)(st_ + A_SLAB_E + a_off + 24)  = l3;
        }
    };

    // prologue: fill stage 0, prefetch B for stage 1
    load_B(0);
    fill_A(0, smem);
    store_B(smem);
    if (NS > 1) load_B(1);

#pragma unroll 1
    for (int k = 0; k < NS; k++) {
        __syncthreads();

        uint32_t stb = sb + (uint32_t)((k & 1) * STAGE_E * 2);
        uint32_t aB = stb + aAddr;
        uint32_t bB = stb + bAddr;

#define KK_BLOCK(AOFF, BOFF) { \
        uint4 ah0, al0, ah1, al1, ah2, al2, ah3, al3; \
        LDM4(ah0, aB + (AOFF));                         LDM4(al0, aB + (AOFF) + A_LO); \
        LDM4(ah1, aB + (AOFF) + 1 * 16 * PITCH_A * 2);  LDM4(al1, aB + (AOFF) + A_LO + 1 * 16 * PITCH_A * 2); \
        LDM4(ah2, aB + (AOFF) + 2 * 16 * PITCH_A * 2);  LDM4(al2, aB + (AOFF) + A_LO + 2 * 16 * PITCH_A * 2); \
        LDM4(ah3, aB + (AOFF) + 3 * 16 * PITCH_A * 2);  LDM4(al3, aB + (AOFF) + A_LO + 3 * 16 * PITCH_A * 2); \
        { uint4 bh, bl; \
          LDM4T(bh, bB + (BOFF));        LDM4T(bl, bB + (BOFF) + B_LO); \
          PASS3(d00, d01, ah0, al0, bh, bl); \
          PASS3(d10, d11, ah1, al1, bh, bl); \
          PASS3(d20, d21, ah2, al2, bh, bl); \
          PASS3(d30, d31, ah3, al3, bh, bl); } \
        { uint4 bh, bl; \
          LDM4T(bh, bB + (BOFF) + 32);   LDM4T(bl, bB + (BOFF) + B_LO + 32); \
          PASS3(d02, d03, ah0, al0, bh, bl); \
          PASS3(d12, d13, ah1, al1, bh, bl); \
          PASS3(d22, d23, ah2, al2, bh, bl); \
          PASS3(d32, d33, ah3, al3, bh, bl); } \
        { uint4 bh, bl; \
          LDM4T(bh, bB + (BOFF) + 64);   LDM4T(bl, bB + (BOFF) + B_LO + 64); \
          PASS3(d04, d05, ah0, al0, bh, bl); \
          PASS3(d14, d15, ah1, al1, bh, bl); \
          PASS3(d24, d25, ah2, al2, bh, bl); \
          PASS3(d34, d35, ah3, al3, bh, bl); } \
        { uint4 bh, bl; \
          LDM4T(bh, bB + (BOFF) + 96);   LDM4T(bl, bB + (BOFF) + B_LO + 96); \
          PASS3(d06, d07, ah0, al0, bh, bl); \
          PASS3(d16, d17, ah1, al1, bh, bl); \
          PASS3(d26, d27, ah2, al2, bh, bl); \
          PASS3(d36, d37, ah3, al3, bh, bl); } \
    }
        KK_BLOCK(0, 0)
        KK_BLOCK(32, 16 * PITCH_B * 2)
#undef KK_BLOCK

        if (k + 1 < NS) {
            __nv_bfloat16* nb = smem + ((k + 1) & 1) * STAGE_E;
            fill_A(k + 1, nb);
            store_B(nb);
        }
        if (k + 2 < NS) load_B(k + 2);
    }
    __syncthreads();

    // ---- epilogue: regs -> smem fp32, then coalesced bias/gelu/store ----
    float* ebuf = (float*)smem;      // 128 x 132 fp32 = 67584 B < 79872 B
    {
        int er = wm * 64 + (lane >> 2);
        int ec = wn * 64 + (lane & 3) * 2;
#define EST(cv, mb, n8) { \
        float* p = ebuf + (er + (mb) * 16) * 132 + ec + (n8) * 8; \
        *(float2*)(p)          = make_float2((cv).x, (cv).y); \
        *(float2*)(p + 8*132)  = make_float2((cv).z, (cv).w); \
    }
        EST(d00,0,0) EST(d01,0,1) EST(d02,0,2) EST(d03,0,3) EST(d04,0,4) EST(d05,0,5) EST(d06,0,6) EST(d07,0,7)
        EST(d10,1,0) EST(d11,1,1) EST(d12,1,2) EST(d13,1,3) EST(d14,1,4) EST(d15,1,5) EST(d16,1,6) EST(d17,1,7)
        EST(d20,2,0) EST(d21,2,1) EST(d22,2,2) EST(d23,2,3) EST(d24,2,4) EST(d25,2,5) EST(d26,2,6) EST(d27,2,7)
        EST(d30,3,0) EST(d31,3,1) EST(d32,3,2) EST(d33,3,3) EST(d34,3,4) EST(d35,3,5) EST(d36,3,6) EST(d37,3,7)
#undef EST
    }
    __syncthreads();

    int c4 = (tid & 31) * 4;
    int rw = tid >> 5;                 // 0..3
    float4 bias4 = *(const float4*)(bias_g + (size_t)e * NDIM + col0 + c4);
#pragma unroll
    for (int i = 0; i < 32; i++) {
        int r = rw + i * 4;
        float4 v = *(const float4*)(ebuf + r * 132 + c4);
        v.x += bias4.x; v.y += bias4.y; v.z += bias4.z; v.w += bias4.w;
        if (MODE == 0) {
            v.x = fast_gelu(v.x);
            v.y = fast_gelu(v.y);
            v.z = fast_gelu(v.z);
            v.w = fast_gelu(v.w);
            uint2 h2, l2;
            h2.x = pack_bf2(v.x, v.y);
            h2.y = pack_bf2(v.z, v.w);
            __nv_bfloat162* hh = reinterpret_cast<__nv_bfloat162*>(&h2);
            l2.x = pack_bf2(v.x - __bfloat162float(hh[0].x), v.y - __bfloat162float(hh[0].y));
            l2.y = pack_bf2(v.z - __bfloat162float(hh[1].x), v.w - __bfloat162float(hh[1].y));
            size_t o = (size_t)(row0 + r) * DFF + col0 + c4;
            *(uint2*)(d_h_hi + o) = h2;
            *(uint2*)(d_h_lo + o) = l2;
        } else {
            *(float4*)(d_outslot + (size_t)(row0 + r) * DMODEL + col0 + c4) = v;
        }
    }
}

// ---------------- combine ----------------
__global__ void combine_kernel(float* __restrict__ out) {
    int t = blockIdx.x;
    int s0 = d_token_slot[2 * t];
    int s1 = d_token_slot[2 * t + 1];
    float g0 = d_top_g[2 * t];
    float g1 = d_top_g[2 * t + 1];
    int d = threadIdx.x * 4;
    float4 a = *(const float4*)(d_outslot + (size_t)s0 * DMODEL + d);
    float4 b = *(const float4*)(d_outslot + (size_t)s1 * DMODEL + d);
    float4 r;
    r.x = g0 * a.x + g1 * b.x;
    r.y = g0 * a.y + g1 * b.y;
    r.z = g0 * a.z + g1 * b.z;
    r.w = g0 * a.w + g1 * b.w;
    *(float4*)(out + (size_t)t * DMODEL + d) = r;
}

// ---------------- launch ----------------
extern "C" void kernel_launch(void* const* d_in, const int* in_sizes, int n_in,
                              void* d_out, int out_size)
{
    const float* x        = (const float*)d_in[0];
    const int*   city     = (const int*)d_in[1];
    const float* dt       = (const float*)d_in[2];
    const float* ddis     = (const float*)d_in[3];
    const float* drg      = (const float*)d_in[4];
    const float* dent     = (const float*)d_in[5];
    const float* city_emb = (const float*)d_in[6];
    const float* rw       = (const float*)d_in[7];
    const float* rb       = (const float*)d_in[8];
    const float* w1       = (const float*)d_in[9];
    const float* b1       = (const float*)d_in[10];
    const float* w2       = (const float*)d_in[11];
    const float* b2       = (const float*)d_in[12];

    float* out   = (float*)d_out;
    float* gate1 = (float*)d_out + (size_t)NTOK * DMODEL;

    cudaFuncSetAttribute(moe_mma<0>, cudaFuncAttributeMaxDynamicSharedMemorySize, SMEM_BYTES);
    cudaFuncSetAttribute(moe_mma<1>, cudaFuncAttributeMaxDynamicSharedMemorySize, SMEM_BYTES);

    init_kernel<<<(CAP + 255) / 256, 256>>>();
    router_kernel<<<NTOK * 32 / 256, 256>>>(x, city, dt, ddis, drg, dent,
                                            city_emb, rw, rb, gate1);
    scan_kernel<<<1, 32>>>();
    dispatch_kernel<<<(NTOK * 2 + 255) / 256, 256>>>();

    moe_mma<0><<<dim3(DFF / 128, CAP / 128), 128, SMEM_BYTES>>>(x, w1, b1);
    moe_mma<1><<<dim3(DMODEL / 128, CAP / 128), 128, SMEM_BYTES>>>(x, w2, b2);

    combine_kernel<<<NTOK, DMODEL / 4>>>(out);
}

// round 14
// speedup vs baseline: 2.7462x; 1.0469x over previous
#include <cuda_runtime.h>
#include <cuda_bf16.h>
#include <math.h>
#include <stdint.h>

#define NTOK   8192
#define NE     10
#define DMODEL 768
#define DFF    3072
#define LINSZ  1376
#define BM     128
#define CAP    18432          // 144 * 128

// ---- smem stage (bf16 elems): Ahi(128x40) Alo Bhi(32x136) Blo ----
#define PITCH_A 40
#define PITCH_B 136
#define A_SLAB_E (128 * PITCH_A)                 // 5120
#define B_SLAB_E (32 * PITCH_B)                  // 4352
#define STAGE_E  (2 * A_SLAB_E + 2 * B_SLAB_E)   // 18944 elems = 37888 B
#define SMEM_BYTES (2 * STAGE_E * 2)             // 75776 B

// ---------------- device scratch (283 MB — proven-safe footprint) ----------------
__device__ int   d_counts[NE];
__device__ int   d_cursor[NE];
__device__ int   d_seg_start[NE + 1];
__device__ int   d_top_e[NTOK * 2];
__device__ float d_top_g[NTOK * 2];
__device__ int   d_slot_token[CAP];
__device__ int   d_token_slot[NTOK * 2];
__device__ __nv_bfloat16 d_h_hi[(size_t)CAP * DFF];
__device__ __nv_bfloat16 d_h_lo[(size_t)CAP * DFF];
__device__ float d_outslot[(size_t)CAP * DMODEL];

// ---------------- PTX helpers ----------------
__device__ __forceinline__ uint32_t smem_u32(const void* p) {
    uint32_t a;
    asm("{ .reg .u64 t; cvta.to.shared.u64 t, %1; cvt.u32.u64 %0, t; }" : "=r"(a) : "l"(p));
    return a;
}

__device__ __forceinline__ void cpa16(uint32_t dst, const void* src) {
    asm volatile("cp.async.cg.shared.global [%0], [%1], 16;"
                 :: "r"(dst), "l"(src) : "memory");
}
#define CP_COMMIT() asm volatile("cp.async.commit_group;" ::: "memory")
#define CP_WAIT0()  asm volatile("cp.async.wait_group 0;" ::: "memory")

#define LDM4(v, addr) \
    asm volatile("ldmatrix.sync.aligned.m8n8.x4.shared.b16 {%0,%1,%2,%3}, [%4];" \
                 : "=r"((v).x), "=r"((v).y), "=r"((v).z), "=r"((v).w) : "r"(addr))

#define LDM4T(v, addr) \
    asm volatile("ldmatrix.sync.aligned.m8n8.x4.trans.shared.b16 {%0,%1,%2,%3}, [%4];" \
                 : "=r"((v).x), "=r"((v).y), "=r"((v).z), "=r"((v).w) : "r"(addr))

#define MMA4(c, a, b0, b1) \
    asm volatile( \
        "mma.sync.aligned.m16n8k16.row.col.f32.bf16.bf16.f32 " \
        "{%0,%1,%2,%3}, {%4,%5,%6,%7}, {%8,%9}, {%0,%1,%2,%3};" \
        : "+f"((c).x), "+f"((c).y), "+f"((c).z), "+f"((c).w) \
        : "r"((a).x), "r"((a).y), "r"((a).z), "r"((a).w), "r"(b0), "r"(b1))

#define PASS3(cE, cO, aH, aL, vH, vL) \
    MMA4(cE, aH, (vH).x, (vH).y); MMA4(cE, aL, (vH).x, (vH).y); MMA4(cE, aH, (vL).x, (vL).y); \
    MMA4(cO, aH, (vH).z, (vH).w); MMA4(cO, aL, (vH).z, (vH).w); MMA4(cO, aH, (vL).z, (vL).w)

// ---------------- init ----------------
__global__ void init_kernel() {
    int i = blockIdx.x * blockDim.x + threadIdx.x;
    if (i < NE) { d_counts[i] = 0; d_cursor[i] = 0; }
    if (i < CAP) d_slot_token[i] = -1;
}

// ---------------- router: warp per token ----------------
__global__ __launch_bounds__(256) void router_kernel(
    const float* __restrict__ x, const int* __restrict__ city,
    const float* __restrict__ dt, const float* __restrict__ ddis,
    const float* __restrict__ drg, const float* __restrict__ dent,
    const float* __restrict__ city_emb, const float* __restrict__ rw,
    const float* __restrict__ rb, float* __restrict__ gate1_out)
{
    int gwarp = (blockIdx.x * blockDim.x + threadIdx.x) >> 5;
    int lane  = threadIdx.x & 31;
    if (gwarp >= NTOK) return;
    int t = gwarp;
    const float* ce = city_emb + city[0] * 32;

    float rin[43];
#pragma unroll
    for (int i = 0; i < 43; i++) {
        int f = lane + 32 * i;
        float v;
        if      (f < 768)  v = x[(size_t)t * 768 + f];
        else if (f < 800)  v = ce[f - 768];
        else if (f < 992)  v = dt[(size_t)t * 192 + (f - 800)];
        else if (f < 1184) v = ddis[(size_t)t * 192 + (f - 992)];
        else if (f < 1280) v = drg[(size_t)t * 96 + (f - 1184)];
        else               v = dent[(size_t)t * 96 + (f - 1280)];
        rin[i] = v;
    }

    float logits[NE];
#pragma unroll
    for (int e = 0; e < NE; e++) {
        const float* w = rw + e * LINSZ;
        float acc = 0.f;
#pragma unroll
        for (int i = 0; i < 43; i++) acc = fmaf(rin[i], w[lane + 32 * i], acc);
#pragma unroll
        for (int o = 16; o > 0; o >>= 1) acc += __shfl_xor_sync(0xffffffffu, acc, o);
        logits[e] = acc + rb[e];
    }

    if (lane == 0) {
        float m = logits[0];
#pragma unroll
        for (int e = 1; e < NE; e++) m = fmaxf(m, logits[e]);
        float ex[NE], s = 0.f;
#pragma unroll
        for (int e = 0; e < NE; e++) { ex[e] = expf(logits[e] - m); s += ex[e]; }
        float inv = 1.f / s;
#pragma unroll
        for (int e = 0; e < NE; e++) gate1_out[(size_t)t * NE + e] = ex[e] * inv;

        int i0 = 0;
#pragma unroll
        for (int e = 1; e < NE; e++) if (logits[e] > logits[i0]) i0 = e;
        int i1 = (i0 == 0) ? 1 : 0;
#pragma unroll
        for (int e = 0; e < NE; e++) if (e != i0 && logits[e] > logits[i1]) i1 = e;

        float e1 = expf(logits[i1] - logits[i0]);
        float g0 = 1.f / (1.f + e1);
        float g1 = e1 * g0;

        d_top_e[2 * t] = i0;     d_top_e[2 * t + 1] = i1;
        d_top_g[2 * t] = g0;     d_top_g[2 * t + 1] = g1;
        atomicAdd(&d_counts[i0], 1);
        atomicAdd(&d_counts[i1], 1);
    }
}

__global__ void scan_kernel() {
    if (threadIdx.x == 0) {
        int off = 0;
#pragma unroll
        for (int e = 0; e < NE; e++) {
            d_seg_start[e] = off;
            off += ((d_counts[e] + BM - 1) / BM) * BM;
        }
        d_seg_start[NE] = off;
    }
}

__global__ void dispatch_kernel() {
    int i = blockIdx.x * blockDim.x + threadIdx.x;
    if (i >= NTOK * 2) return;
    int e = d_top_e[i];
    int pos = atomicAdd(&d_cursor[e], 1);
    int slot = d_seg_start[e] + pos;
    d_slot_token[slot] = i >> 1;
    d_token_slot[i] = slot;
}

// ---------------- helpers ----------------
// truncation hi/lo split: hi = top 16 bits (PRMT pack), lo = exact remainder truncated
__device__ __forceinline__ void split8t(float4 f0, float4 f1, uint4& hi, uint4& lo) {
    uint32_t u0 = __float_as_uint(f0.x), u1 = __float_as_uint(f0.y);
    uint32_t u2 = __float_as_uint(f0.z), u3 = __float_as_uint(f0.w);
    uint32_t u4 = __float_as_uint(f1.x), u5 = __float_as_uint(f1.y);
    uint32_t u6 = __float_as_uint(f1.z), u7 = __float_as_uint(f1.w);
    hi.x = __byte_perm(u0, u1, 0x7632);
    hi.y = __byte_perm(u2, u3, 0x7632);
    hi.z = __byte_perm(u4, u5, 0x7632);
    hi.w = __byte_perm(u6, u7, 0x7632);
    float r0 = f0.x - __uint_as_float(u0 & 0xFFFF0000u);
    float r1 = f0.y - __uint_as_float(u1 & 0xFFFF0000u);
    float r2 = f0.z - __uint_as_float(u2 & 0xFFFF0000u);
    float r3 = f0.w - __uint_as_float(u3 & 0xFFFF0000u);
    float r4 = f1.x - __uint_as_float(u4 & 0xFFFF0000u);
    float r5 = f1.y - __uint_as_float(u5 & 0xFFFF0000u);
    float r6 = f1.z - __uint_as_float(u6 & 0xFFFF0000u);
    float r7 = f1.w - __uint_as_float(u7 & 0xFFFF0000u);
    lo.x = __byte_perm(__float_as_uint(r0), __float_as_uint(r1), 0x7632);
    lo.y = __byte_perm(__float_as_uint(r2), __float_as_uint(r3), 0x7632);
    lo.z = __byte_perm(__float_as_uint(r4), __float_as_uint(r5), 0x7632);
    lo.w = __byte_perm(__float_as_uint(r6), __float_as_uint(r7), 0x7632);
}

__device__ __forceinline__ void split2t(float v0, float v1, uint32_t& hi, uint32_t& lo) {
    uint32_t u0 = __float_as_uint(v0), u1 = __float_as_uint(v1);
    hi = __byte_perm(u0, u1, 0x7632);
    float r0 = v0 - __uint_as_float(u0 & 0xFFFF0000u);
    float r1 = v1 - __uint_as_float(u1 & 0xFFFF0000u);
    lo = __byte_perm(__float_as_uint(r0), __float_as_uint(r1), 0x7632);
}

__device__ __forceinline__ float fast_gelu(float x) {
    float z = fabsf(x) * 0.70710678118654752f;
    float t = __fdividef(1.0f, fmaf(0.3275911f, z, 1.0f));
    float p = fmaf(1.061405429f, t, -1.453152027f);
    p = fmaf(p, t, 1.421413741f);
    p = fmaf(p, t, -0.284496736f);
    p = fmaf(p, t, 0.254829592f);
    p = p * t;
    float s = 1.0f - p * __expf(-z * z);
    return 0.5f * x * (1.0f + copysignf(s, x));
}

// ---------------- raw mma.sync MoE GEMM, CTA 128x128, 4 warps (64x64/warp) ----------------
// MODE 0: d_h(hi/lo) = gelu(gather(x) @ w1[e] + b1[e])   K=768,  N=3072
// MODE 1: d_outslot = (d_h_hi + d_h_lo) @ w2[e] + b2[e]  K=3072, N=768
// BK=32. B register-prefetched + split in regs; A: MODE0 JIT-split, MODE1 cp.async.
template<int MODE>
__global__ __launch_bounds__(128, 1) void moe_mma(
    const float* __restrict__ Ain,
    const float* __restrict__ Wglob,
    const float* __restrict__ bias_g)
{
    constexpr int KDIM = MODE ? DFF : DMODEL;
    constexpr int NDIM = MODE ? DMODEL : DFF;
    constexpr int NS   = KDIM / 32;

    extern __shared__ __align__(256) __nv_bfloat16 smem[];

    int row0 = blockIdx.y * 128;
    if (row0 >= d_seg_start[NE]) return;
    int col0 = blockIdx.x * 128;

    int e = 0;
#pragma unroll
    for (int i = 0; i < NE; i++) if (row0 >= d_seg_start[i + 1]) e = i + 1;

    int tid  = threadIdx.x;
    int lane = tid & 31;
    int wid  = tid >> 5;
    int wm   = wid & 1;
    int wn   = wid >> 1;

    // ---- A loader: thread owns full row 'tid' (32 k elems / stage) ----
    const float* gpa = nullptr;
    const __nv_bfloat16* gpah = nullptr;
    const __nv_bfloat16* gpal = nullptr;
    bool zf = false;
    if (MODE == 0) {
        int tok = d_slot_token[row0 + tid];
        if (tok < 0) { zf = true; tok = 0; }
        gpa = Ain + (size_t)tok * DMODEL;
    } else {
        gpah = d_h_hi + (size_t)(row0 + tid) * DFF;
        gpal = d_h_lo + (size_t)(row0 + tid) * DFF;
    }
    uint32_t a_off = (uint32_t)(tid * PITCH_A);

    // ---- B loader: kb = tid>>2 (32 rows), ngb = (tid&3)*8, strides of 32 cols ----
    int kb  = tid >> 2;
    int ngb = (tid & 3) * 8;
    const float* gpb = Wglob + (size_t)e * DMODEL * DFF + (size_t)kb * NDIM + col0 + ngb;
    uint32_t b_off = (uint32_t)(kb * PITCH_B + ngb);

    uint32_t sb = smem_u32(smem);
    uint32_t aAddr = (uint32_t)(((wm * 64 + (lane & 15)) * PITCH_A + ((lane >> 4) << 3)) * 2);
    uint32_t bAddr = (uint32_t)(((lane & 15) * PITCH_B + wn * 64 + ((lane >> 4) << 3)) * 2)
                   + 2 * A_SLAB_E * 2;
    const uint32_t A_LO = A_SLAB_E * 2;
    const uint32_t B_LO = B_SLAB_E * 2;

    // 32 named accumulators
    float4 d00 = {}, d01 = {}, d02 = {}, d03 = {}, d04 = {}, d05 = {}, d06 = {}, d07 = {};
    float4 d10 = {}, d11 = {}, d12 = {}, d13 = {}, d14 = {}, d15 = {}, d16 = {}, d17 = {};
    float4 d20 = {}, d21 = {}, d22 = {}, d23 = {}, d24 = {}, d25 = {}, d26 = {}, d27 = {};
    float4 d30 = {}, d31 = {}, d32 = {}, d33 = {}, d34 = {}, d35 = {}, d36 = {}, d37 = {};

    float4 b0, b1, b2, b3, b4, b5, b6, b7;
    const float4 zero4 = make_float4(0.f, 0.f, 0.f, 0.f);

    auto load_B = [&](int s) {
        const float* pb = gpb + (size_t)s * 32 * NDIM;
        b0 = *(const float4*)(pb);       b1 = *(const float4*)(pb + 4);
        b2 = *(const float4*)(pb + 32);  b3 = *(const float4*)(pb + 36);
        b4 = *(const float4*)(pb + 64);  b5 = *(const float4*)(pb + 68);
        b6 = *(const float4*)(pb + 96);  b7 = *(const float4*)(pb + 100);
    };
    auto store_B = [&](__nv_bfloat16* st_) {
        uint4 hi_, lo_;
        split8t(b0, b1, hi_, lo_);
        *(uint4*)(st_ + 2 * A_SLAB_E + b_off)                  = hi_;
        *(uint4*)(st_ + 2 * A_SLAB_E + B_SLAB_E + b_off)       = lo_;
        split8t(b2, b3, hi_, lo_);
        *(uint4*)(st_ + 2 * A_SLAB_E + b_off + 32)             = hi_;
        *(uint4*)(st_ + 2 * A_SLAB_E + B_SLAB_E + b_off + 32)  = lo_;
        split8t(b4, b5, hi_, lo_);
        *(uint4*)(st_ + 2 * A_SLAB_E + b_off + 64)             = hi_;
        *(uint4*)(st_ + 2 * A_SLAB_E + B_SLAB_E + b_off + 64)  = lo_;
        split8t(b6, b7, hi_, lo_);
        *(uint4*)(st_ + 2 * A_SLAB_E + b_off + 96)             = hi_;
        *(uint4*)(st_ + 2 * A_SLAB_E + B_SLAB_E + b_off + 96)  = lo_;
    };
    auto fill_A = [&](int s, __nv_bfloat16* st_) {
        if (MODE == 0) {
            const float* pa = gpa + s * 32;
            float4 a0 = zf ? zero4 : *(const float4*)(pa);
            float4 a1 = zf ? zero4 : *(const float4*)(pa + 4);
            float4 a2 = zf ? zero4 : *(const float4*)(pa + 8);
            float4 a3 = zf ? zero4 : *(const float4*)(pa + 12);
            float4 a4 = zf ? zero4 : *(const float4*)(pa + 16);
            float4 a5 = zf ? zero4 : *(const float4*)(pa + 20);
            float4 a6 = zf ? zero4 : *(const float4*)(pa + 24);
            float4 a7 = zf ? zero4 : *(const float4*)(pa + 28);
            uint4 hi_, lo_;
            split8t(a0, a1, hi_, lo_);
            *(uint4*)(st_ + a_off)                  = hi_;
            *(uint4*)(st_ + A_SLAB_E + a_off)       = lo_;
            split8t(a2, a3, hi_, lo_);
            *(uint4*)(st_ + a_off + 8)              = hi_;
            *(uint4*)(st_ + A_SLAB_E + a_off + 8)   = lo_;
            split8t(a4, a5, hi_, lo_);
            *(uint4*)(st_ + a_off + 16)             = hi_;
            *(uint4*)(st_ + A_SLAB_E + a_off + 16)  = lo_;
            split8t(a6, a7, hi_, lo_);
            *(uint4*)(st_ + a_off + 24)             = hi_;
            *(uint4*)(st_ + A_SLAB_E + a_off + 24)  = lo_;
        } else {
            // h is already bf16 hi/lo: async copy 8 x 16B straight into smem
            uint32_t dst = smem_u32(st_);
            const char* ph = (const char*)(gpah + s * 32);
            const char* pl = (const char*)(gpal + s * 32);
            cpa16(dst + a_off * 2,                   ph);
            cpa16(dst + a_off * 2 + 16,              ph + 16);
            cpa16(dst + a_off * 2 + 32,              ph + 32);
            cpa16(dst + a_off * 2 + 48,              ph + 48);
            cpa16(dst + (A_SLAB_E + a_off) * 2,      pl);
            cpa16(dst + (A_SLAB_E + a_off) * 2 + 16, pl + 16);
            cpa16(dst + (A_SLAB_E + a_off) * 2 + 32, pl + 32);
            cpa16(dst + (A_SLAB_E + a_off) * 2 + 48, pl + 48);
        }
    };

    // prologue: fill stage 0, prefetch B for stage 1
    load_B(0);
    fill_A(0, smem);
    store_B(smem);
    CP_COMMIT();
    if (NS > 1) load_B(1);

#pragma unroll 1
    for (int k = 0; k < NS; k++) {
        CP_WAIT0();
        __syncthreads();

        uint32_t stb = sb + (uint32_t)((k & 1) * STAGE_E * 2);
        uint32_t aB = stb + aAddr;
        uint32_t bB = stb + bAddr;

#define KK_BLOCK(AOFF, BOFF) { \
        uint4 ah0, al0, ah1, al1, ah2, al2, ah3, al3; \
        LDM4(ah0, aB + (AOFF));                         LDM4(al0, aB + (AOFF) + A_LO); \
        LDM4(ah1, aB + (AOFF) + 1 * 16 * PITCH_A * 2);  LDM4(al1, aB + (AOFF) + A_LO + 1 * 16 * PITCH_A * 2); \
        LDM4(ah2, aB + (AOFF) + 2 * 16 * PITCH_A * 2);  LDM4(al2, aB + (AOFF) + A_LO + 2 * 16 * PITCH_A * 2); \
        LDM4(ah3, aB + (AOFF) + 3 * 16 * PITCH_A * 2);  LDM4(al3, aB + (AOFF) + A_LO + 3 * 16 * PITCH_A * 2); \
        { uint4 bh, bl; \
          LDM4T(bh, bB + (BOFF));        LDM4T(bl, bB + (BOFF) + B_LO); \
          PASS3(d00, d01, ah0, al0, bh, bl); \
          PASS3(d10, d11, ah1, al1, bh, bl); \
          PASS3(d20, d21, ah2, al2, bh, bl); \
          PASS3(d30, d31, ah3, al3, bh, bl); } \
        { uint4 bh, bl; \
          LDM4T(bh, bB + (BOFF) + 32);   LDM4T(bl, bB + (BOFF) + B_LO + 32); \
          PASS3(d02, d03, ah0, al0, bh, bl); \
          PASS3(d12, d13, ah1, al1, bh, bl); \
          PASS3(d22, d23, ah2, al2, bh, bl); \
          PASS3(d32, d33, ah3, al3, bh, bl); } \
        { uint4 bh, bl; \
          LDM4T(bh, bB + (BOFF) + 64);   LDM4T(bl, bB + (BOFF) + B_LO + 64); \
          PASS3(d04, d05, ah0, al0, bh, bl); \
          PASS3(d14, d15, ah1, al1, bh, bl); \
          PASS3(d24, d25, ah2, al2, bh, bl); \
          PASS3(d34, d35, ah3, al3, bh, bl); } \
        { uint4 bh, bl; \
          LDM4T(bh, bB + (BOFF) + 96);   LDM4T(bl, bB + (BOFF) + B_LO + 96); \
          PASS3(d06, d07, ah0, al0, bh, bl); \
          PASS3(d16, d17, ah1, al1, bh, bl); \
          PASS3(d26, d27, ah2, al2, bh, bl); \
          PASS3(d36, d37, ah3, al3, bh, bl); } \
    }
        KK_BLOCK(0, 0)
        KK_BLOCK(32, 16 * PITCH_B * 2)
#undef KK_BLOCK

        if (k + 1 < NS) {
            __nv_bfloat16* nb = smem + ((k + 1) & 1) * STAGE_E;
            fill_A(k + 1, nb);
            store_B(nb);
        }
        CP_COMMIT();
        if (k + 2 < NS) load_B(k + 2);
    }
    __syncthreads();

    // ---- epilogue: regs -> smem fp32, then coalesced bias/gelu/store ----
    float* ebuf = (float*)smem;      // 128 x 132 fp32 = 67584 B < 75776 B
    {
        int er = wm * 64 + (lane >> 2);
        int ec = wn * 64 + (lane & 3) * 2;
#define EST(cv, mb, n8) { \
        float* p = ebuf + (er + (mb) * 16) * 132 + ec + (n8) * 8; \
        *(float2*)(p)          = make_float2((cv).x, (cv).y); \
        *(float2*)(p + 8*132)  = make_float2((cv).z, (cv).w); \
    }
        EST(d00,0,0) EST(d01,0,1) EST(d02,0,2) EST(d03,0,3) EST(d04,0,4) EST(d05,0,5) EST(d06,0,6) EST(d07,0,7)
        EST(d10,1,0) EST(d11,1,1) EST(d12,1,2) EST(d13,1,3) EST(d14,1,4) EST(d15,1,5) EST(d16,1,6) EST(d17,1,7)
        EST(d20,2,0) EST(d21,2,1) EST(d22,2,2) EST(d23,2,3) EST(d24,2,4) EST(d25,2,5) EST(d26,2,6) EST(d27,2,7)
        EST(d30,3,0) EST(d31,3,1) EST(d32,3,2) EST(d33,3,3) EST(d34,3,4) EST(d35,3,5) EST(d36,3,6) EST(d37,3,7)
#undef EST
    }
    __syncthreads();

    int c4 = (tid & 31) * 4;
    int rw = tid >> 5;
    float4 bias4 = *(const float4*)(bias_g + (size_t)e * NDIM + col0 + c4);
#pragma unroll
    for (int i = 0; i < 32; i++) {
        int r = rw + i * 4;
        float4 v = *(const float4*)(ebuf + r * 132 + c4);
        v.x += bias4.x; v.y += bias4.y; v.z += bias4.z; v.w += bias4.w;
        if (MODE == 0) {
            v.x = fast_gelu(v.x);
            v.y = fast_gelu(v.y);
            v.z = fast_gelu(v.z);
            v.w = fast_gelu(v.w);
            uint2 h2, l2;
            split2t(v.x, v.y, h2.x, l2.x);
            split2t(v.z, v.w, h2.y, l2.y);
            size_t o = (size_t)(row0 + r) * DFF + col0 + c4;
            *(uint2*)(d_h_hi + o) = h2;
            *(uint2*)(d_h_lo + o) = l2;
        } else {
            *(float4*)(d_outslot + (size_t)(row0 + r) * DMODEL + col0 + c4) = v;
        }
    }
}

// ---------------- combine ----------------
__global__ void combine_kernel(float* __restrict__ out) {
    int t = blockIdx.x;
    int s0 = d_token_slot[2 * t];
    int s1 = d_token_slot[2 * t + 1];
    float g0 = d_top_g[2 * t];
    float g1 = d_top_g[2 * t + 1];
    int d = threadIdx.x * 4;
    float4 a = *(const float4*)(d_outslot + (size_t)s0 * DMODEL + d);
    float4 b = *(const float4*)(d_outslot + (size_t)s1 * DMODEL + d);
    float4 r;
    r.x = g0 * a.x + g1 * b.x;
    r.y = g0 * a.y + g1 * b.y;
    r.z = g0 * a.z + g1 * b.z;
    r.w = g0 * a.w + g1 * b.w;
    *(float4*)(out + (size_t)t * DMODEL + d) = r;
}

// ---------------- launch ----------------
extern "C" void kernel_launch(void* const* d_in, const int* in_sizes, int n_in,
                              void* d_out, int out_size)
{
    const float* x        = (const float*)d_in[0];
    const int*   city     = (const int*)d_in[1];
    const float* dt       = (const float*)d_in[2];
    const float* ddis     = (const float*)d_in[3];
    const float* drg      = (const float*)d_in[4];
    const float* dent     = (const float*)d_in[5];
    const float* city_emb = (const float*)d_in[6];
    const float* rw       = (const float*)d_in[7];
    const float* rb       = (const float*)d_in[8];
    const float* w1       = (const float*)d_in[9];
    const float* b1       = (const float*)d_in[10];
    const float* w2       = (const float*)d_in[11];
    const float* b2       = (const float*)d_in[12];

    float* out   = (float*)d_out;
    float* gate1 = (float*)d_out + (size_t)NTOK * DMODEL;

    cudaFuncSetAttribute(moe_mma<0>, cudaFuncAttributeMaxDynamicSharedMemorySize, SMEM_BYTES);
    cudaFuncSetAttribute(moe_mma<1>, cudaFuncAttributeMaxDynamicSharedMemorySize, SMEM_BYTES);

    init_kernel<<<(CAP + 255) / 256, 256>>>();
    router_kernel<<<NTOK * 32 / 256, 256>>>(x, city, dt, ddis, drg, dent,
                                            city_emb, rw, rb, gate1);
    scan_kernel<<<1, 32>>>();
    dispatch_kernel<<<(NTOK * 2 + 255) / 256, 256>>>();

    moe_mma<0><<<dim3(DFF / 128, CAP / 128), 128, SMEM_BYTES>>>(x, w1, b1);
    moe_mma<1><<<dim3(DMODEL / 128, CAP / 128), 128, SMEM_BYTES>>>(x, w2, b2);

    combine_kernel<<<NTOK, DMODEL / 4>>>(out);
}

// round 15
// speedup vs baseline: 2.7500x; 1.0014x over previous
#include <cuda_runtime.h>
#include <cuda_bf16.h>
#include <math.h>
#include <stdint.h>

#define NTOK   8192
#define NE     10
#define DMODEL 768
#define DFF    3072
#define LINSZ  1376
#define BM     128
#define CAP    18432          // 144 * 128

// ---- smem stage (bf16 elems): Ahi(128x40) Alo Bhi(32x136) Blo ----
#define PITCH_A 40
#define PITCH_B 136
#define A_SLAB_E (128 * PITCH_A)                 // 5120
#define B_SLAB_E (32 * PITCH_B)                  // 4352
#define STAGE_E  (2 * A_SLAB_E + 2 * B_SLAB_E)   // 18944 elems = 37888 B
#define SMEM_BYTES (2 * STAGE_E * 2)             // 75776 B

// ---------------- device scratch (283 MB — proven-safe footprint) ----------------
__device__ int   d_counts[NE];
__device__ int   d_cursor[NE];
__device__ int   d_seg_start[NE + 1];
__device__ int   d_top_e[NTOK * 2];
__device__ float d_top_g[NTOK * 2];
__device__ int   d_slot_token[CAP];
__device__ int   d_token_slot[NTOK * 2];
__device__ __nv_bfloat16 d_h_hi[(size_t)CAP * DFF];
__device__ __nv_bfloat16 d_h_lo[(size_t)CAP * DFF];
__device__ float d_outslot[(size_t)CAP * DMODEL];

// ---------------- PTX helpers ----------------
__device__ __forceinline__ uint32_t smem_u32(const void* p) {
    uint32_t a;
    asm("{ .reg .u64 t; cvta.to.shared.u64 t, %1; cvt.u32.u64 %0, t; }" : "=r"(a) : "l"(p));
    return a;
}

__device__ __forceinline__ void cpa16(uint32_t dst, const void* src) {
    asm volatile("cp.async.cg.shared.global [%0], [%1], 16;"
                 :: "r"(dst), "l"(src) : "memory");
}
#define CP_COMMIT() asm volatile("cp.async.commit_group;" ::: "memory")
#define CP_WAIT0()  asm volatile("cp.async.wait_group 0;" ::: "memory")

#define LDM4(v, addr) \
    asm volatile("ldmatrix.sync.aligned.m8n8.x4.shared.b16 {%0,%1,%2,%3}, [%4];" \
                 : "=r"((v).x), "=r"((v).y), "=r"((v).z), "=r"((v).w) : "r"(addr))

#define LDM4T(v, addr) \
    asm volatile("ldmatrix.sync.aligned.m8n8.x4.trans.shared.b16 {%0,%1,%2,%3}, [%4];" \
                 : "=r"((v).x), "=r"((v).y), "=r"((v).z), "=r"((v).w) : "r"(addr))

#define MMA4(c, a, b0, b1) \
    asm volatile( \
        "mma.sync.aligned.m16n8k16.row.col.f32.bf16.bf16.f32 " \
        "{%0,%1,%2,%3}, {%4,%5,%6,%7}, {%8,%9}, {%0,%1,%2,%3};" \
        : "+f"((c).x), "+f"((c).y), "+f"((c).z), "+f"((c).w) \
        : "r"((a).x), "r"((a).y), "r"((a).z), "r"((a).w), "r"(b0), "r"(b1))

// 24 MMAs for one bn-group, pass-major: consecutive MMAs always hit
// DIFFERENT accumulators (reuse distance 8 >> HMMA latency/issue ratio).
#define GROUP24(e0, o0, e1, o1, e2, o2, e3, o3, bh, bl) \
    /* pass 1: aH x bH */ \
    MMA4(e0, ah0, (bh).x, (bh).y); MMA4(o0, ah0, (bh).z, (bh).w); \
    MMA4(e1, ah1, (bh).x, (bh).y); MMA4(o1, ah1, (bh).z, (bh).w); \
    MMA4(e2, ah2, (bh).x, (bh).y); MMA4(o2, ah2, (bh).z, (bh).w); \
    MMA4(e3, ah3, (bh).x, (bh).y); MMA4(o3, ah3, (bh).z, (bh).w); \
    /* pass 2: aL x bH */ \
    MMA4(e0, al0, (bh).x, (bh).y); MMA4(o0, al0, (bh).z, (bh).w); \
    MMA4(e1, al1, (bh).x, (bh).y); MMA4(o1, al1, (bh).z, (bh).w); \
    MMA4(e2, al2, (bh).x, (bh).y); MMA4(o2, al2, (bh).z, (bh).w); \
    MMA4(e3, al3, (bh).x, (bh).y); MMA4(o3, al3, (bh).z, (bh).w); \
    /* pass 3: aH x bL */ \
    MMA4(e0, ah0, (bl).x, (bl).y); MMA4(o0, ah0, (bl).z, (bl).w); \
    MMA4(e1, ah1, (bl).x, (bl).y); MMA4(o1, ah1, (bl).z, (bl).w); \
    MMA4(e2, ah2, (bl).x, (bl).y); MMA4(o2, ah2, (bl).z, (bl).w); \
    MMA4(e3, ah3, (bl).x, (bl).y); MMA4(o3, ah3, (bl).z, (bl).w)

// ---------------- init ----------------
__global__ void init_kernel() {
    int i = blockIdx.x * blockDim.x + threadIdx.x;
    if (i < NE) { d_counts[i] = 0; d_cursor[i] = 0; }
    if (i < CAP) d_slot_token[i] = -1;
}

// ---------------- router: warp per token ----------------
__global__ __launch_bounds__(256) void router_kernel(
    const float* __restrict__ x, const int* __restrict__ city,
    const float* __restrict__ dt, const float* __restrict__ ddis,
    const float* __restrict__ drg, const float* __restrict__ dent,
    const float* __restrict__ city_emb, const float* __restrict__ rw,
    const float* __restrict__ rb, float* __restrict__ gate1_out)
{
    int gwarp = (blockIdx.x * blockDim.x + threadIdx.x) >> 5;
    int lane  = threadIdx.x & 31;
    if (gwarp >= NTOK) return;
    int t = gwarp;
    const float* ce = city_emb + city[0] * 32;

    float rin[43];
#pragma unroll
    for (int i = 0; i < 43; i++) {
        int f = lane + 32 * i;
        float v;
        if      (f < 768)  v = x[(size_t)t * 768 + f];
        else if (f < 800)  v = ce[f - 768];
        else if (f < 992)  v = dt[(size_t)t * 192 + (f - 800)];
        else if (f < 1184) v = ddis[(size_t)t * 192 + (f - 992)];
        else if (f < 1280) v = drg[(size_t)t * 96 + (f - 1184)];
        else               v = dent[(size_t)t * 96 + (f - 1280)];
        rin[i] = v;
    }

    float logits[NE];
#pragma unroll
    for (int e = 0; e < NE; e++) {
        const float* w = rw + e * LINSZ;
        float acc = 0.f;
#pragma unroll
        for (int i = 0; i < 43; i++) acc = fmaf(rin[i], w[lane + 32 * i], acc);
#pragma unroll
        for (int o = 16; o > 0; o >>= 1) acc += __shfl_xor_sync(0xffffffffu, acc, o);
        logits[e] = acc + rb[e];
    }

    if (lane == 0) {
        float m = logits[0];
#pragma unroll
        for (int e = 1; e < NE; e++) m = fmaxf(m, logits[e]);
        float ex[NE], s = 0.f;
#pragma unroll
        for (int e = 0; e < NE; e++) { ex[e] = expf(logits[e] - m); s += ex[e]; }
        float inv = 1.f / s;
#pragma unroll
        for (int e = 0; e < NE; e++) gate1_out[(size_t)t * NE + e] = ex[e] * inv;

        int i0 = 0;
#pragma unroll
        for (int e = 1; e < NE; e++) if (logits[e] > logits[i0]) i0 = e;
        int i1 = (i0 == 0) ? 1 : 0;
#pragma unroll
        for (int e = 0; e < NE; e++) if (e != i0 && logits[e] > logits[i1]) i1 = e;

        float e1 = expf(logits[i1] - logits[i0]);
        float g0 = 1.f / (1.f + e1);
        float g1 = e1 * g0;

        d_top_e[2 * t] = i0;     d_top_e[2 * t + 1] = i1;
        d_top_g[2 * t] = g0;     d_top_g[2 * t + 1] = g1;
        atomicAdd(&d_counts[i0], 1);
        atomicAdd(&d_counts[i1], 1);
    }
}

__global__ void scan_kernel() {
    if (threadIdx.x == 0) {
        int off = 0;
#pragma unroll
        for (int e = 0; e < NE; e++) {
            d_seg_start[e] = off;
            off += ((d_counts[e] + BM - 1) / BM) * BM;
        }
        d_seg_start[NE] = off;
    }
}

__global__ void dispatch_kernel() {
    int i = blockIdx.x * blockDim.x + threadIdx.x;
    if (i >= NTOK * 2) return;
    int e = d_top_e[i];
    int pos = atomicAdd(&d_cursor[e], 1);
    int slot = d_seg_start[e] + pos;
    d_slot_token[slot] = i >> 1;
    d_token_slot[i] = slot;
}

// ---------------- helpers ----------------
__device__ __forceinline__ void split8t(float4 f0, float4 f1, uint4& hi, uint4& lo) {
    uint32_t u0 = __float_as_uint(f0.x), u1 = __float_as_uint(f0.y);
    uint32_t u2 = __float_as_uint(f0.z), u3 = __float_as_uint(f0.w);
    uint32_t u4 = __float_as_uint(f1.x), u5 = __float_as_uint(f1.y);
    uint32_t u6 = __float_as_uint(f1.z), u7 = __float_as_uint(f1.w);
    hi.x = __byte_perm(u0, u1, 0x7632);
    hi.y = __byte_perm(u2, u3, 0x7632);
    hi.z = __byte_perm(u4, u5, 0x7632);
    hi.w = __byte_perm(u6, u7, 0x7632);
    float r0 = f0.x - __uint_as_float(u0 & 0xFFFF0000u);
    float r1 = f0.y - __uint_as_float(u1 & 0xFFFF0000u);
    float r2 = f0.z - __uint_as_float(u2 & 0xFFFF0000u);
    float r3 = f0.w - __uint_as_float(u3 & 0xFFFF0000u);
    float r4 = f1.x - __uint_as_float(u4 & 0xFFFF0000u);
    float r5 = f1.y - __uint_as_float(u5 & 0xFFFF0000u);
    float r6 = f1.z - __uint_as_float(u6 & 0xFFFF0000u);
    float r7 = f1.w - __uint_as_float(u7 & 0xFFFF0000u);
    lo.x = __byte_perm(__float_as_uint(r0), __float_as_uint(r1), 0x7632);
    lo.y = __byte_perm(__float_as_uint(r2), __float_as_uint(r3), 0x7632);
    lo.z = __byte_perm(__float_as_uint(r4), __float_as_uint(r5), 0x7632);
    lo.w = __byte_perm(__float_as_uint(r6), __float_as_uint(r7), 0x7632);
}

__device__ __forceinline__ void split2t(float v0, float v1, uint32_t& hi, uint32_t& lo) {
    uint32_t u0 = __float_as_uint(v0), u1 = __float_as_uint(v1);
    hi = __byte_perm(u0, u1, 0x7632);
    float r0 = v0 - __uint_as_float(u0 & 0xFFFF0000u);
    float r1 = v1 - __uint_as_float(u1 & 0xFFFF0000u);
    lo = __byte_perm(__float_as_uint(r0), __float_as_uint(r1), 0x7632);
}

__device__ __forceinline__ float fast_gelu(float x) {
    float z = fabsf(x) * 0.70710678118654752f;
    float t = __fdividef(1.0f, fmaf(0.3275911f, z, 1.0f));
    float p = fmaf(1.061405429f, t, -1.453152027f);
    p = fmaf(p, t, 1.421413741f);
    p = fmaf(p, t, -0.284496736f);
    p = fmaf(p, t, 0.254829592f);
    p = p * t;
    float s = 1.0f - p * __expf(-z * z);
    return 0.5f * x * (1.0f + copysignf(s, x));
}

// ---------------- raw mma.sync MoE GEMM, CTA 128x128, 4 warps (64x64/warp) ----------------
template<int MODE>
__global__ __launch_bounds__(128, 1) void moe_mma(
    const float* __restrict__ Ain,
    const float* __restrict__ Wglob,
    const float* __restrict__ bias_g)
{
    constexpr int KDIM = MODE ? DFF : DMODEL;
    constexpr int NDIM = MODE ? DMODEL : DFF;
    constexpr int NS   = KDIM / 32;

    extern __shared__ __align__(256) __nv_bfloat16 smem[];

    int row0 = blockIdx.y * 128;
    if (row0 >= d_seg_start[NE]) return;
    int col0 = blockIdx.x * 128;

    int e = 0;
#pragma unroll
    for (int i = 0; i < NE; i++) if (row0 >= d_seg_start[i + 1]) e = i + 1;

    int tid  = threadIdx.x;
    int lane = tid & 31;
    int wid  = tid >> 5;
    int wm   = wid & 1;
    int wn   = wid >> 1;

    // ---- A loader ----
    const float* gpa = nullptr;
    const __nv_bfloat16* gpah = nullptr;
    const __nv_bfloat16* gpal = nullptr;
    bool zf = false;
    if (MODE == 0) {
        int tok = d_slot_token[row0 + tid];
        if (tok < 0) { zf = true; tok = 0; }
        gpa = Ain + (size_t)tok * DMODEL;
    } else {
        gpah = d_h_hi + (size_t)(row0 + tid) * DFF;
        gpal = d_h_lo + (size_t)(row0 + tid) * DFF;
    }
    uint32_t a_off = (uint32_t)(tid * PITCH_A);

    // ---- B loader ----
    int kb  = tid >> 2;
    int ngb = (tid & 3) * 8;
    const float* gpb = Wglob + (size_t)e * DMODEL * DFF + (size_t)kb * NDIM + col0 + ngb;
    uint32_t b_off = (uint32_t)(kb * PITCH_B + ngb);

    uint32_t sb = smem_u32(smem);
    uint32_t aAddr = (uint32_t)(((wm * 64 + (lane & 15)) * PITCH_A + ((lane >> 4) << 3)) * 2);
    uint32_t bAddr = (uint32_t)(((lane & 15) * PITCH_B + wn * 64 + ((lane >> 4) << 3)) * 2)
                   + 2 * A_SLAB_E * 2;
    const uint32_t A_LO = A_SLAB_E * 2;
    const uint32_t B_LO = B_SLAB_E * 2;

    // 32 named accumulators
    float4 d00 = {}, d01 = {}, d02 = {}, d03 = {}, d04 = {}, d05 = {}, d06 = {}, d07 = {};
    float4 d10 = {}, d11 = {}, d12 = {}, d13 = {}, d14 = {}, d15 = {}, d16 = {}, d17 = {};
    float4 d20 = {}, d21 = {}, d22 = {}, d23 = {}, d24 = {}, d25 = {}, d26 = {}, d27 = {};
    float4 d30 = {}, d31 = {}, d32 = {}, d33 = {}, d34 = {}, d35 = {}, d36 = {}, d37 = {};

    float4 b0, b1, b2, b3, b4, b5, b6, b7;
    const float4 zero4 = make_float4(0.f, 0.f, 0.f, 0.f);

    auto load_B = [&](int s) {
        const float* pb = gpb + (size_t)s * 32 * NDIM;
        b0 = *(const float4*)(pb);       b1 = *(const float4*)(pb + 4);
        b2 = *(const float4*)(pb + 32);  b3 = *(const float4*)(pb + 36);
        b4 = *(const float4*)(pb + 64);  b5 = *(const float4*)(pb + 68);
        b6 = *(const float4*)(pb + 96);  b7 = *(const float4*)(pb + 100);
    };
    auto store_B = [&](__nv_bfloat16* st_) {
        uint4 hi_, lo_;
        split8t(b0, b1, hi_, lo_);
        *(uint4*)(st_ + 2 * A_SLAB_E + b_off)                  = hi_;
        *(uint4*)(st_ + 2 * A_SLAB_E + B_SLAB_E + b_off)       = lo_;
        split8t(b2, b3, hi_, lo_);
        *(uint4*)(st_ + 2 * A_SLAB_E + b_off + 32)             = hi_;
        *(uint4*)(st_ + 2 * A_SLAB_E + B_SLAB_E + b_off + 32)  = lo_;
        split8t(b4, b5, hi_, lo_);
        *(uint4*)(st_ + 2 * A_SLAB_E + b_off + 64)             = hi_;
        *(uint4*)(st_ + 2 * A_SLAB_E + B_SLAB_E + b_off + 64)  = lo_;
        split8t(b6, b7, hi_, lo_);
        *(uint4*)(st_ + 2 * A_SLAB_E + b_off + 96)             = hi_;
        *(uint4*)(st_ + 2 * A_SLAB_E + B_SLAB_E + b_off + 96)  = lo_;
    };
    auto fill_A = [&](int s, __nv_bfloat16* st_) {
        if (MODE == 0) {
            const float* pa = gpa + s * 32;
            float4 a0 = zf ? zero4 : *(const float4*)(pa);
            float4 a1 = zf ? zero4 : *(const float4*)(pa + 4);
            float4 a2 = zf ? zero4 : *(const float4*)(pa + 8);
            float4 a3 = zf ? zero4 : *(const float4*)(pa + 12);
            float4 a4 = zf ? zero4 : *(const float4*)(pa + 16);
            float4 a5 = zf ? zero4 : *(const float4*)(pa + 20);
            float4 a6 = zf ? zero4 : *(const float4*)(pa + 24);
            float4 a7 = zf ? zero4 : *(const float4*)(pa + 28);
            uint4 hi_, lo_;
            split8t(a0, a1, hi_, lo_);
            *(uint4*)(st_ + a_off)                  = hi_;
            *(uint4*)(st_ + A_SLAB_E + a_off)       = lo_;
            split8t(a2, a3, hi_, lo_);
            *(uint4*)(st_ + a_off + 8)              = hi_;
            *(uint4*)(st_ + A_SLAB_E + a_off + 8)   = lo_;
            split8t(a4, a5, hi_, lo_);
            *(uint4*)(st_ + a_off + 16)             = hi_;
            *(uint4*)(st_ + A_SLAB_E + a_off + 16)  = lo_;
            split8t(a6, a7, hi_, lo_);
            *(uint4*)(st_ + a_off + 24)             = hi_;
            *(uint4*)(st_ + A_SLAB_E + a_off + 24)  = lo_;
        } else {
            uint32_t dst = smem_u32(st_);
            const char* ph = (const char*)(gpah + s * 32);
            const char* pl = (const char*)(gpal + s * 32);
            cpa16(dst + a_off * 2,                   ph);
            cpa16(dst + a_off * 2 + 16,              ph + 16);
            cpa16(dst + a_off * 2 + 32,              ph + 32);
            cpa16(dst + a_off * 2 + 48,              ph + 48);
            cpa16(dst + (A_SLAB_E + a_off) * 2,      pl);
            cpa16(dst + (A_SLAB_E + a_off) * 2 + 16, pl + 16);
            cpa16(dst + (A_SLAB_E + a_off) * 2 + 32, pl + 32);
            cpa16(dst + (A_SLAB_E + a_off) * 2 + 48, pl + 48);
        }
    };

    // prologue
    load_B(0);
    fill_A(0, smem);
    store_B(smem);
    CP_COMMIT();
    if (NS > 1) load_B(1);

#pragma unroll 1
    for (int k = 0; k < NS; k++) {
        CP_WAIT0();
        __syncthreads();

        uint32_t stb = sb + (uint32_t)((k & 1) * STAGE_E * 2);
        uint32_t aB = stb + aAddr;
        uint32_t bB = stb + bAddr;

#define KK_BLOCK(AOFF, BOFF) { \
        uint4 ah0, al0, ah1, al1, ah2, al2, ah3, al3; \
        LDM4(ah0, aB + (AOFF));                         LDM4(al0, aB + (AOFF) + A_LO); \
        LDM4(ah1, aB + (AOFF) + 1 * 16 * PITCH_A * 2);  LDM4(al1, aB + (AOFF) + A_LO + 1 * 16 * PITCH_A * 2); \
        LDM4(ah2, aB + (AOFF) + 2 * 16 * PITCH_A * 2);  LDM4(al2, aB + (AOFF) + A_LO + 2 * 16 * PITCH_A * 2); \
        LDM4(ah3, aB + (AOFF) + 3 * 16 * PITCH_A * 2);  LDM4(al3, aB + (AOFF) + A_LO + 3 * 16 * PITCH_A * 2); \
        { uint4 bh, bl; \
          LDM4T(bh, bB + (BOFF));        LDM4T(bl, bB + (BOFF) + B_LO); \
          GROUP24(d00, d01, d10, d11, d20, d21, d30, d31, bh, bl); } \
        { uint4 bh, bl; \
          LDM4T(bh, bB + (BOFF) + 32);   LDM4T(bl, bB + (BOFF) + B_LO + 32); \
          GROUP24(d02, d03, d12, d13, d22, d23, d32, d33, bh, bl); } \
        { uint4 bh, bl; \
          LDM4T(bh, bB + (BOFF) + 64);   LDM4T(bl, bB + (BOFF) + B_LO + 64); \
          GROUP24(d04, d05, d14, d15, d24, d25, d34, d35, bh, bl); } \
        { uint4 bh, bl; \
          LDM4T(bh, bB + (BOFF) + 96);   LDM4T(bl, bB + (BOFF) + B_LO + 96); \
          GROUP24(d06, d07, d16, d17, d26, d27, d36, d37, bh, bl); } \
    }
        KK_BLOCK(0, 0)
        KK_BLOCK(32, 16 * PITCH_B * 2)
#undef KK_BLOCK

        if (k + 1 < NS) {
            __nv_bfloat16* nb = smem + ((k + 1) & 1) * STAGE_E;
            fill_A(k + 1, nb);
            store_B(nb);
        }
        CP_COMMIT();
        if (k + 2 < NS) load_B(k + 2);
    }
    __syncthreads();

    // ---- epilogue ----
    float* ebuf = (float*)smem;
    {
        int er = wm * 64 + (lane >> 2);
        int ec = wn * 64 + (lane & 3) * 2;
#define EST(cv, mb, n8) { \
        float* p = ebuf + (er + (mb) * 16) * 132 + ec + (n8) * 8; \
        *(float2*)(p)          = make_float2((cv).x, (cv).y); \
        *(float2*)(p + 8*132)  = make_float2((cv).z, (cv).w); \
    }
        EST(d00,0,0) EST(d01,0,1) EST(d02,0,2) EST(d03,0,3) EST(d04,0,4) EST(d05,0,5) EST(d06,0,6) EST(d07,0,7)
        EST(d10,1,0) EST(d11,1,1) EST(d12,1,2) EST(d13,1,3) EST(d14,1,4) EST(d15,1,5) EST(d16,1,6) EST(d17,1,7)
        EST(d20,2,0) EST(d21,2,1) EST(d22,2,2) EST(d23,2,3) EST(d24,2,4) EST(d25,2,5) EST(d26,2,6) EST(d27,2,7)
        EST(d30,3,0) EST(d31,3,1) EST(d32,3,2) EST(d33,3,3) EST(d34,3,4) EST(d35,3,5) EST(d36,3,6) EST(d37,3,7)
#undef EST
    }
    __syncthreads();

    int c4 = (tid & 31) * 4;
    int rw = tid >> 5;
    float4 bias4 = *(const float4*)(bias_g + (size_t)e * NDIM + col0 + c4);
#pragma unroll
    for (int i = 0; i < 32; i++) {
        int r = rw + i * 4;
        float4 v = *(const float4*)(ebuf + r * 132 + c4);
        v.x += bias4.x; v.y += bias4.y; v.z += bias4.z; v.w += bias4.w;
        if (MODE == 0) {
            v.x = fast_gelu(v.x);
            v.y = fast_gelu(v.y);
            v.z = fast_gelu(v.z);
            v.w = fast_gelu(v.w);
            uint2 h2, l2;
            split2t(v.x, v.y, h2.x, l2.x);
            split2t(v.z, v.w, h2.y, l2.y);
            size_t o = (size_t)(row0 + r) * DFF + col0 + c4;
            *(uint2*)(d_h_hi + o) = h2;
            *(uint2*)(d_h_lo + o) = l2;
        } else {
            *(float4*)(d_outslot + (size_t)(row0 + r) * DMODEL + col0 + c4) = v;
        }
    }
}

// ---------------- combine ----------------
__global__ void combine_kernel(float* __restrict__ out) {
    int t = blockIdx.x;
    int s0 = d_token_slot[2 * t];
    int s1 = d_token_slot[2 * t + 1];
    float g0 = d_top_g[2 * t];
    float g1 = d_top_g[2 * t + 1];
    int d = threadIdx.x * 4;
    float4 a = *(const float4*)(d_outslot + (size_t)s0 * DMODEL + d);
    float4 b = *(const float4*)(d_outslot + (size_t)s1 * DMODEL + d);
    float4 r;
    r.x = g0 * a.x + g1 * b.x;
    r.y = g0 * a.y + g1 * b.y;
    r.z = g0 * a.z + g1 * b.z;
    r.w = g0 * a.w + g1 * b.w;
    *(float4*)(out + (size_t)t * DMODEL + d) = r;
}

// ---------------- launch ----------------
extern "C" void kernel_launch(void* const* d_in, const int* in_sizes, int n_in,
                              void* d_out, int out_size)
{
    const float* x        = (const float*)d_in[0];
    const int*   city     = (const int*)d_in[1];
    const float* dt       = (const float*)d_in[2];
    const float* ddis     = (const float*)d_in[3];
    const float* drg      = (const float*)d_in[4];
    const float* dent     = (const float*)d_in[5];
    const float* city_emb = (const float*)d_in[6];
    const float* rw       = (const float*)d_in[7];
    const float* rb       = (const float*)d_in[8];
    const float* w1       = (const float*)d_in[9];
    const float* b1       = (const float*)d_in[10];
    const float* w2       = (const float*)d_in[11];
    const float* b2       = (const float*)d_in[12];

    float* out   = (float*)d_out;
    float* gate1 = (float*)d_out + (size_t)NTOK * DMODEL;

    cudaFuncSetAttribute(moe_mma<0>, cudaFuncAttributeMaxDynamicSharedMemorySize, SMEM_BYTES);
    cudaFuncSetAttribute(moe_mma<1>, cudaFuncAttributeMaxDynamicSharedMemorySize, SMEM_BYTES);

    init_kernel<<<(CAP + 255) / 256, 256>>>();
    router_kernel<<<NTOK * 32 / 256, 256>>>(x, city, dt, ddis, drg, dent,
                                            city_emb, rw, rb, gate1);
    scan_kernel<<<1, 32>>>();
    dispatch_kernel<<<(NTOK * 2 + 255) / 256, 256>>>();

    moe_mma<0><<<dim3(DFF / 128, CAP / 128), 128, SMEM_BYTES>>>(x, w1, b1);
    moe_mma<1><<<dim3(DMODEL / 128, CAP / 128), 128, SMEM_BYTES>>>(x, w2, b2);

    combine_kernel<<<NTOK, DMODEL / 4>>>(out);
}

// round 16
// speedup vs baseline: 3.0702x; 1.1164x over previous
#include <cuda_runtime.h>
#include <cuda_bf16.h>
#include <math.h>
#include <stdint.h>

#define NTOK   8192
#define NE     10
#define DMODEL 768
#define DFF    3072
#define LINSZ  1376
#define BM     128
#define CAP    18432          // 144 * 128

// ---- smem stage (bf16 elems): Ahi(128x40) Alo Bhi(32x280) Blo ----
#define PITCH_A 40
#define PITCH_B 280
#define A_SLAB_E (128 * PITCH_A)                 // 5120
#define B_SLAB_E (32 * PITCH_B)                  // 8960
#define STAGE_E  (2 * A_SLAB_E + 2 * B_SLAB_E)   // 28160 elems = 56320 B
#define SMEM_BYTES (2 * STAGE_E * 2)             // 112640 B

// ---------------- device scratch (283 MB — proven-safe footprint) ----------------
__device__ int   d_counts[NE];
__device__ int   d_cursor[NE];
__device__ int   d_seg_start[NE + 1];
__device__ int   d_top_e[NTOK * 2];
__device__ float d_top_g[NTOK * 2];
__device__ int   d_slot_token[CAP];
__device__ int   d_token_slot[NTOK * 2];
__device__ __nv_bfloat16 d_h_hi[(size_t)CAP * DFF];
__device__ __nv_bfloat16 d_h_lo[(size_t)CAP * DFF];
__device__ float d_outslot[(size_t)CAP * DMODEL];

// ---------------- PTX helpers ----------------
__device__ __forceinline__ uint32_t smem_u32(const void* p) {
    uint32_t a;
    asm("{ .reg .u64 t; cvta.to.shared.u64 t, %1; cvt.u32.u64 %0, t; }" : "=r"(a) : "l"(p));
    return a;
}

__device__ __forceinline__ void cpa16(uint32_t dst, const void* src) {
    asm volatile("cp.async.cg.shared.global [%0], [%1], 16;"
                 :: "r"(dst), "l"(src) : "memory");
}
#define CP_COMMIT() asm volatile("cp.async.commit_group;" ::: "memory")
#define CP_WAIT0()  asm volatile("cp.async.wait_group 0;" ::: "memory")

#define LDM4(v, addr) \
    asm volatile("ldmatrix.sync.aligned.m8n8.x4.shared.b16 {%0,%1,%2,%3}, [%4];" \
                 : "=r"((v).x), "=r"((v).y), "=r"((v).z), "=r"((v).w) : "r"(addr))

#define LDM4T(v, addr) \
    asm volatile("ldmatrix.sync.aligned.m8n8.x4.trans.shared.b16 {%0,%1,%2,%3}, [%4];" \
                 : "=r"((v).x), "=r"((v).y), "=r"((v).z), "=r"((v).w) : "r"(addr))

#define MMA4(c, a, b0, b1) \
    asm volatile( \
        "mma.sync.aligned.m16n8k16.row.col.f32.bf16.bf16.f32 " \
        "{%0,%1,%2,%3}, {%4,%5,%6,%7}, {%8,%9}, {%0,%1,%2,%3};" \
        : "+f"((c).x), "+f"((c).y), "+f"((c).z), "+f"((c).w) \
        : "r"((a).x), "r"((a).y), "r"((a).z), "r"((a).w), "r"(b0), "r"(b1))

// 24 MMAs for one bn-group, pass-major (accumulator reuse distance 8)
#define GROUP24(e0, o0, e1, o1, e2, o2, e3, o3, bh, bl) \
    MMA4(e0, ah0, (bh).x, (bh).y); MMA4(o0, ah0, (bh).z, (bh).w); \
    MMA4(e1, ah1, (bh).x, (bh).y); MMA4(o1, ah1, (bh).z, (bh).w); \
    MMA4(e2, ah2, (bh).x, (bh).y); MMA4(o2, ah2, (bh).z, (bh).w); \
    MMA4(e3, ah3, (bh).x, (bh).y); MMA4(o3, ah3, (bh).z, (bh).w); \
    MMA4(e0, al0, (bh).x, (bh).y); MMA4(o0, al0, (bh).z, (bh).w); \
    MMA4(e1, al1, (bh).x, (bh).y); MMA4(o1, al1, (bh).z, (bh).w); \
    MMA4(e2, al2, (bh).x, (bh).y); MMA4(o2, al2, (bh).z, (bh).w); \
    MMA4(e3, al3, (bh).x, (bh).y); MMA4(o3, al3, (bh).z, (bh).w); \
    MMA4(e0, ah0, (bl).x, (bl).y); MMA4(o0, ah0, (bl).z, (bl).w); \
    MMA4(e1, ah1, (bl).x, (bl).y); MMA4(o1, ah1, (bl).z, (bl).w); \
    MMA4(e2, ah2, (bl).x, (bl).y); MMA4(o2, ah2, (bl).z, (bl).w); \
    MMA4(e3, ah3, (bl).x, (bl).y); MMA4(o3, ah3, (bl).z, (bl).w)

// ---------------- init ----------------
__global__ void init_kernel() {
    int i = blockIdx.x * blockDim.x + threadIdx.x;
    if (i < NE) { d_counts[i] = 0; d_cursor[i] = 0; }
    if (i < CAP) d_slot_token[i] = -1;
}

// ---------------- router: warp per token ----------------
__global__ __launch_bounds__(256) void router_kernel(
    const float* __restrict__ x, const int* __restrict__ city,
    const float* __restrict__ dt, const float* __restrict__ ddis,
    const float* __restrict__ drg, const float* __restrict__ dent,
    const float* __restrict__ city_emb, const float* __restrict__ rw,
    const float* __restrict__ rb, float* __restrict__ gate1_out)
{
    int gwarp = (blockIdx.x * blockDim.x + threadIdx.x) >> 5;
    int lane  = threadIdx.x & 31;
    if (gwarp >= NTOK) return;
    int t = gwarp;
    const float* ce = city_emb + city[0] * 32;

    float rin[43];
#pragma unroll
    for (int i = 0; i < 43; i++) {
        int f = lane + 32 * i;
        float v;
        if      (f < 768)  v = x[(size_t)t * 768 + f];
        else if (f < 800)  v = ce[f - 768];
        else if (f < 992)  v = dt[(size_t)t * 192 + (f - 800)];
        else if (f < 1184) v = ddis[(size_t)t * 192 + (f - 992)];
        else if (f < 1280) v = drg[(size_t)t * 96 + (f - 1184)];
        else               v = dent[(size_t)t * 96 + (f - 1280)];
        rin[i] = v;
    }

    float logits[NE];
#pragma unroll
    for (int e = 0; e < NE; e++) {
        const float* w = rw + e * LINSZ;
        float acc = 0.f;
#pragma unroll
        for (int i = 0; i < 43; i++) acc = fmaf(rin[i], w[lane + 32 * i], acc);
#pragma unroll
        for (int o = 16; o > 0; o >>= 1) acc += __shfl_xor_sync(0xffffffffu, acc, o);
        logits[e] = acc + rb[e];
    }

    if (lane == 0) {
        float m = logits[0];
#pragma unroll
        for (int e = 1; e < NE; e++) m = fmaxf(m, logits[e]);
        float ex[NE], s = 0.f;
#pragma unroll
        for (int e = 0; e < NE; e++) { ex[e] = expf(logits[e] - m); s += ex[e]; }
        float inv = 1.f / s;
#pragma unroll
        for (int e = 0; e < NE; e++) gate1_out[(size_t)t * NE + e] = ex[e] * inv;

        int i0 = 0;
#pragma unroll
        for (int e = 1; e < NE; e++) if (logits[e] > logits[i0]) i0 = e;
        int i1 = (i0 == 0) ? 1 : 0;
#pragma unroll
        for (int e = 0; e < NE; e++) if (e != i0 && logits[e] > logits[i1]) i1 = e;

        float e1 = expf(logits[i1] - logits[i0]);
        float g0 = 1.f / (1.f + e1);
        float g1 = e1 * g0;

        d_top_e[2 * t] = i0;     d_top_e[2 * t + 1] = i1;
        d_top_g[2 * t] = g0;     d_top_g[2 * t + 1] = g1;
        atomicAdd(&d_counts[i0], 1);
        atomicAdd(&d_counts[i1], 1);
    }
}

__global__ void scan_kernel() {
    if (threadIdx.x == 0) {
        int off = 0;
#pragma unroll
        for (int e = 0; e < NE; e++) {
            d_seg_start[e] = off;
            off += ((d_counts[e] + BM - 1) / BM) * BM;
        }
        d_seg_start[NE] = off;
    }
}

__global__ void dispatch_kernel() {
    int i = blockIdx.x * blockDim.x + threadIdx.x;
    if (i >= NTOK * 2) return;
    int e = d_top_e[i];
    int pos = atomicAdd(&d_cursor[e], 1);
    int slot = d_seg_start[e] + pos;
    d_slot_token[slot] = i >> 1;
    d_token_slot[i] = slot;
}

// ---------------- helpers ----------------
__device__ __forceinline__ void split8t(float4 f0, float4 f1, uint4& hi, uint4& lo) {
    uint32_t u0 = __float_as_uint(f0.x), u1 = __float_as_uint(f0.y);
    uint32_t u2 = __float_as_uint(f0.z), u3 = __float_as_uint(f0.w);
    uint32_t u4 = __float_as_uint(f1.x), u5 = __float_as_uint(f1.y);
    uint32_t u6 = __float_as_uint(f1.z), u7 = __float_as_uint(f1.w);
    hi.x = __byte_perm(u0, u1, 0x7632);
    hi.y = __byte_perm(u2, u3, 0x7632);
    hi.z = __byte_perm(u4, u5, 0x7632);
    hi.w = __byte_perm(u6, u7, 0x7632);
    float r0 = f0.x - __uint_as_float(u0 & 0xFFFF0000u);
    float r1 = f0.y - __uint_as_float(u1 & 0xFFFF0000u);
    float r2 = f0.z - __uint_as_float(u2 & 0xFFFF0000u);
    float r3 = f0.w - __uint_as_float(u3 & 0xFFFF0000u);
    float r4 = f1.x - __uint_as_float(u4 & 0xFFFF0000u);
    float r5 = f1.y - __uint_as_float(u5 & 0xFFFF0000u);
    float r6 = f1.z - __uint_as_float(u6 & 0xFFFF0000u);
    float r7 = f1.w - __uint_as_float(u7 & 0xFFFF0000u);
    lo.x = __byte_perm(__float_as_uint(r0), __float_as_uint(r1), 0x7632);
    lo.y = __byte_perm(__float_as_uint(r2), __float_as_uint(r3), 0x7632);
    lo.z = __byte_perm(__float_as_uint(r4), __float_as_uint(r5), 0x7632);
    lo.w = __byte_perm(__float_as_uint(r6), __float_as_uint(r7), 0x7632);
}

__device__ __forceinline__ void split2t(float v0, float v1, uint32_t& hi, uint32_t& lo) {
    uint32_t u0 = __float_as_uint(v0), u1 = __float_as_uint(v1);
    hi = __byte_perm(u0, u1, 0x7632);
    float r0 = v0 - __uint_as_float(u0 & 0xFFFF0000u);
    float r1 = v1 - __uint_as_float(u1 & 0xFFFF0000u);
    lo = __byte_perm(__float_as_uint(r0), __float_as_uint(r1), 0x7632);
}

__device__ __forceinline__ float fast_gelu(float x) {
    float z = fabsf(x) * 0.70710678118654752f;
    float t = __fdividef(1.0f, fmaf(0.3275911f, z, 1.0f));
    float p = fmaf(1.061405429f, t, -1.453152027f);
    p = fmaf(p, t, 1.421413741f);
    p = fmaf(p, t, -0.284496736f);
    p = fmaf(p, t, 0.254829592f);
    p = p * t;
    float s = 1.0f - p * __expf(-z * z);
    return 0.5f * x * (1.0f + copysignf(s, x));
}

// ---------------- raw mma.sync MoE GEMM, CTA 128x256, 8 warps (64x64/warp) ----------------
// MODE 0: d_h(hi/lo) = gelu(gather(x) @ w1[e] + b1[e])   K=768,  N=3072
// MODE 1: d_outslot = (d_h_hi + d_h_lo) @ w2[e] + b2[e]  K=3072, N=768
// BK=32, 256 threads, warps 2m x 4n. Fill-before-compute pipeline.
template<int MODE>
__global__ __launch_bounds__(256, 1) void moe_mma(
    const float* __restrict__ Ain,
    const float* __restrict__ Wglob,
    const float* __restrict__ bias_g)
{
    constexpr int KDIM = MODE ? DFF : DMODEL;
    constexpr int NDIM = MODE ? DMODEL : DFF;
    constexpr int NS   = KDIM / 32;

    extern __shared__ __align__(256) __nv_bfloat16 smem[];

    int row0 = blockIdx.y * 128;
    if (row0 >= d_seg_start[NE]) return;
    int col0 = blockIdx.x * 256;

    int e = 0;
#pragma unroll
    for (int i = 0; i < NE; i++) if (row0 >= d_seg_start[i + 1]) e = i + 1;

    int tid  = threadIdx.x;
    int lane = tid & 31;
    int wid  = tid >> 5;
    int wm   = wid & 1;        // m half (64 rows)
    int wn   = wid >> 1;       // n quarter (64 cols)

    // ---- A loader: row ra = tid>>1, half-k kg = (tid&1)*16 ----
    int ra = tid >> 1;
    int kg = (tid & 1) * 16;
    const float* gpa = nullptr;
    const __nv_bfloat16* gpah = nullptr;
    const __nv_bfloat16* gpal = nullptr;
    bool zf = false;
    if (MODE == 0) {
        int tok = d_slot_token[row0 + ra];
        if (tok < 0) { zf = true; tok = 0; }
        gpa = Ain + (size_t)tok * DMODEL + kg;
    } else {
        gpah = d_h_hi + (size_t)(row0 + ra) * DFF + kg;
        gpal = d_h_lo + (size_t)(row0 + ra) * DFF + kg;
    }
    uint32_t a_off = (uint32_t)(ra * PITCH_A + kg);

    // ---- B loader: kb = tid>>3 (32 rows), ng = (tid&7)*8, 4 chunks stride 64 ----
    int kb  = tid >> 3;
    int ngb = (tid & 7) * 8;
    const float* gpb = Wglob + (size_t)e * DMODEL * DFF + (size_t)kb * NDIM + col0 + ngb;
    uint32_t b_off = (uint32_t)(kb * PITCH_B + ngb);

    uint32_t sb = smem_u32(smem);
    uint32_t aAddr = (uint32_t)(((wm * 64 + (lane & 15)) * PITCH_A + ((lane >> 4) << 3)) * 2);
    uint32_t bAddr = (uint32_t)(((lane & 15) * PITCH_B + wn * 64 + ((lane >> 4) << 3)) * 2)
                   + 2 * A_SLAB_E * 2;
    const uint32_t A_LO = A_SLAB_E * 2;
    const uint32_t B_LO = B_SLAB_E * 2;

    // 32 named accumulators (warp tile 64x64)
    float4 d00 = {}, d01 = {}, d02 = {}, d03 = {}, d04 = {}, d05 = {}, d06 = {}, d07 = {};
    float4 d10 = {}, d11 = {}, d12 = {}, d13 = {}, d14 = {}, d15 = {}, d16 = {}, d17 = {};
    float4 d20 = {}, d21 = {}, d22 = {}, d23 = {}, d24 = {}, d25 = {}, d26 = {}, d27 = {};
    float4 d30 = {}, d31 = {}, d32 = {}, d33 = {}, d34 = {}, d35 = {}, d36 = {}, d37 = {};

    // register prefetch: B 8 float4 + A 4 float4 (MODE 0)
    float4 b0, b1, b2, b3, b4, b5, b6, b7;
    float4 pa0, pa1, pa2, pa3;
    const float4 zero4 = make_float4(0.f, 0.f, 0.f, 0.f);

    auto load_G = [&](int s) {
        const float* pb = gpb + (size_t)s * 32 * NDIM;
        b0 = *(const float4*)(pb);        b1 = *(const float4*)(pb + 4);
        b2 = *(const float4*)(pb + 64);   b3 = *(const float4*)(pb + 68);
        b4 = *(const float4*)(pb + 128);  b5 = *(const float4*)(pb + 132);
        b6 = *(const float4*)(pb + 192);  b7 = *(const float4*)(pb + 196);
        if (MODE == 0) {
            const float* pa = gpa + s * 32;
            pa0 = zf ? zero4 : *(const float4*)(pa);
            pa1 = zf ? zero4 : *(const float4*)(pa + 4);
            pa2 = zf ? zero4 : *(const float4*)(pa + 8);
            pa3 = zf ? zero4 : *(const float4*)(pa + 12);
        }
    };

    auto store_stage = [&](int s, __nv_bfloat16* st_) {
        uint4 hi_, lo_;
        split8t(b0, b1, hi_, lo_);
        *(uint4*)(st_ + 2 * A_SLAB_E + b_off)                   = hi_;
        *(uint4*)(st_ + 2 * A_SLAB_E + B_SLAB_E + b_off)        = lo_;
        split8t(b2, b3, hi_, lo_);
        *(uint4*)(st_ + 2 * A_SLAB_E + b_off + 64)              = hi_;
        *(uint4*)(st_ + 2 * A_SLAB_E + B_SLAB_E + b_off + 64)   = lo_;
        split8t(b4, b5, hi_, lo_);
        *(uint4*)(st_ + 2 * A_SLAB_E + b_off + 128)             = hi_;
        *(uint4*)(st_ + 2 * A_SLAB_E + B_SLAB_E + b_off + 128)  = lo_;
        split8t(b6, b7, hi_, lo_);
        *(uint4*)(st_ + 2 * A_SLAB_E + b_off + 192)             = hi_;
        *(uint4*)(st_ + 2 * A_SLAB_E + B_SLAB_E + b_off + 192)  = lo_;
        if (MODE == 0) {
            split8t(pa0, pa1, hi_, lo_);
            *(uint4*)(st_ + a_off)                 = hi_;
            *(uint4*)(st_ + A_SLAB_E + a_off)      = lo_;
            split8t(pa2, pa3, hi_, lo_);
            *(uint4*)(st_ + a_off + 8)             = hi_;
            *(uint4*)(st_ + A_SLAB_E + a_off + 8)  = lo_;
        } else {
            uint32_t dst = smem_u32(st_);
            const char* ph = (const char*)(gpah + s * 32);
            const char* pl = (const char*)(gpal + s * 32);
            cpa16(dst + a_off * 2,                   ph);
            cpa16(dst + a_off * 2 + 16,              ph + 16);
            cpa16(dst + (A_SLAB_E + a_off) * 2,      pl);
            cpa16(dst + (A_SLAB_E + a_off) * 2 + 16, pl + 16);
        }
    };

    // prologue: fill stage 0, prefetch stage 1 regs
    load_G(0);
    store_stage(0, smem);
    CP_COMMIT();
    if (NS > 1) load_G(1);

#pragma unroll 1
    for (int k = 0; k < NS; k++) {
        CP_WAIT0();
        __syncthreads();

        // fill NEXT stage first: cp.async + STS get the whole compute to land
        if (k + 1 < NS) store_stage(k + 1, smem + ((k + 1) & 1) * STAGE_E);
        CP_COMMIT();
        if (k + 2 < NS) load_G(k + 2);

        uint32_t stb = sb + (uint32_t)((k & 1) * STAGE_E * 2);
        uint32_t aB = stb + aAddr;
        uint32_t bB = stb + bAddr;

#define KK_BLOCK(AOFF, BOFF) { \
        uint4 ah0, al0, ah1, al1, ah2, al2, ah3, al3; \
        LDM4(ah0, aB + (AOFF));                         LDM4(al0, aB + (AOFF) + A_LO); \
        LDM4(ah1, aB + (AOFF) + 1 * 16 * PITCH_A * 2);  LDM4(al1, aB + (AOFF) + A_LO + 1 * 16 * PITCH_A * 2); \
        LDM4(ah2, aB + (AOFF) + 2 * 16 * PITCH_A * 2);  LDM4(al2, aB + (AOFF) + A_LO + 2 * 16 * PITCH_A * 2); \
        LDM4(ah3, aB + (AOFF) + 3 * 16 * PITCH_A * 2);  LDM4(al3, aB + (AOFF) + A_LO + 3 * 16 * PITCH_A * 2); \
        { uint4 bh, bl; \
          LDM4T(bh, bB + (BOFF));        LDM4T(bl, bB + (BOFF) + B_LO); \
          GROUP24(d00, d01, d10, d11, d20, d21, d30, d31, bh, bl); } \
        { uint4 bh, bl; \
          LDM4T(bh, bB + (BOFF) + 32);   LDM4T(bl, bB + (BOFF) + B_LO + 32); \
          GROUP24(d02, d03, d12, d13, d22, d23, d32, d33, bh, bl); } \
        { uint4 bh, bl; \
          LDM4T(bh, bB + (BOFF) + 64);   LDM4T(bl, bB + (BOFF) + B_LO + 64); \
          GROUP24(d04, d05, d14, d15, d24, d25, d34, d35, bh, bl); } \
        { uint4 bh, bl; \
          LDM4T(bh, bB + (BOFF) + 96);   LDM4T(bl, bB + (BOFF) + B_LO + 96); \
          GROUP24(d06, d07, d16, d17, d26, d27, d36, d37, bh, bl); } \
    }
        KK_BLOCK(0, 0)
        KK_BLOCK(32, 16 * PITCH_B * 2)
#undef KK_BLOCK
    }

    // ---- epilogue: two n-half passes through a 128x128 fp32 smem buffer ----
    float* ebuf = (float*)smem;     // 128 x 132 fp32 = 67584 B < 112640 B
#pragma unroll 1
    for (int p = 0; p < 2; p++) {
        __syncthreads();
        if ((wn >> 1) == p) {
            int er = wm * 64 + (lane >> 2);
            int ec = (wn & 1) * 64 + (lane & 3) * 2;
#define EST(cv, mb, n8) { \
            float* q = ebuf + (er + (mb) * 16) * 132 + ec + (n8) * 8; \
            *(float2*)(q)          = make_float2((cv).x, (cv).y); \
            *(float2*)(q + 8*132)  = make_float2((cv).z, (cv).w); \
        }
            EST(d00,0,0) EST(d01,0,1) EST(d02,0,2) EST(d03,0,3) EST(d04,0,4) EST(d05,0,5) EST(d06,0,6) EST(d07,0,7)
            EST(d10,1,0) EST(d11,1,1) EST(d12,1,2) EST(d13,1,3) EST(d14,1,4) EST(d15,1,5) EST(d16,1,6) EST(d17,1,7)
            EST(d20,2,0) EST(d21,2,1) EST(d22,2,2) EST(d23,2,3) EST(d24,2,4) EST(d25,2,5) EST(d26,2,6) EST(d27,2,7)
            EST(d30,3,0) EST(d31,3,1) EST(d32,3,2) EST(d33,3,3) EST(d34,3,4) EST(d35,3,5) EST(d36,3,6) EST(d37,3,7)
#undef EST
        }
        __syncthreads();

        int c4 = (tid & 31) * 4;
        int rw = tid >> 5;                 // 0..7
        int gcol = col0 + p * 128 + c4;
        float4 bias4 = *(const float4*)(bias_g + (size_t)e * NDIM + gcol);
#pragma unroll
        for (int i = 0; i < 16; i++) {
            int r = rw + i * 8;
            float4 v = *(const float4*)(ebuf + r * 132 + c4);
            v.x += bias4.x; v.y += bias4.y; v.z += bias4.z; v.w += bias4.w;
            if (MODE == 0) {
                v.x = fast_gelu(v.x);
                v.y = fast_gelu(v.y);
                v.z = fast_gelu(v.z);
                v.w = fast_gelu(v.w);
                uint2 h2, l2;
                split2t(v.x, v.y, h2.x, l2.x);
                split2t(v.z, v.w, h2.y, l2.y);
                size_t o = (size_t)(row0 + r) * DFF + gcol;
                *(uint2*)(d_h_hi + o) = h2;
                *(uint2*)(d_h_lo + o) = l2;
            } else {
                *(float4*)(d_outslot + (size_t)(row0 + r) * DMODEL + gcol) = v;
            }
        }
    }
}

// ---------------- combine ----------------
__global__ void combine_kernel(float* __restrict__ out) {
    int t = blockIdx.x;
    int s0 = d_token_slot[2 * t];
    int s1 = d_token_slot[2 * t + 1];
    float g0 = d_top_g[2 * t];
    float g1 = d_top_g[2 * t + 1];
    int d = threadIdx.x * 4;
    float4 a = *(const float4*)(d_outslot + (size_t)s0 * DMODEL + d);
    float4 b = *(const float4*)(d_outslot + (size_t)s1 * DMODEL + d);
    float4 r;
    r.x = g0 * a.x + g1 * b.x;
    r.y = g0 * a.y + g1 * b.y;
    r.z = g0 * a.z + g1 * b.z;
    r.w = g0 * a.w + g1 * b.w;
    *(float4*)(out + (size_t)t * DMODEL + d) = r;
}

// ---------------- launch ----------------
extern "C" void kernel_launch(void* const* d_in, const int* in_sizes, int n_in,
                              void* d_out, int out_size)
{
    const float* x        = (const float*)d_in[0];
    const int*   city     = (const int*)d_in[1];
    const float* dt       = (const float*)d_in[2];
    const float* ddis     = (const float*)d_in[3];
    const float* drg      = (const float*)d_in[4];
    const float* dent     = (const float*)d_in[5];
    const float* city_emb = (const float*)d_in[6];
    const float* rw       = (const float*)d_in[7];
    const float* rb       = (const float*)d_in[8];
    const float* w1       = (const float*)d_in[9];
    const float* b1       = (const float*)d_in[10];
    const float* w2       = (const float*)d_in[11];
    const float* b2       = (const float*)d_in[12];

    float* out   = (float*)d_out;
    float* gate1 = (float*)d_out + (size_t)NTOK * DMODEL;

    cudaFuncSetAttribute(moe_mma<0>, cudaFuncAttributeMaxDynamicSharedMemorySize, SMEM_BYTES);
    cudaFuncSetAttribute(moe_mma<1>, cudaFuncAttributeMaxDynamicSharedMemorySize, SMEM_BYTES);

    init_kernel<<<(CAP + 255) / 256, 256>>>();
    router_kernel<<<NTOK * 32 / 256, 256>>>(x, city, dt, ddis, drg, dent,
                                            city_emb, rw, rb, gate1);
    scan_kernel<<<1, 32>>>();
    dispatch_kernel<<<(NTOK * 2 + 255) / 256, 256>>>();

    moe_mma<0><<<dim3(DFF / 256, CAP / 128), 256, SMEM_BYTES>>>(x, w1, b1);
    moe_mma<1><<<dim3(DMODEL / 256, CAP / 128), 256, SMEM_BYTES>>>(x, w2, b2);

    combine_kernel<<<NTOK, DMODEL / 4>>>(out);
}

// round 17
// speedup vs baseline: 3.3721x; 1.0983x over previous
#include <cuda_runtime.h>
#include <cuda_bf16.h>
#include <cuda_fp16.h>
#include <math.h>
#include <stdint.h>

#define NTOK   8192
#define NE     10
#define DMODEL 768
#define DFF    3072
#define LINSZ  1376
#define BM     128
#define CAP    18432          // 144 * 128

// ---- GEMM1 smem stage (bf16 elems): Ahi(128x40) Alo Bhi(32x280) Blo ----
#define PITCH_A 40
#define PITCH_B 280
#define A_SLAB_E (128 * PITCH_A)                 // 5120
#define B_SLAB_E (32 * PITCH_B)                  // 8960
#define STAGE_E  (2 * A_SLAB_E + 2 * B_SLAB_E)   // 28160 elems
#define SMEM1_BYTES (2 * STAGE_E * 2)            // 112640 B
// ---- GEMM2 smem stage (fp16 elems): A(128x40) Bhi(32x280) Blo ----
#define STAGE2_E (A_SLAB_E + 2 * B_SLAB_E)       // 23040 elems
#define SMEM2_BYTES (2 * STAGE2_E * 2)           // 92160 B

// ---------------- device scratch (~264 MB < proven-safe 283 MB) ----------------
__device__ int   d_counts[NE];
__device__ int   d_cursor[NE];
__device__ int   d_seg_start[NE + 1];
__device__ int   d_top_e[NTOK * 2];
__device__ float d_top_g[NTOK * 2];
__device__ int   d_slot_token[CAP];
__device__ int   d_token_slot[NTOK * 2];
__device__ __half d_h[(size_t)CAP * DFF];                  // 113.2 MB
__device__ __half d_w2s_hi[(size_t)NE * DFF * DMODEL];     // 47.2 MB
__device__ __half d_w2s_lo[(size_t)NE * DFF * DMODEL];     // 47.2 MB
__device__ float d_outslot[(size_t)CAP * DMODEL];          // 56.6 MB

// ---------------- PTX helpers ----------------
__device__ __forceinline__ uint32_t smem_u32(const void* p) {
    uint32_t a;
    asm("{ .reg .u64 t; cvta.to.shared.u64 t, %1; cvt.u32.u64 %0, t; }" : "=r"(a) : "l"(p));
    return a;
}

__device__ __forceinline__ void cpa16(uint32_t dst, const void* src) {
    asm volatile("cp.async.cg.shared.global [%0], [%1], 16;"
                 :: "r"(dst), "l"(src) : "memory");
}
#define CP_COMMIT() asm volatile("cp.async.commit_group;" ::: "memory")
#define CP_WAIT0()  asm volatile("cp.async.wait_group 0;" ::: "memory")

#define LDM4(v, addr) \
    asm volatile("ldmatrix.sync.aligned.m8n8.x4.shared.b16 {%0,%1,%2,%3}, [%4];" \
                 : "=r"((v).x), "=r"((v).y), "=r"((v).z), "=r"((v).w) : "r"(addr))

#define LDM4T(v, addr) \
    asm volatile("ldmatrix.sync.aligned.m8n8.x4.trans.shared.b16 {%0,%1,%2,%3}, [%4];" \
                 : "=r"((v).x), "=r"((v).y), "=r"((v).z), "=r"((v).w) : "r"(addr))

#define MMA4(c, a, b0, b1) \
    asm volatile( \
        "mma.sync.aligned.m16n8k16.row.col.f32.bf16.bf16.f32 " \
        "{%0,%1,%2,%3}, {%4,%5,%6,%7}, {%8,%9}, {%0,%1,%2,%3};" \
        : "+f"((c).x), "+f"((c).y), "+f"((c).z), "+f"((c).w) \
        : "r"((a).x), "r"((a).y), "r"((a).z), "r"((a).w), "r"(b0), "r"(b1))

#define MMAH4(c, a, b0, b1) \
    asm volatile( \
        "mma.sync.aligned.m16n8k16.row.col.f32.f16.f16.f32 " \
        "{%0,%1,%2,%3}, {%4,%5,%6,%7}, {%8,%9}, {%0,%1,%2,%3};" \
        : "+f"((c).x), "+f"((c).y), "+f"((c).z), "+f"((c).w) \
        : "r"((a).x), "r"((a).y), "r"((a).z), "r"((a).w), "r"(b0), "r"(b1))

// GEMM1: 24 MMAs per bn-group, pass-major
#define GROUP24(e0, o0, e1, o1, e2, o2, e3, o3, bh, bl) \
    MMA4(e0, ah0, (bh).x, (bh).y); MMA4(o0, ah0, (bh).z, (bh).w); \
    MMA4(e1, ah1, (bh).x, (bh).y); MMA4(o1, ah1, (bh).z, (bh).w); \
    MMA4(e2, ah2, (bh).x, (bh).y); MMA4(o2, ah2, (bh).z, (bh).w); \
    MMA4(e3, ah3, (bh).x, (bh).y); MMA4(o3, ah3, (bh).z, (bh).w); \
    MMA4(e0, al0, (bh).x, (bh).y); MMA4(o0, al0, (bh).z, (bh).w); \
    MMA4(e1, al1, (bh).x, (bh).y); MMA4(o1, al1, (bh).z, (bh).w); \
    MMA4(e2, al2, (bh).x, (bh).y); MMA4(o2, al2, (bh).z, (bh).w); \
    MMA4(e3, al3, (bh).x, (bh).y); MMA4(o3, al3, (bh).z, (bh).w); \
    MMA4(e0, ah0, (bl).x, (bl).y); MMA4(o0, ah0, (bl).z, (bl).w); \
    MMA4(e1, ah1, (bl).x, (bl).y); MMA4(o1, ah1, (bl).z, (bl).w); \
    MMA4(e2, ah2, (bl).x, (bl).y); MMA4(o2, ah2, (bl).z, (bl).w); \
    MMA4(e3, ah3, (bl).x, (bl).y); MMA4(o3, ah3, (bl).z, (bl).w)

// GEMM2: 16 MMAs per bn-group (A single, B hi/lo)
#define GROUP16(e0, o0, e1, o1, e2, o2, e3, o3, bh, bl) \
    MMAH4(e0, ah0, (bh).x, (bh).y); MMAH4(o0, ah0, (bh).z, (bh).w); \
    MMAH4(e1, ah1, (bh).x, (bh).y); MMAH4(o1, ah1, (bh).z, (bh).w); \
    MMAH4(e2, ah2, (bh).x, (bh).y); MMAH4(o2, ah2, (bh).z, (bh).w); \
    MMAH4(e3, ah3, (bh).x, (bh).y); MMAH4(o3, ah3, (bh).z, (bh).w); \
    MMAH4(e0, ah0, (bl).x, (bl).y); MMAH4(o0, ah0, (bl).z, (bl).w); \
    MMAH4(e1, ah1, (bl).x, (bl).y); MMAH4(o1, ah1, (bl).z, (bl).w); \
    MMAH4(e2, ah2, (bl).x, (bl).y); MMAH4(o2, ah2, (bl).z, (bl).w); \
    MMAH4(e3, ah3, (bl).x, (bl).y); MMAH4(o3, ah3, (bl).z, (bl).w)

// ---------------- init ----------------
__global__ void init_kernel() {
    int i = blockIdx.x * blockDim.x + threadIdx.x;
    if (i < NE) { d_counts[i] = 0; d_cursor[i] = 0; }
    if (i < CAP) d_slot_token[i] = -1;
}

// ---------------- router: warp per token ----------------
__global__ __launch_bounds__(256) void router_kernel(
    const float* __restrict__ x, const int* __restrict__ city,
    const float* __restrict__ dt, const float* __restrict__ ddis,
    const float* __restrict__ drg, const float* __restrict__ dent,
    const float* __restrict__ city_emb, const float* __restrict__ rw,
    const float* __restrict__ rb, float* __restrict__ gate1_out)
{
    int gwarp = (blockIdx.x * blockDim.x + threadIdx.x) >> 5;
    int lane  = threadIdx.x & 31;
    if (gwarp >= NTOK) return;
    int t = gwarp;
    const float* ce = city_emb + city[0] * 32;

    float rin[43];
#pragma unroll
    for (int i = 0; i < 43; i++) {
        int f = lane + 32 * i;
        float v;
        if      (f < 768)  v = x[(size_t)t * 768 + f];
        else if (f < 800)  v = ce[f - 768];
        else if (f < 992)  v = dt[(size_t)t * 192 + (f - 800)];
        else if (f < 1184) v = ddis[(size_t)t * 192 + (f - 992)];
        else if (f < 1280) v = drg[(size_t)t * 96 + (f - 1184)];
        else               v = dent[(size_t)t * 96 + (f - 1280)];
        rin[i] = v;
    }

    float logits[NE];
#pragma unroll
    for (int e = 0; e < NE; e++) {
        const float* w = rw + e * LINSZ;
        float acc = 0.f;
#pragma unroll
        for (int i = 0; i < 43; i++) acc = fmaf(rin[i], w[lane + 32 * i], acc);
#pragma unroll
        for (int o = 16; o > 0; o >>= 1) acc += __shfl_xor_sync(0xffffffffu, acc, o);
        logits[e] = acc + rb[e];
    }

    if (lane == 0) {
        float m = logits[0];
#pragma unroll
        for (int e = 1; e < NE; e++) m = fmaxf(m, logits[e]);
        float ex[NE], s = 0.f;
#pragma unroll
        for (int e = 0; e < NE; e++) { ex[e] = expf(logits[e] - m); s += ex[e]; }
        float inv = 1.f / s;
#pragma unroll
        for (int e = 0; e < NE; e++) gate1_out[(size_t)t * NE + e] = ex[e] * inv;

        int i0 = 0;
#pragma unroll
        for (int e = 1; e < NE; e++) if (logits[e] > logits[i0]) i0 = e;
        int i1 = (i0 == 0) ? 1 : 0;
#pragma unroll
        for (int e = 0; e < NE; e++) if (e != i0 && logits[e] > logits[i1]) i1 = e;

        float e1 = expf(logits[i1] - logits[i0]);
        float g0 = 1.f / (1.f + e1);
        float g1 = e1 * g0;

        d_top_e[2 * t] = i0;     d_top_e[2 * t + 1] = i1;
        d_top_g[2 * t] = g0;     d_top_g[2 * t + 1] = g1;
        atomicAdd(&d_counts[i0], 1);
        atomicAdd(&d_counts[i1], 1);
    }
}

__global__ void scan_kernel() {
    if (threadIdx.x == 0) {
        int off = 0;
#pragma unroll
        for (int e = 0; e < NE; e++) {
            d_seg_start[e] = off;
            off += ((d_counts[e] + BM - 1) / BM) * BM;
        }
        d_seg_start[NE] = off;
    }
}

__global__ void dispatch_kernel() {
    int i = blockIdx.x * blockDim.x + threadIdx.x;
    if (i >= NTOK * 2) return;
    int e = d_top_e[i];
    int pos = atomicAdd(&d_cursor[e], 1);
    int slot = d_seg_start[e] + pos;
    d_slot_token[slot] = i >> 1;
    d_token_slot[i] = slot;
}

// ---------------- w2 pre-split: fp32 -> fp16 hi + fp16 lo ----------------
__global__ __launch_bounds__(256) void conv_w2_kernel(const float* __restrict__ w2) {
    size_t i = ((size_t)blockIdx.x * blockDim.x + threadIdx.x) * 4;
    if (i >= (size_t)NE * DFF * DMODEL) return;
    float4 v = *(const float4*)(w2 + i);
    __half2 h0 = __floats2half2_rn(v.x, v.y);
    __half2 h1 = __floats2half2_rn(v.z, v.w);
    __half2 l0 = __floats2half2_rn(v.x - __half2float(__low2half(h0)),
                                   v.y - __half2float(__high2half(h0)));
    __half2 l1 = __floats2half2_rn(v.z - __half2float(__low2half(h1)),
                                   v.w - __half2float(__high2half(h1)));
    *(__half2*)(d_w2s_hi + i)     = h0;
    *(__half2*)(d_w2s_hi + i + 2) = h1;
    *(__half2*)(d_w2s_lo + i)     = l0;
    *(__half2*)(d_w2s_lo + i + 2) = l1;
}

// ---------------- helpers ----------------
__device__ __forceinline__ void split8t(float4 f0, float4 f1, uint4& hi, uint4& lo) {
    uint32_t u0 = __float_as_uint(f0.x), u1 = __float_as_uint(f0.y);
    uint32_t u2 = __float_as_uint(f0.z), u3 = __float_as_uint(f0.w);
    uint32_t u4 = __float_as_uint(f1.x), u5 = __float_as_uint(f1.y);
    uint32_t u6 = __float_as_uint(f1.z), u7 = __float_as_uint(f1.w);
    hi.x = __byte_perm(u0, u1, 0x7632);
    hi.y = __byte_perm(u2, u3, 0x7632);
    hi.z = __byte_perm(u4, u5, 0x7632);
    hi.w = __byte_perm(u6, u7, 0x7632);
    float r0 = f0.x - __uint_as_float(u0 & 0xFFFF0000u);
    float r1 = f0.y - __uint_as_float(u1 & 0xFFFF0000u);
    float r2 = f0.z - __uint_as_float(u2 & 0xFFFF0000u);
    float r3 = f0.w - __uint_as_float(u3 & 0xFFFF0000u);
    float r4 = f1.x - __uint_as_float(u4 & 0xFFFF0000u);
    float r5 = f1.y - __uint_as_float(u5 & 0xFFFF0000u);
    float r6 = f1.z - __uint_as_float(u6 & 0xFFFF0000u);
    float r7 = f1.w - __uint_as_float(u7 & 0xFFFF0000u);
    lo.x = __byte_perm(__float_as_uint(r0), __float_as_uint(r1), 0x7632);
    lo.y = __byte_perm(__float_as_uint(r2), __float_as_uint(r3), 0x7632);
    lo.z = __byte_perm(__float_as_uint(r4), __float_as_uint(r5), 0x7632);
    lo.w = __byte_perm(__float_as_uint(r6), __float_as_uint(r7), 0x7632);
}

__device__ __forceinline__ float fast_gelu(float x) {
    float z = fabsf(x) * 0.70710678118654752f;
    float t = __fdividef(1.0f, fmaf(0.3275911f, z, 1.0f));
    float p = fmaf(1.061405429f, t, -1.453152027f);
    p = fmaf(p, t, 1.421413741f);
    p = fmaf(p, t, -0.284496736f);
    p = fmaf(p, t, 0.254829592f);
    p = p * t;
    float s = 1.0f - p * __expf(-z * z);
    return 0.5f * x * (1.0f + copysignf(s, x));
}

// ---------------- GEMM1: d_h(fp16) = gelu(gather(x) @ w1[e] + b1[e]) ----------------
// CTA 128x256, 8 warps (2m x 4n, warp 64x64), BK=32, 3-pass bf16 JIT split.
__global__ __launch_bounds__(256, 1) void moe_mma1(
    const float* __restrict__ Ain,
    const float* __restrict__ Wglob,
    const float* __restrict__ bias_g)
{
    constexpr int NDIM = DFF;
    constexpr int NS   = DMODEL / 32;

    extern __shared__ __align__(256) __nv_bfloat16 smem[];

    int row0 = blockIdx.y * 128;
    if (row0 >= d_seg_start[NE]) return;
    int col0 = blockIdx.x * 256;

    int e = 0;
#pragma unroll
    for (int i = 0; i < NE; i++) if (row0 >= d_seg_start[i + 1]) e = i + 1;

    int tid  = threadIdx.x;
    int lane = tid & 31;
    int wid  = tid >> 5;
    int wm   = wid & 1;
    int wn   = wid >> 1;

    int ra = tid >> 1;
    int kg = (tid & 1) * 16;
    bool zf = false;
    const float* gpa;
    {
        int tok = d_slot_token[row0 + ra];
        if (tok < 0) { zf = true; tok = 0; }
        gpa = Ain + (size_t)tok * DMODEL + kg;
    }
    uint32_t a_off = (uint32_t)(ra * PITCH_A + kg);

    int kb  = tid >> 3;
    int ngb = (tid & 7) * 8;
    const float* gpb = Wglob + (size_t)e * DMODEL * DFF + (size_t)kb * NDIM + col0 + ngb;
    uint32_t b_off = (uint32_t)(kb * PITCH_B + ngb);

    uint32_t sb = smem_u32(smem);
    uint32_t aAddr = (uint32_t)(((wm * 64 + (lane & 15)) * PITCH_A + ((lane >> 4) << 3)) * 2);
    uint32_t bAddr = (uint32_t)(((lane & 15) * PITCH_B + wn * 64 + ((lane >> 4) << 3)) * 2)
                   + 2 * A_SLAB_E * 2;
    const uint32_t A_LO = A_SLAB_E * 2;
    const uint32_t B_LO = B_SLAB_E * 2;

    float4 d00 = {}, d01 = {}, d02 = {}, d03 = {}, d04 = {}, d05 = {}, d06 = {}, d07 = {};
    float4 d10 = {}, d11 = {}, d12 = {}, d13 = {}, d14 = {}, d15 = {}, d16 = {}, d17 = {};
    float4 d20 = {}, d21 = {}, d22 = {}, d23 = {}, d24 = {}, d25 = {}, d26 = {}, d27 = {};
    float4 d30 = {}, d31 = {}, d32 = {}, d33 = {}, d34 = {}, d35 = {}, d36 = {}, d37 = {};

    float4 b0, b1, b2, b3, b4, b5, b6, b7;
    float4 pa0, pa1, pa2, pa3;
    const float4 zero4 = make_float4(0.f, 0.f, 0.f, 0.f);

    auto load_G = [&](int s) {
        const float* pb = gpb + (size_t)s * 32 * NDIM;
        b0 = *(const float4*)(pb);        b1 = *(const float4*)(pb + 4);
        b2 = *(const float4*)(pb + 64);   b3 = *(const float4*)(pb + 68);
        b4 = *(const float4*)(pb + 128);  b5 = *(const float4*)(pb + 132);
        b6 = *(const float4*)(pb + 192);  b7 = *(const float4*)(pb + 196);
        const float* pa = gpa + s * 32;
        pa0 = zf ? zero4 : *(const float4*)(pa);
        pa1 = zf ? zero4 : *(const float4*)(pa + 4);
        pa2 = zf ? zero4 : *(const float4*)(pa + 8);
        pa3 = zf ? zero4 : *(const float4*)(pa + 12);
    };

    auto store_stage = [&](__nv_bfloat16* st_) {
        uint4 hi_, lo_;
        split8t(b0, b1, hi_, lo_);
        *(uint4*)(st_ + 2 * A_SLAB_E + b_off)                   = hi_;
        *(uint4*)(st_ + 2 * A_SLAB_E + B_SLAB_E + b_off)        = lo_;
        split8t(b2, b3, hi_, lo_);
        *(uint4*)(st_ + 2 * A_SLAB_E + b_off + 64)              = hi_;
        *(uint4*)(st_ + 2 * A_SLAB_E + B_SLAB_E + b_off + 64)   = lo_;
        split8t(b4, b5, hi_, lo_);
        *(uint4*)(st_ + 2 * A_SLAB_E + b_off + 128)             = hi_;
        *(uint4*)(st_ + 2 * A_SLAB_E + B_SLAB_E + b_off + 128)  = lo_;
        split8t(b6, b7, hi_, lo_);
        *(uint4*)(st_ + 2 * A_SLAB_E + b_off + 192)             = hi_;
        *(uint4*)(st_ + 2 * A_SLAB_E + B_SLAB_E + b_off + 192)  = lo_;
        split8t(pa0, pa1, hi_, lo_);
        *(uint4*)(st_ + a_off)                 = hi_;
        *(uint4*)(st_ + A_SLAB_E + a_off)      = lo_;
        split8t(pa2, pa3, hi_, lo_);
        *(uint4*)(st_ + a_off + 8)             = hi_;
        *(uint4*)(st_ + A_SLAB_E + a_off + 8)  = lo_;
    };

    load_G(0);
    store_stage(smem);
    if (NS > 1) load_G(1);

#pragma unroll 1
    for (int k = 0; k < NS; k++) {
        __syncthreads();
        if (k + 1 < NS) store_stage(smem + ((k + 1) & 1) * STAGE_E);
        if (k + 2 < NS) load_G(k + 2);

        uint32_t stb = sb + (uint32_t)((k & 1) * STAGE_E * 2);
        uint32_t aB = stb + aAddr;
        uint32_t bB = stb + bAddr;

#define KK_BLOCK(AOFF, BOFF) { \
        uint4 ah0, al0, ah1, al1, ah2, al2, ah3, al3; \
        LDM4(ah0, aB + (AOFF));                         LDM4(al0, aB + (AOFF) + A_LO); \
        LDM4(ah1, aB + (AOFF) + 1 * 16 * PITCH_A * 2);  LDM4(al1, aB + (AOFF) + A_LO + 1 * 16 * PITCH_A * 2); \
        LDM4(ah2, aB + (AOFF) + 2 * 16 * PITCH_A * 2);  LDM4(al2, aB + (AOFF) + A_LO + 2 * 16 * PITCH_A * 2); \
        LDM4(ah3, aB + (AOFF) + 3 * 16 * PITCH_A * 2);  LDM4(al3, aB + (AOFF) + A_LO + 3 * 16 * PITCH_A * 2); \
        { uint4 bh, bl; \
          LDM4T(bh, bB + (BOFF));        LDM4T(bl, bB + (BOFF) + B_LO); \
          GROUP24(d00, d01, d10, d11, d20, d21, d30, d31, bh, bl); } \
        { uint4 bh, bl; \
          LDM4T(bh, bB + (BOFF) + 32);   LDM4T(bl, bB + (BOFF) + B_LO + 32); \
          GROUP24(d02, d03, d12, d13, d22, d23, d32, d33, bh, bl); } \
        { uint4 bh, bl; \
          LDM4T(bh, bB + (BOFF) + 64);   LDM4T(bl, bB + (BOFF) + B_LO + 64); \
          GROUP24(d04, d05, d14, d15, d24, d25, d34, d35, bh, bl); } \
        { uint4 bh, bl; \
          LDM4T(bh, bB + (BOFF) + 96);   LDM4T(bl, bB + (BOFF) + B_LO + 96); \
          GROUP24(d06, d07, d16, d17, d26, d27, d36, d37, bh, bl); } \
    }
        KK_BLOCK(0, 0)
        KK_BLOCK(32, 16 * PITCH_B * 2)
#undef KK_BLOCK
    }

    // epilogue: two n-half passes; bias + gelu + fp16 store
    float* ebuf = (float*)smem;
#pragma unroll 1
    for (int p = 0; p < 2; p++) {
        __syncthreads();
        if ((wn >> 1) == p) {
            int er = wm * 64 + (lane >> 2);
            int ec = (wn & 1) * 64 + (lane & 3) * 2;
#define EST(cv, mb, n8) { \
            float* q = ebuf + (er + (mb) * 16) * 132 + ec + (n8) * 8; \
            *(float2*)(q)          = make_float2((cv).x, (cv).y); \
            *(float2*)(q + 8*132)  = make_float2((cv).z, (cv).w); \
        }
            EST(d00,0,0) EST(d01,0,1) EST(d02,0,2) EST(d03,0,3) EST(d04,0,4) EST(d05,0,5) EST(d06,0,6) EST(d07,0,7)
            EST(d10,1,0) EST(d11,1,1) EST(d12,1,2) EST(d13,1,3) EST(d14,1,4) EST(d15,1,5) EST(d16,1,6) EST(d17,1,7)
            EST(d20,2,0) EST(d21,2,1) EST(d22,2,2) EST(d23,2,3) EST(d24,2,4) EST(d25,2,5) EST(d26,2,6) EST(d27,2,7)
            EST(d30,3,0) EST(d31,3,1) EST(d32,3,2) EST(d33,3,3) EST(d34,3,4) EST(d35,3,5) EST(d36,3,6) EST(d37,3,7)
#undef EST
        }
        __syncthreads();

        int c4 = (tid & 31) * 4;
        int rw = tid >> 5;
        int gcol = col0 + p * 128 + c4;
        float4 bias4 = *(const float4*)(bias_g + (size_t)e * NDIM + gcol);
#pragma unroll
        for (int i = 0; i < 16; i++) {
            int r = rw + i * 8;
            float4 v = *(const float4*)(ebuf + r * 132 + c4);
            v.x = fast_gelu(v.x + bias4.x);
            v.y = fast_gelu(v.y + bias4.y);
            v.z = fast_gelu(v.z + bias4.z);
            v.w = fast_gelu(v.w + bias4.w);
            __half2 p0 = __floats2half2_rn(v.x, v.y);
            __half2 p1 = __floats2half2_rn(v.z, v.w);
            __half2* dst = (__half2*)(d_h + (size_t)(row0 + r) * DFF + gcol);
            dst[0] = p0;
            dst[1] = p1;
        }
    }
}

// ---------------- GEMM2: d_outslot = h(fp16) @ (w2hi + w2lo) + b2 ----------------
// CTA 128x256, 8 warps, BK=32, 2-pass fp16, all loads cp.async (zero stage ALU).
__global__ __launch_bounds__(256, 1) void moe_mma2(const float* __restrict__ bias_g)
{
    constexpr int NDIM = DMODEL;
    constexpr int NS   = DFF / 32;

    extern __shared__ __align__(256) __half smem2[];

    int row0 = blockIdx.y * 128;
    if (row0 >= d_seg_start[NE]) return;
    int col0 = blockIdx.x * 256;

    int e = 0;
#pragma unroll
    for (int i = 0; i < NE; i++) if (row0 >= d_seg_start[i + 1]) e = i + 1;

    int tid  = threadIdx.x;
    int lane = tid & 31;
    int wid  = tid >> 5;
    int wm   = wid & 1;
    int wn   = wid >> 1;

    // A: row ra = tid>>1, k half kg = (tid&1)*16 (16 fp16 = 32 B = 2 cpa16)
    int ra = tid >> 1;
    int kg = (tid & 1) * 16;
    const __half* gpa = d_h + (size_t)(row0 + ra) * DFF + kg;
    uint32_t a_off = (uint32_t)(ra * PITCH_A + kg);

    // B: kb = tid>>3 (32 rows), ngb = (tid&7)*8, 4 chunks stride 64
    int kb  = tid >> 3;
    int ngb = (tid & 7) * 8;
    size_t boffg = (size_t)e * DFF * DMODEL + (size_t)kb * NDIM + col0 + ngb;
    const __half* gpbh = d_w2s_hi + boffg;
    const __half* gpbl = d_w2s_lo + boffg;
    uint32_t b_off = (uint32_t)(kb * PITCH_B + ngb);

    uint32_t sb = smem_u32(smem2);
    uint32_t aAddr = (uint32_t)(((wm * 64 + (lane & 15)) * PITCH_A + ((lane >> 4) << 3)) * 2);
    uint32_t bAddr = (uint32_t)(((lane & 15) * PITCH_B + wn * 64 + ((lane >> 4) << 3)) * 2)
                   + A_SLAB_E * 2;
    const uint32_t B_LO = B_SLAB_E * 2;

    float4 d00 = {}, d01 = {}, d02 = {}, d03 = {}, d04 = {}, d05 = {}, d06 = {}, d07 = {};
    float4 d10 = {}, d11 = {}, d12 = {}, d13 = {}, d14 = {}, d15 = {}, d16 = {}, d17 = {};
    float4 d20 = {}, d21 = {}, d22 = {}, d23 = {}, d24 = {}, d25 = {}, d26 = {}, d27 = {};
    float4 d30 = {}, d31 = {}, d32 = {}, d33 = {}, d34 = {}, d35 = {}, d36 = {}, d37 = {};

    auto fill_stage = [&](int s, __half* st_) {
        uint32_t dst = smem_u32(st_);
        const char* pa = (const char*)(gpa + s * 32);
        cpa16(dst + a_off * 2,      pa);
        cpa16(dst + a_off * 2 + 16, pa + 16);
        const char* ph = (const char*)(gpbh + (size_t)s * 32 * NDIM);
        const char* pl = (const char*)(gpbl + (size_t)s * 32 * NDIM);
        uint32_t bd = dst + (A_SLAB_E + b_off) * 2;
        cpa16(bd,                       ph);
        cpa16(bd + 128,                 ph + 128);
        cpa16(bd + 256,                 ph + 256);
        cpa16(bd + 384,                 ph + 384);
        cpa16(bd + B_LO,                pl);
        cpa16(bd + B_LO + 128,          pl + 128);
        cpa16(bd + B_LO + 256,          pl + 256);
        cpa16(bd + B_LO + 384,          pl + 384);
    };

    fill_stage(0, smem2);
    CP_COMMIT();

#pragma unroll 1
    for (int k = 0; k < NS; k++) {
        CP_WAIT0();
        __syncthreads();

        if (k + 1 < NS) fill_stage(k + 1, smem2 + ((k + 1) & 1) * STAGE2_E);
        CP_COMMIT();

        uint32_t stb = sb + (uint32_t)((k & 1) * STAGE2_E * 2);
        uint32_t aB = stb + aAddr;
        uint32_t bB = stb + bAddr;

#define KK_BLOCK2(AOFF, BOFF) { \
        uint4 ah0, ah1, ah2, ah3; \
        LDM4(ah0, aB + (AOFF)); \
        LDM4(ah1, aB + (AOFF) + 1 * 16 * PITCH_A * 2); \
        LDM4(ah2, aB + (AOFF) + 2 * 16 * PITCH_A * 2); \
        LDM4(ah3, aB + (AOFF) + 3 * 16 * PITCH_A * 2); \
        { uint4 bh, bl; \
          LDM4T(bh, bB + (BOFF));        LDM4T(bl, bB + (BOFF) + B_LO); \
          GROUP16(d00, d01, d10, d11, d20, d21, d30, d31, bh, bl); } \
        { uint4 bh, bl; \
          LDM4T(bh, bB + (BOFF) + 32);   LDM4T(bl, bB + (BOFF) + B_LO + 32); \
          GROUP16(d02, d03, d12, d13, d22, d23, d32, d33, bh, bl); } \
        { uint4 bh, bl; \
          LDM4T(bh, bB + (BOFF) + 64);   LDM4T(bl, bB + (BOFF) + B_LO + 64); \
          GROUP16(d04, d05, d14, d15, d24, d25, d34, d35, bh, bl); } \
        { uint4 bh, bl; \
          LDM4T(bh, bB + (BOFF) + 96);   LDM4T(bl, bB + (BOFF) + B_LO + 96); \
          GROUP16(d06, d07, d16, d17, d26, d27, d36, d37, bh, bl); } \
    }
        KK_BLOCK2(0, 0)
        KK_BLOCK2(32, 16 * PITCH_B * 2)
#undef KK_BLOCK2
    }

    // epilogue: two n-half passes through fp32 smem buffer
    float* ebuf = (float*)smem2;
#pragma unroll 1
    for (int p = 0; p < 2; p++) {
        __syncthreads();
        if ((wn >> 1) == p) {
            int er = wm * 64 + (lane >> 2);
            int ec = (wn & 1) * 64 + (lane & 3) * 2;
#define EST(cv, mb, n8) { \
            float* q = ebuf + (er + (mb) * 16) * 132 + ec + (n8) * 8; \
            *(float2*)(q)          = make_float2((cv).x, (cv).y); \
            *(float2*)(q + 8*132)  = make_float2((cv).z, (cv).w); \
        }
            EST(d00,0,0) EST(d01,0,1) EST(d02,0,2) EST(d03,0,3) EST(d04,0,4) EST(d05,0,5) EST(d06,0,6) EST(d07,0,7)
            EST(d10,1,0) EST(d11,1,1) EST(d12,1,2) EST(d13,1,3) EST(d14,1,4) EST(d15,1,5) EST(d16,1,6) EST(d17,1,7)
            EST(d20,2,0) EST(d21,2,1) EST(d22,2,2) EST(d23,2,3) EST(d24,2,4) EST(d25,2,5) EST(d26,2,6) EST(d27,2,7)
            EST(d30,3,0) EST(d31,3,1) EST(d32,3,2) EST(d33,3,3) EST(d34,3,4) EST(d35,3,5) EST(d36,3,6) EST(d37,3,7)
#undef EST
        }
        __syncthreads();

        int c4 = (tid & 31) * 4;
        int rw = tid >> 5;
        int gcol = col0 + p * 128 + c4;
        if (gcol < NDIM) {
            float4 bias4 = *(const float4*)(bias_g + (size_t)e * NDIM + gcol);
#pragma unroll
            for (int i = 0; i < 16; i++) {
                int r = rw + i * 8;
                float4 v = *(const float4*)(ebuf + r * 132 + c4);
                v.x += bias4.x; v.y += bias4.y; v.z += bias4.z; v.w += bias4.w;
                *(float4*)(d_outslot + (size_t)(row0 + r) * DMODEL + gcol) = v;
            }
        }
    }
}

// ---------------- combine ----------------
__global__ void combine_kernel(float* __restrict__ out) {
    int t = blockIdx.x;
    int s0 = d_token_slot[2 * t];
    int s1 = d_token_slot[2 * t + 1];
    float g0 = d_top_g[2 * t];
    float g1 = d_top_g[2 * t + 1];
    int d = threadIdx.x * 4;
    float4 a = *(const float4*)(d_outslot + (size_t)s0 * DMODEL + d);
    float4 b = *(const float4*)(d_outslot + (size_t)s1 * DMODEL + d);
    float4 r;
    r.x = g0 * a.x + g1 * b.x;
    r.y = g0 * a.y + g1 * b.y;
    r.z = g0 * a.z + g1 * b.z;
    r.w = g0 * a.w + g1 * b.w;
    *(float4*)(out + (size_t)t * DMODEL + d) = r;
}

// ---------------- launch ----------------
extern "C" void kernel_launch(void* const* d_in, const int* in_sizes, int n_in,
                              void* d_out, int out_size)
{
    const float* x        = (const float*)d_in[0];
    const int*   city     = (const int*)d_in[1];
    const float* dt       = (const float*)d_in[2];
    const float* ddis     = (const float*)d_in[3];
    const float* drg      = (const float*)d_in[4];
    const float* dent     = (const float*)d_in[5];
    const float* city_emb = (const float*)d_in[6];
    const float* rw       = (const float*)d_in[7];
    const float* rb       = (const float*)d_in[8];
    const float* w1       = (const float*)d_in[9];
    const float* b1       = (const float*)d_in[10];
    const float* w2       = (const float*)d_in[11];
    const float* b2       = (const float*)d_in[12];

    float* out   = (float*)d_out;
    float* gate1 = (float*)d_out + (size_t)NTOK * DMODEL;

    cudaFuncSetAttribute(moe_mma1, cudaFuncAttributeMaxDynamicSharedMemorySize, SMEM1_BYTES);
    cudaFuncSetAttribute(moe_mma2, cudaFuncAttributeMaxDynamicSharedMemorySize, SMEM2_BYTES);

    init_kernel<<<(CAP + 255) / 256, 256>>>();
    router_kernel<<<NTOK * 32 / 256, 256>>>(x, city, dt, ddis, drg, dent,
                                            city_emb, rw, rb, gate1);
    conv_w2_kernel<<<(NE * DFF * DMODEL / 4 + 255) / 256, 256>>>(w2);
    scan_kernel<<<1, 32>>>();
    dispatch_kernel<<<(NTOK * 2 + 255) / 256, 256>>>();

    moe_mma1<<<dim3(DFF / 256, CAP / 128), 256, SMEM1_BYTES>>>(x, w1, b1);
    moe_mma2<<<dim3(DMODEL / 256, CAP / 128), 256, SMEM2_BYTES>>>(b2);

    combine_kernel<<<NTOK, DMODEL / 4>>>(out);
}